// round 6
// baseline (speedup 1.0000x reference)
#include <cuda_runtime.h>
#include <cuda_bf16.h>
#include <cstdint>

// Problem constants
#define BB 4
#define TT 2048
#define DD 1024
#define KK 64
#define RR (BB*TT)        // 8192 rows
#define NQ 192            // Q|K|V packed cols
#define CH 128            // chunk length
#define NC (TT/CH)        // 16 chunks per batch

// Scratch (device globals — no allocation allowed)
__device__ float g_Wpart[8 * DD * 128];          // split-K partials for W_pre@[Qf|Kf]
__device__ float g_bqkv[NQ];
__device__ float g_QKV[RR * NQ];                 // [row, 192]
__device__ float g_S[BB * NC * KK * KK];         // per-chunk state sums
__device__ float g_H[BB * NC * KK * KK];         // exclusive prefix states
// bf16 split operands
__device__ __nv_bfloat16 g_xhi[RR * DD];
__device__ __nv_bfloat16 g_xlo[RR * DD];
__device__ __nv_bfloat16 g_Whi[DD * NQ];
__device__ __nv_bfloat16 g_Wlo[DD * NQ];
__device__ __nv_bfloat16 g_Yhi[RR * KK];
__device__ __nv_bfloat16 g_Ylo[RR * KK];
__device__ __nv_bfloat16 g_Wohi[KK * DD];
__device__ __nv_bfloat16 g_Wolo[KK * DD];

// ---------------------------------------------------------------------------
// helpers
// ---------------------------------------------------------------------------
__device__ __forceinline__ uint32_t smaddr(const void* p) {
    return (uint32_t)__cvta_generic_to_shared(p);
}
__device__ __forceinline__ void ldsm_x4(uint32_t& r0, uint32_t& r1,
                                        uint32_t& r2, uint32_t& r3, uint32_t a) {
    asm volatile("ldmatrix.sync.aligned.m8n8.x4.shared.b16 {%0,%1,%2,%3}, [%4];"
                 : "=r"(r0), "=r"(r1), "=r"(r2), "=r"(r3) : "r"(a));
}
__device__ __forceinline__ void ldsm_x4_t(uint32_t& r0, uint32_t& r1,
                                          uint32_t& r2, uint32_t& r3, uint32_t a) {
    asm volatile("ldmatrix.sync.aligned.m8n8.x4.trans.shared.b16 {%0,%1,%2,%3}, [%4];"
                 : "=r"(r0), "=r"(r1), "=r"(r2), "=r"(r3) : "r"(a));
}
__device__ __forceinline__ void mma_bf16(float* c, const uint32_t* a,
                                         uint32_t b0, uint32_t b1) {
    asm volatile(
        "mma.sync.aligned.m16n8k16.row.col.f32.bf16.bf16.f32 "
        "{%0,%1,%2,%3}, {%4,%5,%6,%7}, {%8,%9}, {%0,%1,%2,%3};"
        : "+f"(c[0]), "+f"(c[1]), "+f"(c[2]), "+f"(c[3])
        : "r"(a[0]), "r"(a[1]), "r"(a[2]), "r"(a[3]), "r"(b0), "r"(b1));
}

// ---------------------------------------------------------------------------
// Kernel A: partial W_pre[D,T] @ [Q_filt | K_filt]  (split-K over T, 8 splits)
// ---------------------------------------------------------------------------
__global__ __launch_bounds__(256) void wfilt_partial(
    const float* __restrict__ W_pre,
    const float* __restrict__ Q_filt,
    const float* __restrict__ K_filt)
{
    __shared__ float Wp[64][33];
    __shared__ float Fs[32][128];
    int d0 = blockIdx.x * 64;
    int split = blockIdx.y;
    int tid = threadIdx.x;
    int ty = tid >> 4, tx = tid & 15;
    float acc[4][8];
#pragma unroll
    for (int i = 0; i < 4; i++)
#pragma unroll
        for (int j = 0; j < 8; j++) acc[i][j] = 0.f;

    int t0 = split * 256;
    for (int kt = t0; kt < t0 + 256; kt += 32) {
        for (int i = tid; i < 64 * 32; i += 256) {
            int r = i >> 5, c = i & 31;
            Wp[r][c] = W_pre[(d0 + r) * TT + kt + c];
        }
        for (int i = tid; i < 32 * 128; i += 256) {
            int r = i >> 7, c = i & 127;
            Fs[r][c] = (c < 64) ? Q_filt[(kt + r) * KK + c]
                                : K_filt[(kt + r) * KK + (c - 64)];
        }
        __syncthreads();
#pragma unroll
        for (int kk = 0; kk < 32; kk++) {
            float a[4];
#pragma unroll
            for (int i = 0; i < 4; i++) a[i] = Wp[ty * 4 + i][kk];
            const float4* F4 = (const float4*)&Fs[kk][0];
            float4 b0 = F4[tx * 2 + 0];
            float4 b1 = F4[tx * 2 + 1];
            float bb[8] = {b0.x, b0.y, b0.z, b0.w, b1.x, b1.y, b1.z, b1.w};
#pragma unroll
            for (int i = 0; i < 4; i++)
#pragma unroll
                for (int j = 0; j < 8; j++) acc[i][j] += a[i] * bb[j];
        }
        __syncthreads();
    }
#pragma unroll
    for (int i = 0; i < 4; i++)
#pragma unroll
        for (int j = 0; j < 8; j++)
            g_Wpart[(split * DD + d0 + ty * 4 + i) * 128 + tx * 8 + j] = acc[i][j];
}

// ---------------------------------------------------------------------------
// Kernel A2: reduce split-K partials + W_v, write bf16 hi/lo directly
// ---------------------------------------------------------------------------
__global__ void wqkv_finalize(const float* __restrict__ W_v)
{
    int idx = blockIdx.x * blockDim.x + threadIdx.x;
    if (idx >= DD * NQ) return;
    int d = idx / NQ, j = idx % NQ;
    float s;
    if (j < 128) {
        s = 0.f;
#pragma unroll
        for (int p = 0; p < 8; p++) s += g_Wpart[(p * DD + d) * 128 + j];
    } else {
        s = W_v[d * KK + (j - 128)];
    }
    __nv_bfloat16 h = __float2bfloat16_rn(s);
    g_Whi[idx] = h;
    g_Wlo[idx] = __float2bfloat16_rn(s - __bfloat162float(h));
}

// ---------------------------------------------------------------------------
// Kernel A3: biases — one block per output column, tree reduce
// ---------------------------------------------------------------------------
__global__ __launch_bounds__(256) void bias_kernel(
    const float* __restrict__ b_pre,
    const float* __restrict__ Q_filt,
    const float* __restrict__ K_filt,
    const float* __restrict__ b_v)
{
    int j = blockIdx.x;                 // 0..191
    int tid = threadIdx.x;
    if (j >= 128) {
        if (tid == 0) g_bqkv[j] = b_v[j - 128];
        return;
    }
    const float* F = (j < 64) ? Q_filt : K_filt;
    int col = j & 63;
    float s = 0.f;
    for (int t = tid; t < TT; t += 256)
        s += b_pre[t] * F[t * KK + col];
#pragma unroll
    for (int o = 16; o > 0; o >>= 1)
        s += __shfl_xor_sync(0xffffffff, s, o);
    __shared__ float red[8];
    if ((tid & 31) == 0) red[tid >> 5] = s;
    __syncthreads();
    if (tid == 0) {
        float tot = 0.f;
#pragma unroll
        for (int w = 0; w < 8; w++) tot += red[w];
        g_bqkv[j] = tot;
    }
}

// ---------------------------------------------------------------------------
// Split kernels: fp32 -> bf16 hi/lo pairs
// ---------------------------------------------------------------------------
__global__ __launch_bounds__(256) void split_x(const float* __restrict__ x)
{
    int i = blockIdx.x * blockDim.x + threadIdx.x;   // one float4 per thread
    float4 v = ((const float4*)x)[i];
    __nv_bfloat16 h[4], l[4];
    float f[4] = {v.x, v.y, v.z, v.w};
#pragma unroll
    for (int j = 0; j < 4; j++) {
        h[j] = __float2bfloat16_rn(f[j]);
        l[j] = __float2bfloat16_rn(f[j] - __bfloat162float(h[j]));
    }
    *(uint2*)&g_xhi[i * 4] = *(uint2*)h;
    *(uint2*)&g_xlo[i * 4] = *(uint2*)l;
}

__global__ __launch_bounds__(256) void wo_split(const float* __restrict__ W_o)
{
    int i = blockIdx.x * blockDim.x + threadIdx.x;   // one float4 per thread
    float4 v = ((const float4*)W_o)[i];
    __nv_bfloat16 h[4], l[4];
    float f[4] = {v.x, v.y, v.z, v.w};
#pragma unroll
    for (int j = 0; j < 4; j++) {
        h[j] = __float2bfloat16_rn(f[j]);
        l[j] = __float2bfloat16_rn(f[j] - __bfloat162float(h[j]));
    }
    *(uint2*)&g_Wohi[i * 4] = *(uint2*)h;
    *(uint2*)&g_Wolo[i * 4] = *(uint2*)l;
}

// ---------------------------------------------------------------------------
// Kernel B: QKV GEMM on tensor cores, bf16 split (3 phases packed as K=3072)
// PROVEN R3 pattern: register prefetch, single smem buffer.
// Block tile 128x64, 8 warps (4m x 2n), warp tile 32x32, k-step 32.
// ---------------------------------------------------------------------------
#define APITCH 40
#define BPITCH 72
__global__ __launch_bounds__(256) void qkv_mma()
{
    __shared__ __nv_bfloat16 As[128][APITCH];
    __shared__ __nv_bfloat16 Bs[32][BPITCH];
    int r0 = blockIdx.x * 128;
    int n0 = blockIdx.y * 64;
    int tid = threadIdx.x;
    int lane = tid & 31, w = tid >> 5;
    int wm = (w & 3) * 32, wn = (w >> 2) * 32;

    float acc[2][4][4];
#pragma unroll
    for (int mt = 0; mt < 2; mt++)
#pragma unroll
        for (int nt = 0; nt < 4; nt++)
#pragma unroll
            for (int r = 0; r < 4; r++) acc[mt][nt][r] = 0.f;

    int ar = tid >> 2, ac = (tid & 3) * 8;      // A: rows ar, ar+64 ; 8 bf16 each
    int br = tid >> 3, bc = (tid & 7) * 8;      // B: one 8-bf16 vector

    float4 a0v, a1v, bv;
    {
        a0v = *(const float4*)&g_xhi[(r0 + ar) * DD + ac];
        a1v = *(const float4*)&g_xhi[(r0 + ar + 64) * DD + ac];
        bv  = *(const float4*)&g_Whi[br * NQ + n0 + bc];
    }

    for (int it = 0; it < 96; it++) {
        *(float4*)&As[ar][ac]      = a0v;
        *(float4*)&As[ar + 64][ac] = a1v;
        *(float4*)&Bs[br][bc]      = bv;
        __syncthreads();

        if (it + 1 < 96) {
            int kt = (it + 1) * 32;
            int phase = kt >> 10;
            int kk = kt & 1023;
            const __nv_bfloat16* Asrc = (phase == 1) ? g_xlo : g_xhi;
            const __nv_bfloat16* Bsrc = (phase == 2) ? g_Wlo : g_Whi;
            a0v = *(const float4*)&Asrc[(r0 + ar) * DD + kk + ac];
            a1v = *(const float4*)&Asrc[(r0 + ar + 64) * DD + kk + ac];
            bv  = *(const float4*)&Bsrc[(kk + br) * NQ + n0 + bc];
        }

#pragma unroll
        for (int ks = 0; ks < 2; ks++) {
            int k = ks * 16;
            uint32_t a[2][4];
#pragma unroll
            for (int mt = 0; mt < 2; mt++) {
                uint32_t ad = smaddr(&As[wm + mt * 16 + (lane & 15)][k + ((lane >> 4) << 3)]);
                ldsm_x4(a[mt][0], a[mt][1], a[mt][2], a[mt][3], ad);
            }
            uint32_t b[2][4];
#pragma unroll
            for (int nb = 0; nb < 2; nb++) {
                uint32_t bd = smaddr(&Bs[k + (lane & 15)][wn + nb * 16 + ((lane >> 4) << 3)]);
                ldsm_x4_t(b[nb][0], b[nb][1], b[nb][2], b[nb][3], bd);
            }
#pragma unroll
            for (int mt = 0; mt < 2; mt++)
#pragma unroll
                for (int nt = 0; nt < 4; nt++) {
                    int nb = nt >> 1, pr = nt & 1;
                    mma_bf16(acc[mt][nt], a[mt], b[nb][pr * 2], b[nb][pr * 2 + 1]);
                }
        }
        __syncthreads();
    }

    // epilogue: add bias, write fp32 QKV
    int gr = lane >> 2, tc = (lane & 3) * 2;
#pragma unroll
    for (int mt = 0; mt < 2; mt++)
#pragma unroll
        for (int nt = 0; nt < 4; nt++) {
            int row = r0 + wm + mt * 16 + gr;
            int col = n0 + wn + nt * 8 + tc;
            float bb0 = g_bqkv[col], bb1 = g_bqkv[col + 1];
            g_QKV[row * NQ + col]           = acc[mt][nt][0] + bb0;
            g_QKV[row * NQ + col + 1]       = acc[mt][nt][1] + bb1;
            g_QKV[(row + 8) * NQ + col]     = acc[mt][nt][2] + bb0;
            g_QKV[(row + 8) * NQ + col + 1] = acc[mt][nt][3] + bb1;
        }
}

// ---------------------------------------------------------------------------
// Kernel C1: per-chunk state sums  S_c[p,n] = sum_s decay_s * V[s,p]*Kf[s,n]
// ---------------------------------------------------------------------------
__global__ __launch_bounds__(256) void chunk_sum(const float* __restrict__ decay)
{
    __shared__ float Vs[64][65];
    __shared__ float Ks[64][65];
    int b = blockIdx.x >> 4, c = blockIdx.x & 15;
    int base = b * TT + c * CH;
    int tid = threadIdx.x;
    int ty = tid >> 4, tx = tid & 15;
    float acc[4][4];
#pragma unroll
    for (int i = 0; i < 4; i++)
#pragma unroll
        for (int j = 0; j < 4; j++) acc[i][j] = 0.f;

    for (int st = 0; st < CH; st += 64) {
        for (int i = tid; i < 64 * 64; i += 256) {
            int r = i >> 6, k = i & 63;
            int row = base + st + r;
            float d = decay[c * CH + st + r];
            Vs[r][k] = g_QKV[row * NQ + 128 + k];
            Ks[r][k] = g_QKV[row * NQ + 64 + k] * d;
        }
        __syncthreads();
#pragma unroll 8
        for (int s = 0; s < 64; s++) {
            float a[4], bb[4];
#pragma unroll
            for (int i = 0; i < 4; i++) a[i] = Vs[s][ty * 4 + i];
#pragma unroll
            for (int j = 0; j < 4; j++) bb[j] = Ks[s][tx * 4 + j];
#pragma unroll
            for (int i = 0; i < 4; i++)
#pragma unroll
                for (int j = 0; j < 4; j++) acc[i][j] += a[i] * bb[j];
        }
        __syncthreads();
    }
    int sb = (b * NC + c) * KK * KK;
#pragma unroll
    for (int i = 0; i < 4; i++)
#pragma unroll
        for (int j = 0; j < 4; j++)
            g_S[sb + (ty * 4 + i) * KK + tx * 4 + j] = acc[i][j];
}

// ---------------------------------------------------------------------------
// Kernel C2: exclusive prefix over chunks
// ---------------------------------------------------------------------------
__global__ void chunk_prefix()
{
    int b = blockIdx.x >> 2;
    int e = (blockIdx.x & 3) * 1024 + threadIdx.x;
    float acc = 0.f;
    for (int c = 0; c < NC; c++) {
        int idx = (b * NC + c) * KK * KK + e;
        g_H[idx] = acc;
        acc += g_S[idx];
    }
}

// ---------------------------------------------------------------------------
// Kernel C3: Y_chunk = Q @ H_prev + causal intra-chunk; emits Y as bf16 hi/lo
// ---------------------------------------------------------------------------
__global__ __launch_bounds__(256) void attn_kernel(const float* __restrict__ decay)
{
    __shared__ float Qt[KK][CH];
    __shared__ float Reg[4096];
    int b = blockIdx.x >> 4, c = blockIdx.x & 15;
    int base = b * TT + c * CH;
    int tid = threadIdx.x;
    int row = tid >> 1;
    int half = tid & 1;

    for (int i = tid; i < KK * CH; i += 256) {
        int r = i & (CH - 1), k = i >> 7;
        Qt[k][r] = g_QKV[(base + r) * NQ + k];
    }
    int hb = (b * NC + c) * KK * KK;
    for (int i = tid; i < KK * KK; i += 256) Reg[i] = g_H[hb + i];
    __syncthreads();

    float q[KK];
#pragma unroll
    for (int k = 0; k < KK; k++) q[k] = Qt[k][row];

    float y[32];
#pragma unroll
    for (int j = 0; j < 32; j++) y[j] = 0.f;

    {
        const float4* H4 = (const float4*)Reg;
#pragma unroll
        for (int k = 0; k < KK; k++) {
            float qk = q[k];
#pragma unroll
            for (int jj = 0; jj < 8; jj++) {
                float4 h = H4[k * 16 + half * 8 + jj];
                y[jj * 4 + 0] += qk * h.x;
                y[jj * 4 + 1] += qk * h.y;
                y[jj * 4 + 2] += qk * h.z;
                y[jj * 4 + 3] += qk * h.w;
            }
        }
    }
    __syncthreads();

    for (int st = 0; st < CH; st += 32) {
        for (int i = tid; i < 2048; i += 256) {
            int s = i >> 6, k = i & 63;
            int grow = (base + st + s) * NQ;
            Reg[i]        = g_QKV[grow + 128 + k];
            Reg[2048 + i] = g_QKV[grow + 64 + k] * decay[c * CH + st + s];
        }
        __syncthreads();
        if (row >= st) {
            int sm = row - st + 1;
            if (sm > 32) sm = 32;
            const float4* V4 = (const float4*)Reg;
            const float4* F4 = (const float4*)(Reg + 2048);
            for (int s = 0; s < sm; s++) {
                float sc = 0.f;
#pragma unroll
                for (int kk = 0; kk < 16; kk++) {
                    float4 v = V4[s * 16 + kk];
                    sc += q[kk * 4 + 0] * v.x + q[kk * 4 + 1] * v.y
                        + q[kk * 4 + 2] * v.z + q[kk * 4 + 3] * v.w;
                }
#pragma unroll
                for (int jj = 0; jj < 8; jj++) {
                    float4 f = F4[s * 16 + half * 8 + jj];
                    y[jj * 4 + 0] += sc * f.x;
                    y[jj * 4 + 1] += sc * f.y;
                    y[jj * 4 + 2] += sc * f.z;
                    y[jj * 4 + 3] += sc * f.w;
                }
            }
        }
        __syncthreads();
    }

    // epilogue: split to bf16 hi/lo, packed 2-wide stores
    int ybase = (base + row) * KK + half * 32;
#pragma unroll
    for (int jj = 0; jj < 16; jj++) {
        float f0 = y[jj * 2], f1 = y[jj * 2 + 1];
        __nv_bfloat16 h0 = __float2bfloat16_rn(f0);
        __nv_bfloat16 h1 = __float2bfloat16_rn(f1);
        __nv_bfloat162 hp; hp.x = h0; hp.y = h1;
        __nv_bfloat162 lp;
        lp.x = __float2bfloat16_rn(f0 - __bfloat162float(h0));
        lp.y = __float2bfloat16_rn(f1 - __bfloat162float(h1));
        *(__nv_bfloat162*)&g_Yhi[ybase + jj * 2] = hp;
        *(__nv_bfloat162*)&g_Ylo[ybase + jj * 2] = lp;
    }
}

// ---------------------------------------------------------------------------
// Kernel D: out = Y @ W_o + b_o  on tensor cores (3-term split, K packed=192)
// Block tile 128x64, 8 warps, 6 k-iters of 32. Proven register-prefetch pattern.
// ---------------------------------------------------------------------------
__global__ __launch_bounds__(256) void out_mma(const float* __restrict__ b_o,
                                               float* __restrict__ out)
{
    __shared__ __nv_bfloat16 As[128][APITCH];
    __shared__ __nv_bfloat16 Bs[32][BPITCH];
    int r0 = blockIdx.x * 128;
    int n0 = blockIdx.y * 64;
    int tid = threadIdx.x;
    int lane = tid & 31, w = tid >> 5;
    int wm = (w & 3) * 32, wn = (w >> 2) * 32;

    float acc[2][4][4];
#pragma unroll
    for (int mt = 0; mt < 2; mt++)
#pragma unroll
        for (int nt = 0; nt < 4; nt++)
#pragma unroll
            for (int r = 0; r < 4; r++) acc[mt][nt][r] = 0.f;

    int ar = tid >> 2, ac = (tid & 3) * 8;
    int br = tid >> 3, bc = (tid & 7) * 8;

    float4 a0v, a1v, bv;
    {   // prefetch iter 0: phase 0 (Yhi, Wohi), kk = 0
        a0v = *(const float4*)&g_Yhi[(r0 + ar) * KK + ac];
        a1v = *(const float4*)&g_Yhi[(r0 + ar + 64) * KK + ac];
        bv  = *(const float4*)&g_Wohi[br * DD + n0 + bc];
    }

    for (int it = 0; it < 6; it++) {
        *(float4*)&As[ar][ac]      = a0v;
        *(float4*)&As[ar + 64][ac] = a1v;
        *(float4*)&Bs[br][bc]      = bv;
        __syncthreads();

        if (it + 1 < 6) {
            int nit = it + 1;
            int phase = nit >> 1;
            int kk = (nit & 1) * 32;
            const __nv_bfloat16* Asrc = (phase == 1) ? g_Ylo : g_Yhi;
            const __nv_bfloat16* Bsrc = (phase == 2) ? g_Wolo : g_Wohi;
            a0v = *(const float4*)&Asrc[(r0 + ar) * KK + kk + ac];
            a1v = *(const float4*)&Asrc[(r0 + ar + 64) * KK + kk + ac];
            bv  = *(const float4*)&Bsrc[(kk + br) * DD + n0 + bc];
        }

#pragma unroll
        for (int ks = 0; ks < 2; ks++) {
            int k = ks * 16;
            uint32_t a[2][4];
#pragma unroll
            for (int mt = 0; mt < 2; mt++) {
                uint32_t ad = smaddr(&As[wm + mt * 16 + (lane & 15)][k + ((lane >> 4) << 3)]);
                ldsm_x4(a[mt][0], a[mt][1], a[mt][2], a[mt][3], ad);
            }
            uint32_t b[2][4];
#pragma unroll
            for (int nb = 0; nb < 2; nb++) {
                uint32_t bd = smaddr(&Bs[k + (lane & 15)][wn + nb * 16 + ((lane >> 4) << 3)]);
                ldsm_x4_t(b[nb][0], b[nb][1], b[nb][2], b[nb][3], bd);
            }
#pragma unroll
            for (int mt = 0; mt < 2; mt++)
#pragma unroll
                for (int nt = 0; nt < 4; nt++) {
                    int nb = nt >> 1, pr = nt & 1;
                    mma_bf16(acc[mt][nt], a[mt], b[nb][pr * 2], b[nb][pr * 2 + 1]);
                }
        }
        __syncthreads();
    }

    int gr = lane >> 2, tc = (lane & 3) * 2;
#pragma unroll
    for (int mt = 0; mt < 2; mt++)
#pragma unroll
        for (int nt = 0; nt < 4; nt++) {
            int row = r0 + wm + mt * 16 + gr;
            int col = n0 + wn + nt * 8 + tc;
            float bb0 = b_o[col], bb1 = b_o[col + 1];
            out[row * DD + col]           = acc[mt][nt][0] + bb0;
            out[row * DD + col + 1]       = acc[mt][nt][1] + bb1;
            out[(row + 8) * DD + col]     = acc[mt][nt][2] + bb0;
            out[(row + 8) * DD + col + 1] = acc[mt][nt][3] + bb1;
        }
}

// ---------------------------------------------------------------------------
extern "C" void kernel_launch(void* const* d_in, const int* in_sizes, int n_in,
                              void* d_out, int out_size)
{
    const float* x      = (const float*)d_in[0];
    const float* W_pre  = (const float*)d_in[1];
    const float* b_pre  = (const float*)d_in[2];
    const float* Q_filt = (const float*)d_in[3];
    const float* K_filt = (const float*)d_in[4];
    const float* W_v    = (const float*)d_in[5];
    const float* b_v    = (const float*)d_in[6];
    const float* W_o    = (const float*)d_in[7];
    const float* b_o    = (const float*)d_in[8];
    const float* decay  = (const float*)d_in[9];
    float* out = (float*)d_out;

    split_x<<<(RR * DD / 4) / 256, 256>>>(x);
    wfilt_partial<<<dim3(16, 8), 256>>>(W_pre, Q_filt, K_filt);
    wqkv_finalize<<<(DD * NQ + 255) / 256, 256>>>(W_v);
    bias_kernel<<<192, 256>>>(b_pre, Q_filt, K_filt, b_v);
    wo_split<<<(KK * DD / 4) / 256, 256>>>(W_o);
    qkv_mma<<<dim3(64, 3), 256>>>();
    chunk_sum<<<64, 256>>>(decay);
    chunk_prefix<<<16, 1024>>>();
    attn_kernel<<<64, 256>>>(decay);
    out_mma<<<dim3(64, 16), 256>>>(b_o, out);
}

// round 8
// speedup vs baseline: 1.0090x; 1.0090x over previous
#include <cuda_runtime.h>
#include <cuda_bf16.h>
#include <cstdint>

// Problem constants
#define BB 4
#define TT 2048
#define DD 1024
#define KK 64
#define RR (BB*TT)        // 8192 rows
#define NQ 192            // Q|K|V packed cols
#define CH 128            // chunk length
#define NC (TT/CH)        // 16 chunks per batch

// Scratch (device globals — no allocation allowed)
__device__ float g_Wpart[8 * DD * 128];          // split-K partials for W_pre@[Qf|Kf]
__device__ float g_bqkv[NQ];
__device__ float g_QKV[RR * NQ];                 // [row, 192]
__device__ float g_S[BB * NC * KK * KK];         // per-chunk state sums
__device__ float g_H[BB * NC * KK * KK];         // exclusive prefix states
// bf16 split operands
__device__ __nv_bfloat16 g_xhi[RR * DD];
__device__ __nv_bfloat16 g_xlo[RR * DD];
__device__ __nv_bfloat16 g_Whi[DD * NQ];
__device__ __nv_bfloat16 g_Wlo[DD * NQ];
__device__ __nv_bfloat16 g_Yhi[RR * KK];
__device__ __nv_bfloat16 g_Ylo[RR * KK];
__device__ __nv_bfloat16 g_Wohi[KK * DD];
__device__ __nv_bfloat16 g_Wolo[KK * DD];

// ---------------------------------------------------------------------------
// helpers
// ---------------------------------------------------------------------------
__device__ __forceinline__ uint32_t smaddr(const void* p) {
    return (uint32_t)__cvta_generic_to_shared(p);
}
__device__ __forceinline__ void ldsm_x4(uint32_t& r0, uint32_t& r1,
                                        uint32_t& r2, uint32_t& r3, uint32_t a) {
    asm volatile("ldmatrix.sync.aligned.m8n8.x4.shared.b16 {%0,%1,%2,%3}, [%4];"
                 : "=r"(r0), "=r"(r1), "=r"(r2), "=r"(r3) : "r"(a));
}
__device__ __forceinline__ void ldsm_x4_t(uint32_t& r0, uint32_t& r1,
                                          uint32_t& r2, uint32_t& r3, uint32_t a) {
    asm volatile("ldmatrix.sync.aligned.m8n8.x4.trans.shared.b16 {%0,%1,%2,%3}, [%4];"
                 : "=r"(r0), "=r"(r1), "=r"(r2), "=r"(r3) : "r"(a));
}
__device__ __forceinline__ void mma_bf16(float* c, const uint32_t* a,
                                         uint32_t b0, uint32_t b1) {
    asm volatile(
        "mma.sync.aligned.m16n8k16.row.col.f32.bf16.bf16.f32 "
        "{%0,%1,%2,%3}, {%4,%5,%6,%7}, {%8,%9}, {%0,%1,%2,%3};"
        : "+f"(c[0]), "+f"(c[1]), "+f"(c[2]), "+f"(c[3])
        : "r"(a[0]), "r"(a[1]), "r"(a[2]), "r"(a[3]), "r"(b0), "r"(b1));
}

// ---------------------------------------------------------------------------
// Kernel A: partial W_pre[D,T] @ [Q_filt | K_filt]  (split-K over T, 8 splits)
// ---------------------------------------------------------------------------
__global__ __launch_bounds__(256) void wfilt_partial(
    const float* __restrict__ W_pre,
    const float* __restrict__ Q_filt,
    const float* __restrict__ K_filt)
{
    __shared__ float Wp[64][33];
    __shared__ float Fs[32][128];
    int d0 = blockIdx.x * 64;
    int split = blockIdx.y;
    int tid = threadIdx.x;
    int ty = tid >> 4, tx = tid & 15;
    float acc[4][8];
#pragma unroll
    for (int i = 0; i < 4; i++)
#pragma unroll
        for (int j = 0; j < 8; j++) acc[i][j] = 0.f;

    int t0 = split * 256;
    for (int kt = t0; kt < t0 + 256; kt += 32) {
        for (int i = tid; i < 64 * 32; i += 256) {
            int r = i >> 5, c = i & 31;
            Wp[r][c] = W_pre[(d0 + r) * TT + kt + c];
        }
        for (int i = tid; i < 32 * 128; i += 256) {
            int r = i >> 7, c = i & 127;
            Fs[r][c] = (c < 64) ? Q_filt[(kt + r) * KK + c]
                                : K_filt[(kt + r) * KK + (c - 64)];
        }
        __syncthreads();
#pragma unroll
        for (int kk = 0; kk < 32; kk++) {
            float a[4];
#pragma unroll
            for (int i = 0; i < 4; i++) a[i] = Wp[ty * 4 + i][kk];
            const float4* F4 = (const float4*)&Fs[kk][0];
            float4 b0 = F4[tx * 2 + 0];
            float4 b1 = F4[tx * 2 + 1];
            float bb[8] = {b0.x, b0.y, b0.z, b0.w, b1.x, b1.y, b1.z, b1.w};
#pragma unroll
            for (int i = 0; i < 4; i++)
#pragma unroll
                for (int j = 0; j < 8; j++) acc[i][j] += a[i] * bb[j];
        }
        __syncthreads();
    }
#pragma unroll
    for (int i = 0; i < 4; i++)
#pragma unroll
        for (int j = 0; j < 8; j++)
            g_Wpart[(split * DD + d0 + ty * 4 + i) * 128 + tx * 8 + j] = acc[i][j];
}

// ---------------------------------------------------------------------------
// Kernel A2: reduce split-K partials + W_v, write bf16 hi/lo directly
// ---------------------------------------------------------------------------
__global__ void wqkv_finalize(const float* __restrict__ W_v)
{
    int idx = blockIdx.x * blockDim.x + threadIdx.x;
    if (idx >= DD * NQ) return;
    int d = idx / NQ, j = idx % NQ;
    float s;
    if (j < 128) {
        s = 0.f;
#pragma unroll
        for (int p = 0; p < 8; p++) s += g_Wpart[(p * DD + d) * 128 + j];
    } else {
        s = W_v[d * KK + (j - 128)];
    }
    __nv_bfloat16 h = __float2bfloat16_rn(s);
    g_Whi[idx] = h;
    g_Wlo[idx] = __float2bfloat16_rn(s - __bfloat162float(h));
}

// ---------------------------------------------------------------------------
// Kernel A3: biases — transposed mapping: threads = columns (coalesced),
// 4-way t-split reduced in smem. grid 3: {Q_filt, K_filt, b_v copy}
// ---------------------------------------------------------------------------
__global__ __launch_bounds__(256) void bias_kernel(
    const float* __restrict__ b_pre,
    const float* __restrict__ Q_filt,
    const float* __restrict__ K_filt,
    const float* __restrict__ b_v)
{
    int blk = blockIdx.x;
    int tid = threadIdx.x;
    if (blk == 2) {
        if (tid < 64) g_bqkv[128 + tid] = b_v[tid];
        return;
    }
    const float* F = blk ? K_filt : Q_filt;
    int c = tid & 63, tg = tid >> 6;          // 4 t-groups x 64 cols
    float s = 0.f;
    for (int t = tg; t < TT; t += 4)
        s += b_pre[t] * F[t * KK + c];        // coalesced across c
    __shared__ float red[4][64];
    red[tg][c] = s;
    __syncthreads();
    if (tg == 0)
        g_bqkv[blk * 64 + c] = red[0][c] + red[1][c] + red[2][c] + red[3][c];
}

// ---------------------------------------------------------------------------
// Split kernels: fp32 -> bf16 hi/lo pairs
// ---------------------------------------------------------------------------
__global__ __launch_bounds__(256) void split_x(const float* __restrict__ x)
{
    int i = blockIdx.x * blockDim.x + threadIdx.x;   // one float4 per thread
    float4 v = ((const float4*)x)[i];
    __nv_bfloat16 h[4], l[4];
    float f[4] = {v.x, v.y, v.z, v.w};
#pragma unroll
    for (int j = 0; j < 4; j++) {
        h[j] = __float2bfloat16_rn(f[j]);
        l[j] = __float2bfloat16_rn(f[j] - __bfloat162float(h[j]));
    }
    *(uint2*)&g_xhi[i * 4] = *(uint2*)h;
    *(uint2*)&g_xlo[i * 4] = *(uint2*)l;
}

__global__ __launch_bounds__(256) void wo_split(const float* __restrict__ W_o)
{
    int i = blockIdx.x * blockDim.x + threadIdx.x;   // one float4 per thread
    float4 v = ((const float4*)W_o)[i];
    __nv_bfloat16 h[4], l[4];
    float f[4] = {v.x, v.y, v.z, v.w};
#pragma unroll
    for (int j = 0; j < 4; j++) {
        h[j] = __float2bfloat16_rn(f[j]);
        l[j] = __float2bfloat16_rn(f[j] - __bfloat162float(h[j]));
    }
    *(uint2*)&g_Wohi[i * 4] = *(uint2*)h;
    *(uint2*)&g_Wolo[i * 4] = *(uint2*)l;
}

// ---------------------------------------------------------------------------
// Kernel B: QKV GEMM on tensor cores, bf16 split (3 phases packed as K=3072)
// Double-buffered smem (plain stores), ONE __syncthreads per k-iter.
// Block tile 128x64, 8 warps (4m x 2n), warp tile 32x32, k-step 32.
// ---------------------------------------------------------------------------
#define APITCH 40
#define BPITCH 72
__global__ __launch_bounds__(256) void qkv_mma()
{
    __shared__ __nv_bfloat16 As[2][128][APITCH];
    __shared__ __nv_bfloat16 Bs[2][32][BPITCH];
    int r0 = blockIdx.x * 128;
    int n0 = blockIdx.y * 64;
    int tid = threadIdx.x;
    int lane = tid & 31, w = tid >> 5;
    int wm = (w & 3) * 32, wn = (w >> 2) * 32;

    float acc[2][4][4];
#pragma unroll
    for (int mt = 0; mt < 2; mt++)
#pragma unroll
        for (int nt = 0; nt < 4; nt++)
#pragma unroll
            for (int r = 0; r < 4; r++) acc[mt][nt][r] = 0.f;

    int ar = tid >> 2, ac = (tid & 3) * 8;      // A: rows ar, ar+64 ; 8 bf16 each
    int br = tid >> 3, bc = (tid & 7) * 8;      // B: one 8-bf16 vector

    float4 a0v, a1v, bv;
    // iter 0 -> regs -> smem buf 0
    a0v = *(const float4*)&g_xhi[(r0 + ar) * DD + ac];
    a1v = *(const float4*)&g_xhi[(r0 + ar + 64) * DD + ac];
    bv  = *(const float4*)&g_Whi[br * NQ + n0 + bc];
    *(float4*)&As[0][ar][ac]      = a0v;
    *(float4*)&As[0][ar + 64][ac] = a1v;
    *(float4*)&Bs[0][br][bc]      = bv;
    __syncthreads();

    for (int it = 0; it < 96; it++) {
        int buf = it & 1;
        bool more = (it + 1 < 96);
        if (more) {
            int kt = (it + 1) * 32;
            int phase = kt >> 10;
            int kk = kt & 1023;
            const __nv_bfloat16* Asrc = (phase == 1) ? g_xlo : g_xhi;
            const __nv_bfloat16* Bsrc = (phase == 2) ? g_Wlo : g_Whi;
            a0v = *(const float4*)&Asrc[(r0 + ar) * DD + kk + ac];
            a1v = *(const float4*)&Asrc[(r0 + ar + 64) * DD + kk + ac];
            bv  = *(const float4*)&Bsrc[(kk + br) * NQ + n0 + bc];
        }

#pragma unroll
        for (int ks = 0; ks < 2; ks++) {
            int k = ks * 16;
            uint32_t a[2][4];
#pragma unroll
            for (int mt = 0; mt < 2; mt++) {
                uint32_t ad = smaddr(&As[buf][wm + mt * 16 + (lane & 15)][k + ((lane >> 4) << 3)]);
                ldsm_x4(a[mt][0], a[mt][1], a[mt][2], a[mt][3], ad);
            }
            uint32_t b[2][4];
#pragma unroll
            for (int nb = 0; nb < 2; nb++) {
                uint32_t bd = smaddr(&Bs[buf][k + (lane & 15)][wn + nb * 16 + ((lane >> 4) << 3)]);
                ldsm_x4_t(b[nb][0], b[nb][1], b[nb][2], b[nb][3], bd);
            }
#pragma unroll
            for (int mt = 0; mt < 2; mt++)
#pragma unroll
                for (int nt = 0; nt < 4; nt++) {
                    int nb = nt >> 1, pr = nt & 1;
                    mma_bf16(acc[mt][nt], a[mt], b[nb][pr * 2], b[nb][pr * 2 + 1]);
                }
        }

        if (more) {
            *(float4*)&As[buf ^ 1][ar][ac]      = a0v;
            *(float4*)&As[buf ^ 1][ar + 64][ac] = a1v;
            *(float4*)&Bs[buf ^ 1][br][bc]      = bv;
            __syncthreads();
        }
    }

    // epilogue: add bias, write fp32 QKV
    int gr = lane >> 2, tc = (lane & 3) * 2;
#pragma unroll
    for (int mt = 0; mt < 2; mt++)
#pragma unroll
        for (int nt = 0; nt < 4; nt++) {
            int row = r0 + wm + mt * 16 + gr;
            int col = n0 + wn + nt * 8 + tc;
            float bb0 = g_bqkv[col], bb1 = g_bqkv[col + 1];
            g_QKV[row * NQ + col]           = acc[mt][nt][0] + bb0;
            g_QKV[row * NQ + col + 1]       = acc[mt][nt][1] + bb1;
            g_QKV[(row + 8) * NQ + col]     = acc[mt][nt][2] + bb0;
            g_QKV[(row + 8) * NQ + col + 1] = acc[mt][nt][3] + bb1;
        }
}

// ---------------------------------------------------------------------------
// Kernel C1: per-chunk state sums  S_c[p,n] = sum_s decay_s * V[s,p]*Kf[s,n]
// ---------------------------------------------------------------------------
__global__ __launch_bounds__(256) void chunk_sum(const float* __restrict__ decay)
{
    __shared__ float Vs[64][65];
    __shared__ float Ks[64][65];
    int b = blockIdx.x >> 4, c = blockIdx.x & 15;
    int base = b * TT + c * CH;
    int tid = threadIdx.x;
    int ty = tid >> 4, tx = tid & 15;
    float acc[4][4];
#pragma unroll
    for (int i = 0; i < 4; i++)
#pragma unroll
        for (int j = 0; j < 4; j++) acc[i][j] = 0.f;

    for (int st = 0; st < CH; st += 64) {
        for (int i = tid; i < 64 * 64; i += 256) {
            int r = i >> 6, k = i & 63;
            int row = base + st + r;
            float d = decay[c * CH + st + r];
            Vs[r][k] = g_QKV[row * NQ + 128 + k];
            Ks[r][k] = g_QKV[row * NQ + 64 + k] * d;
        }
        __syncthreads();
#pragma unroll 8
        for (int s = 0; s < 64; s++) {
            float a[4], bb[4];
#pragma unroll
            for (int i = 0; i < 4; i++) a[i] = Vs[s][ty * 4 + i];
#pragma unroll
            for (int j = 0; j < 4; j++) bb[j] = Ks[s][tx * 4 + j];
#pragma unroll
            for (int i = 0; i < 4; i++)
#pragma unroll
                for (int j = 0; j < 4; j++) acc[i][j] += a[i] * bb[j];
        }
        __syncthreads();
    }
    int sb = (b * NC + c) * KK * KK;
#pragma unroll
    for (int i = 0; i < 4; i++)
#pragma unroll
        for (int j = 0; j < 4; j++)
            g_S[sb + (ty * 4 + i) * KK + tx * 4 + j] = acc[i][j];
}

// ---------------------------------------------------------------------------
// Kernel C2: exclusive prefix over chunks — 64 blocks for SM coverage
// ---------------------------------------------------------------------------
__global__ __launch_bounds__(256) void chunk_prefix()
{
    int b = blockIdx.x >> 4;
    int e = (blockIdx.x & 15) * 256 + threadIdx.x;   // 0..4095
    float acc = 0.f;
    for (int c = 0; c < NC; c++) {
        int idx = (b * NC + c) * KK * KK + e;
        g_H[idx] = acc;
        acc += g_S[idx];
    }
}

// ---------------------------------------------------------------------------
// Kernel C3: Y_chunk = Q @ H_prev + causal intra-chunk; emits Y as bf16 hi/lo
// ---------------------------------------------------------------------------
__global__ __launch_bounds__(256) void attn_kernel(const float* __restrict__ decay)
{
    __shared__ float Qt[KK][CH];
    __shared__ float Reg[4096];
    int b = blockIdx.x >> 4, c = blockIdx.x & 15;
    int base = b * TT + c * CH;
    int tid = threadIdx.x;
    int row = tid >> 1;
    int half = tid & 1;

    for (int i = tid; i < KK * CH; i += 256) {
        int r = i & (CH - 1), k = i >> 7;
        Qt[k][r] = g_QKV[(base + r) * NQ + k];
    }
    int hb = (b * NC + c) * KK * KK;
    for (int i = tid; i < KK * KK; i += 256) Reg[i] = g_H[hb + i];
    __syncthreads();

    float q[KK];
#pragma unroll
    for (int k = 0; k < KK; k++) q[k] = Qt[k][row];

    float y[32];
#pragma unroll
    for (int j = 0; j < 32; j++) y[j] = 0.f;

    {
        const float4* H4 = (const float4*)Reg;
#pragma unroll
        for (int k = 0; k < KK; k++) {
            float qk = q[k];
#pragma unroll
            for (int jj = 0; jj < 8; jj++) {
                float4 h = H4[k * 16 + half * 8 + jj];
                y[jj * 4 + 0] += qk * h.x;
                y[jj * 4 + 1] += qk * h.y;
                y[jj * 4 + 2] += qk * h.z;
                y[jj * 4 + 3] += qk * h.w;
            }
        }
    }
    __syncthreads();

    for (int st = 0; st < CH; st += 32) {
        for (int i = tid; i < 2048; i += 256) {
            int s = i >> 6, k = i & 63;
            int grow = (base + st + s) * NQ;
            Reg[i]        = g_QKV[grow + 128 + k];
            Reg[2048 + i] = g_QKV[grow + 64 + k] * decay[c * CH + st + s];
        }
        __syncthreads();
        if (row >= st) {
            int sm = row - st + 1;
            if (sm > 32) sm = 32;
            const float4* V4 = (const float4*)Reg;
            const float4* F4 = (const float4*)(Reg + 2048);
            for (int s = 0; s < sm; s++) {
                float sc = 0.f;
#pragma unroll
                for (int kk = 0; kk < 16; kk++) {
                    float4 v = V4[s * 16 + kk];
                    sc += q[kk * 4 + 0] * v.x + q[kk * 4 + 1] * v.y
                        + q[kk * 4 + 2] * v.z + q[kk * 4 + 3] * v.w;
                }
#pragma unroll
                for (int jj = 0; jj < 8; jj++) {
                    float4 f = F4[s * 16 + half * 8 + jj];
                    y[jj * 4 + 0] += sc * f.x;
                    y[jj * 4 + 1] += sc * f.y;
                    y[jj * 4 + 2] += sc * f.z;
                    y[jj * 4 + 3] += sc * f.w;
                }
            }
        }
        __syncthreads();
    }

    // epilogue: split to bf16 hi/lo, 8-byte packed stores
    int ybase = (base + row) * KK + half * 32;
#pragma unroll
    for (int jj = 0; jj < 8; jj++) {
        __nv_bfloat16 hp[4], lp[4];
#pragma unroll
        for (int e = 0; e < 4; e++) {
            float f = y[jj * 4 + e];
            hp[e] = __float2bfloat16_rn(f);
            lp[e] = __float2bfloat16_rn(f - __bfloat162float(hp[e]));
        }
        *(uint2*)&g_Yhi[ybase + jj * 4] = *(uint2*)hp;
        *(uint2*)&g_Ylo[ybase + jj * 4] = *(uint2*)lp;
    }
}

// ---------------------------------------------------------------------------
// Kernel D: out = Y @ W_o + b_o  on tensor cores (3-term split, K packed=192)
// Block tile 128x64, 8 warps, 6 k-iters of 32. Register-prefetch pattern.
// ---------------------------------------------------------------------------
__global__ __launch_bounds__(256) void out_mma(const float* __restrict__ b_o,
                                               float* __restrict__ out)
{
    __shared__ __nv_bfloat16 As[128][APITCH];
    __shared__ __nv_bfloat16 Bs[32][BPITCH];
    int r0 = blockIdx.x * 128;
    int n0 = blockIdx.y * 64;
    int tid = threadIdx.x;
    int lane = tid & 31, w = tid >> 5;
    int wm = (w & 3) * 32, wn = (w >> 2) * 32;

    float acc[2][4][4];
#pragma unroll
    for (int mt = 0; mt < 2; mt++)
#pragma unroll
        for (int nt = 0; nt < 4; nt++)
#pragma unroll
            for (int r = 0; r < 4; r++) acc[mt][nt][r] = 0.f;

    int ar = tid >> 2, ac = (tid & 3) * 8;
    int br = tid >> 3, bc = (tid & 7) * 8;

    float4 a0v, a1v, bv;
    {   // prefetch iter 0: phase 0 (Yhi, Wohi), kk = 0
        a0v = *(const float4*)&g_Yhi[(r0 + ar) * KK + ac];
        a1v = *(const float4*)&g_Yhi[(r0 + ar + 64) * KK + ac];
        bv  = *(const float4*)&g_Wohi[br * DD + n0 + bc];
    }

    for (int it = 0; it < 6; it++) {
        *(float4*)&As[ar][ac]      = a0v;
        *(float4*)&As[ar + 64][ac] = a1v;
        *(float4*)&Bs[br][bc]      = bv;
        __syncthreads();

        if (it + 1 < 6) {
            int nit = it + 1;
            int phase = nit >> 1;
            int kk = (nit & 1) * 32;
            const __nv_bfloat16* Asrc = (phase == 1) ? g_Ylo : g_Yhi;
            const __nv_bfloat16* Bsrc = (phase == 2) ? g_Wolo : g_Wohi;
            a0v = *(const float4*)&Asrc[(r0 + ar) * KK + kk + ac];
            a1v = *(const float4*)&Asrc[(r0 + ar + 64) * KK + kk + ac];
            bv  = *(const float4*)&Bsrc[(kk + br) * DD + n0 + bc];
        }

#pragma unroll
        for (int ks = 0; ks < 2; ks++) {
            int k = ks * 16;
            uint32_t a[2][4];
#pragma unroll
            for (int mt = 0; mt < 2; mt++) {
                uint32_t ad = smaddr(&As[wm + mt * 16 + (lane & 15)][k + ((lane >> 4) << 3)]);
                ldsm_x4(a[mt][0], a[mt][1], a[mt][2], a[mt][3], ad);
            }
            uint32_t b[2][4];
#pragma unroll
            for (int nb = 0; nb < 2; nb++) {
                uint32_t bd = smaddr(&Bs[k + (lane & 15)][wn + nb * 16 + ((lane >> 4) << 3)]);
                ldsm_x4_t(b[nb][0], b[nb][1], b[nb][2], b[nb][3], bd);
            }
#pragma unroll
            for (int mt = 0; mt < 2; mt++)
#pragma unroll
                for (int nt = 0; nt < 4; nt++) {
                    int nb = nt >> 1, pr = nt & 1;
                    mma_bf16(acc[mt][nt], a[mt], b[nb][pr * 2], b[nb][pr * 2 + 1]);
                }
        }
        __syncthreads();
    }

    int gr = lane >> 2, tc = (lane & 3) * 2;
#pragma unroll
    for (int mt = 0; mt < 2; mt++)
#pragma unroll
        for (int nt = 0; nt < 4; nt++) {
            int row = r0 + wm + mt * 16 + gr;
            int col = n0 + wn + nt * 8 + tc;
            float bb0 = b_o[col], bb1 = b_o[col + 1];
            out[row * DD + col]           = acc[mt][nt][0] + bb0;
            out[row * DD + col + 1]       = acc[mt][nt][1] + bb1;
            out[(row + 8) * DD + col]     = acc[mt][nt][2] + bb0;
            out[(row + 8) * DD + col + 1] = acc[mt][nt][3] + bb1;
        }
}

// ---------------------------------------------------------------------------
extern "C" void kernel_launch(void* const* d_in, const int* in_sizes, int n_in,
                              void* d_out, int out_size)
{
    const float* x      = (const float*)d_in[0];
    const float* W_pre  = (const float*)d_in[1];
    const float* b_pre  = (const float*)d_in[2];
    const float* Q_filt = (const float*)d_in[3];
    const float* K_filt = (const float*)d_in[4];
    const float* W_v    = (const float*)d_in[5];
    const float* b_v    = (const float*)d_in[6];
    const float* W_o    = (const float*)d_in[7];
    const float* b_o    = (const float*)d_in[8];
    const float* decay  = (const float*)d_in[9];
    float* out = (float*)d_out;

    split_x<<<(RR * DD / 4) / 256, 256>>>(x);
    wfilt_partial<<<dim3(16, 8), 256>>>(W_pre, Q_filt, K_filt);
    wqkv_finalize<<<(DD * NQ + 255) / 256, 256>>>(W_v);
    bias_kernel<<<3, 256>>>(b_pre, Q_filt, K_filt, b_v);
    wo_split<<<(KK * DD / 4) / 256, 256>>>(W_o);
    qkv_mma<<<dim3(64, 3), 256>>>();
    chunk_sum<<<64, 256>>>(decay);
    chunk_prefix<<<64, 256>>>();
    attn_kernel<<<64, 256>>>(decay);
    out_mma<<<dim3(64, 16), 256>>>(b_o, out);
}

// round 9
// speedup vs baseline: 1.4366x; 1.4238x over previous
#include <cuda_runtime.h>
#include <cuda_bf16.h>
#include <cstdint>

// Problem constants
#define BB 4
#define TT 2048
#define DD 1024
#define KK 64
#define RR (BB*TT)        // 8192 rows
#define NQ 192            // Q|K|V packed cols
#define CH 128            // chunk length
#define NC (TT/CH)        // 16 chunks per batch

// Scratch (device globals — no allocation allowed)
__device__ float g_Wpart[8 * DD * 128];          // split-K partials for W_pre@[Qf|Kf]
__device__ float g_bqkv[NQ];
__device__ float g_QKV[RR * NQ];                 // [row, 192]
__device__ float g_S[BB * NC * KK * KK];         // per-chunk state sums
__device__ float g_H[BB * NC * KK * KK];         // exclusive prefix states
// bf16 split operands
__device__ __nv_bfloat16 g_xhi[RR * DD];
__device__ __nv_bfloat16 g_xlo[RR * DD];
__device__ __nv_bfloat16 g_Whi[DD * NQ];
__device__ __nv_bfloat16 g_Wlo[DD * NQ];
__device__ __nv_bfloat16 g_Yhi[RR * KK];
__device__ __nv_bfloat16 g_Ylo[RR * KK];
__device__ __nv_bfloat16 g_Wohi[KK * DD];
__device__ __nv_bfloat16 g_Wolo[KK * DD];

// ---------------------------------------------------------------------------
// helpers
// ---------------------------------------------------------------------------
__device__ __forceinline__ uint32_t smaddr(const void* p) {
    return (uint32_t)__cvta_generic_to_shared(p);
}
__device__ __forceinline__ void ldsm_x4(uint32_t& r0, uint32_t& r1,
                                        uint32_t& r2, uint32_t& r3, uint32_t a) {
    asm volatile("ldmatrix.sync.aligned.m8n8.x4.shared.b16 {%0,%1,%2,%3}, [%4];"
                 : "=r"(r0), "=r"(r1), "=r"(r2), "=r"(r3) : "r"(a));
}
__device__ __forceinline__ void ldsm_x4_t(uint32_t& r0, uint32_t& r1,
                                          uint32_t& r2, uint32_t& r3, uint32_t a) {
    asm volatile("ldmatrix.sync.aligned.m8n8.x4.trans.shared.b16 {%0,%1,%2,%3}, [%4];"
                 : "=r"(r0), "=r"(r1), "=r"(r2), "=r"(r3) : "r"(a));
}
__device__ __forceinline__ void mma_bf16(float* c, const uint32_t* a,
                                         uint32_t b0, uint32_t b1) {
    asm volatile(
        "mma.sync.aligned.m16n8k16.row.col.f32.bf16.bf16.f32 "
        "{%0,%1,%2,%3}, {%4,%5,%6,%7}, {%8,%9}, {%0,%1,%2,%3};"
        : "+f"(c[0]), "+f"(c[1]), "+f"(c[2]), "+f"(c[3])
        : "r"(a[0]), "r"(a[1]), "r"(a[2]), "r"(a[3]), "r"(b0), "r"(b1));
}

// ---------------------------------------------------------------------------
// Kernel A: partial W_pre[D,T] @ [Q_filt | K_filt]  (split-K over T, 8 splits)
// ---------------------------------------------------------------------------
__global__ __launch_bounds__(256) void wfilt_partial(
    const float* __restrict__ W_pre,
    const float* __restrict__ Q_filt,
    const float* __restrict__ K_filt)
{
    __shared__ float Wp[64][33];
    __shared__ float Fs[32][128];
    int d0 = blockIdx.x * 64;
    int split = blockIdx.y;
    int tid = threadIdx.x;
    int ty = tid >> 4, tx = tid & 15;
    float acc[4][8];
#pragma unroll
    for (int i = 0; i < 4; i++)
#pragma unroll
        for (int j = 0; j < 8; j++) acc[i][j] = 0.f;

    int t0 = split * 256;
    for (int kt = t0; kt < t0 + 256; kt += 32) {
        for (int i = tid; i < 64 * 32; i += 256) {
            int r = i >> 5, c = i & 31;
            Wp[r][c] = W_pre[(d0 + r) * TT + kt + c];
        }
        for (int i = tid; i < 32 * 128; i += 256) {
            int r = i >> 7, c = i & 127;
            Fs[r][c] = (c < 64) ? Q_filt[(kt + r) * KK + c]
                                : K_filt[(kt + r) * KK + (c - 64)];
        }
        __syncthreads();
#pragma unroll
        for (int kk = 0; kk < 32; kk++) {
            float a[4];
#pragma unroll
            for (int i = 0; i < 4; i++) a[i] = Wp[ty * 4 + i][kk];
            const float4* F4 = (const float4*)&Fs[kk][0];
            float4 b0 = F4[tx * 2 + 0];
            float4 b1 = F4[tx * 2 + 1];
            float bb[8] = {b0.x, b0.y, b0.z, b0.w, b1.x, b1.y, b1.z, b1.w};
#pragma unroll
            for (int i = 0; i < 4; i++)
#pragma unroll
                for (int j = 0; j < 8; j++) acc[i][j] += a[i] * bb[j];
        }
        __syncthreads();
    }
#pragma unroll
    for (int i = 0; i < 4; i++)
#pragma unroll
        for (int j = 0; j < 8; j++)
            g_Wpart[(split * DD + d0 + ty * 4 + i) * 128 + tx * 8 + j] = acc[i][j];
}

// ---------------------------------------------------------------------------
// Kernel A2: reduce split-K partials + W_v, write bf16 hi/lo directly
// ---------------------------------------------------------------------------
__global__ void wqkv_finalize(const float* __restrict__ W_v)
{
    int idx = blockIdx.x * blockDim.x + threadIdx.x;
    if (idx >= DD * NQ) return;
    int d = idx / NQ, j = idx % NQ;
    float s;
    if (j < 128) {
        s = 0.f;
#pragma unroll
        for (int p = 0; p < 8; p++) s += g_Wpart[(p * DD + d) * 128 + j];
    } else {
        s = W_v[d * KK + (j - 128)];
    }
    __nv_bfloat16 h = __float2bfloat16_rn(s);
    g_Whi[idx] = h;
    g_Wlo[idx] = __float2bfloat16_rn(s - __bfloat162float(h));
}

// ---------------------------------------------------------------------------
// Kernel A3: biases — PROVEN R3 version: one block per column (192 blocks),
// 256-thread tree reduce. Occupancy >> access-pattern at this size.
// ---------------------------------------------------------------------------
__global__ __launch_bounds__(256) void bias_kernel(
    const float* __restrict__ b_pre,
    const float* __restrict__ Q_filt,
    const float* __restrict__ K_filt,
    const float* __restrict__ b_v)
{
    int j = blockIdx.x;                 // 0..191
    int tid = threadIdx.x;
    if (j >= 128) {
        if (tid == 0) g_bqkv[j] = b_v[j - 128];
        return;
    }
    const float* F = (j < 64) ? Q_filt : K_filt;
    int col = j & 63;
    float s = 0.f;
    for (int t = tid; t < TT; t += 256)
        s += b_pre[t] * F[t * KK + col];
#pragma unroll
    for (int o = 16; o > 0; o >>= 1)
        s += __shfl_xor_sync(0xffffffff, s, o);
    __shared__ float red[8];
    if ((tid & 31) == 0) red[tid >> 5] = s;
    __syncthreads();
    if (tid == 0) {
        float tot = 0.f;
#pragma unroll
        for (int w = 0; w < 8; w++) tot += red[w];
        g_bqkv[j] = tot;
    }
}

// ---------------------------------------------------------------------------
// Split kernels: fp32 -> bf16 hi/lo pairs
// ---------------------------------------------------------------------------
__global__ __launch_bounds__(256) void split_x(const float* __restrict__ x)
{
    int i = blockIdx.x * blockDim.x + threadIdx.x;   // one float4 per thread
    float4 v = ((const float4*)x)[i];
    __nv_bfloat16 h[4], l[4];
    float f[4] = {v.x, v.y, v.z, v.w};
#pragma unroll
    for (int j = 0; j < 4; j++) {
        h[j] = __float2bfloat16_rn(f[j]);
        l[j] = __float2bfloat16_rn(f[j] - __bfloat162float(h[j]));
    }
    *(uint2*)&g_xhi[i * 4] = *(uint2*)h;
    *(uint2*)&g_xlo[i * 4] = *(uint2*)l;
}

__global__ __launch_bounds__(256) void wo_split(const float* __restrict__ W_o)
{
    int i = blockIdx.x * blockDim.x + threadIdx.x;   // one float4 per thread
    float4 v = ((const float4*)W_o)[i];
    __nv_bfloat16 h[4], l[4];
    float f[4] = {v.x, v.y, v.z, v.w};
#pragma unroll
    for (int j = 0; j < 4; j++) {
        h[j] = __float2bfloat16_rn(f[j]);
        l[j] = __float2bfloat16_rn(f[j] - __bfloat162float(h[j]));
    }
    *(uint2*)&g_Wohi[i * 4] = *(uint2*)h;
    *(uint2*)&g_Wolo[i * 4] = *(uint2*)l;
}

// ---------------------------------------------------------------------------
// Kernel B: QKV GEMM on tensor cores, bf16 split (3 phases packed as K=3072)
// Double-buffered smem (plain stores), ONE __syncthreads per k-iter.
// Block tile 128x64, 8 warps (4m x 2n), warp tile 32x32, k-step 32.
// ---------------------------------------------------------------------------
#define APITCH 40
#define BPITCH 72
__global__ __launch_bounds__(256) void qkv_mma()
{
    __shared__ __nv_bfloat16 As[2][128][APITCH];
    __shared__ __nv_bfloat16 Bs[2][32][BPITCH];
    int r0 = blockIdx.x * 128;
    int n0 = blockIdx.y * 64;
    int tid = threadIdx.x;
    int lane = tid & 31, w = tid >> 5;
    int wm = (w & 3) * 32, wn = (w >> 2) * 32;

    float acc[2][4][4];
#pragma unroll
    for (int mt = 0; mt < 2; mt++)
#pragma unroll
        for (int nt = 0; nt < 4; nt++)
#pragma unroll
            for (int r = 0; r < 4; r++) acc[mt][nt][r] = 0.f;

    int ar = tid >> 2, ac = (tid & 3) * 8;      // A: rows ar, ar+64 ; 8 bf16 each
    int br = tid >> 3, bc = (tid & 7) * 8;      // B: one 8-bf16 vector

    float4 a0v, a1v, bv;
    // iter 0 -> regs -> smem buf 0
    a0v = *(const float4*)&g_xhi[(r0 + ar) * DD + ac];
    a1v = *(const float4*)&g_xhi[(r0 + ar + 64) * DD + ac];
    bv  = *(const float4*)&g_Whi[br * NQ + n0 + bc];
    *(float4*)&As[0][ar][ac]      = a0v;
    *(float4*)&As[0][ar + 64][ac] = a1v;
    *(float4*)&Bs[0][br][bc]      = bv;
    __syncthreads();

    for (int it = 0; it < 96; it++) {
        int buf = it & 1;
        bool more = (it + 1 < 96);
        if (more) {
            int kt = (it + 1) * 32;
            int phase = kt >> 10;
            int kk = kt & 1023;
            const __nv_bfloat16* Asrc = (phase == 1) ? g_xlo : g_xhi;
            const __nv_bfloat16* Bsrc = (phase == 2) ? g_Wlo : g_Whi;
            a0v = *(const float4*)&Asrc[(r0 + ar) * DD + kk + ac];
            a1v = *(const float4*)&Asrc[(r0 + ar + 64) * DD + kk + ac];
            bv  = *(const float4*)&Bsrc[(kk + br) * NQ + n0 + bc];
        }

#pragma unroll
        for (int ks = 0; ks < 2; ks++) {
            int k = ks * 16;
            uint32_t a[2][4];
#pragma unroll
            for (int mt = 0; mt < 2; mt++) {
                uint32_t ad = smaddr(&As[buf][wm + mt * 16 + (lane & 15)][k + ((lane >> 4) << 3)]);
                ldsm_x4(a[mt][0], a[mt][1], a[mt][2], a[mt][3], ad);
            }
            uint32_t b[2][4];
#pragma unroll
            for (int nb = 0; nb < 2; nb++) {
                uint32_t bd = smaddr(&Bs[buf][k + (lane & 15)][wn + nb * 16 + ((lane >> 4) << 3)]);
                ldsm_x4_t(b[nb][0], b[nb][1], b[nb][2], b[nb][3], bd);
            }
#pragma unroll
            for (int mt = 0; mt < 2; mt++)
#pragma unroll
                for (int nt = 0; nt < 4; nt++) {
                    int nb = nt >> 1, pr = nt & 1;
                    mma_bf16(acc[mt][nt], a[mt], b[nb][pr * 2], b[nb][pr * 2 + 1]);
                }
        }

        if (more) {
            *(float4*)&As[buf ^ 1][ar][ac]      = a0v;
            *(float4*)&As[buf ^ 1][ar + 64][ac] = a1v;
            *(float4*)&Bs[buf ^ 1][br][bc]      = bv;
            __syncthreads();
        }
    }

    // epilogue: add bias, write fp32 QKV
    int gr = lane >> 2, tc = (lane & 3) * 2;
#pragma unroll
    for (int mt = 0; mt < 2; mt++)
#pragma unroll
        for (int nt = 0; nt < 4; nt++) {
            int row = r0 + wm + mt * 16 + gr;
            int col = n0 + wn + nt * 8 + tc;
            float bb0 = g_bqkv[col], bb1 = g_bqkv[col + 1];
            g_QKV[row * NQ + col]           = acc[mt][nt][0] + bb0;
            g_QKV[row * NQ + col + 1]       = acc[mt][nt][1] + bb1;
            g_QKV[(row + 8) * NQ + col]     = acc[mt][nt][2] + bb0;
            g_QKV[(row + 8) * NQ + col + 1] = acc[mt][nt][3] + bb1;
        }
}

// ---------------------------------------------------------------------------
// Kernel C1: per-chunk state sums  S_c[p,n] = sum_s decay_s * V[s,p]*Kf[s,n]
// ---------------------------------------------------------------------------
__global__ __launch_bounds__(256) void chunk_sum(const float* __restrict__ decay)
{
    __shared__ float Vs[64][65];
    __shared__ float Ks[64][65];
    int b = blockIdx.x >> 4, c = blockIdx.x & 15;
    int base = b * TT + c * CH;
    int tid = threadIdx.x;
    int ty = tid >> 4, tx = tid & 15;
    float acc[4][4];
#pragma unroll
    for (int i = 0; i < 4; i++)
#pragma unroll
        for (int j = 0; j < 4; j++) acc[i][j] = 0.f;

    for (int st = 0; st < CH; st += 64) {
        for (int i = tid; i < 64 * 64; i += 256) {
            int r = i >> 6, k = i & 63;
            int row = base + st + r;
            float d = decay[c * CH + st + r];
            Vs[r][k] = g_QKV[row * NQ + 128 + k];
            Ks[r][k] = g_QKV[row * NQ + 64 + k] * d;
        }
        __syncthreads();
#pragma unroll 8
        for (int s = 0; s < 64; s++) {
            float a[4], bb[4];
#pragma unroll
            for (int i = 0; i < 4; i++) a[i] = Vs[s][ty * 4 + i];
#pragma unroll
            for (int j = 0; j < 4; j++) bb[j] = Ks[s][tx * 4 + j];
#pragma unroll
            for (int i = 0; i < 4; i++)
#pragma unroll
                for (int j = 0; j < 4; j++) acc[i][j] += a[i] * bb[j];
        }
        __syncthreads();
    }
    int sb = (b * NC + c) * KK * KK;
#pragma unroll
    for (int i = 0; i < 4; i++)
#pragma unroll
        for (int j = 0; j < 4; j++)
            g_S[sb + (ty * 4 + i) * KK + tx * 4 + j] = acc[i][j];
}

// ---------------------------------------------------------------------------
// Kernel C2: exclusive prefix over chunks — 64 blocks for SM coverage
// ---------------------------------------------------------------------------
__global__ __launch_bounds__(256) void chunk_prefix()
{
    int b = blockIdx.x >> 4;
    int e = (blockIdx.x & 15) * 256 + threadIdx.x;   // 0..4095
    float acc = 0.f;
    for (int c = 0; c < NC; c++) {
        int idx = (b * NC + c) * KK * KK + e;
        g_H[idx] = acc;
        acc += g_S[idx];
    }
}

// ---------------------------------------------------------------------------
// Kernel C3: Y_chunk = Q @ H_prev + causal intra-chunk; emits Y as bf16 hi/lo
// ---------------------------------------------------------------------------
__global__ __launch_bounds__(256) void attn_kernel(const float* __restrict__ decay)
{
    __shared__ float Qt[KK][CH];
    __shared__ float Reg[4096];
    int b = blockIdx.x >> 4, c = blockIdx.x & 15;
    int base = b * TT + c * CH;
    int tid = threadIdx.x;
    int row = tid >> 1;
    int half = tid & 1;

    for (int i = tid; i < KK * CH; i += 256) {
        int r = i & (CH - 1), k = i >> 7;
        Qt[k][r] = g_QKV[(base + r) * NQ + k];
    }
    int hb = (b * NC + c) * KK * KK;
    for (int i = tid; i < KK * KK; i += 256) Reg[i] = g_H[hb + i];
    __syncthreads();

    float q[KK];
#pragma unroll
    for (int k = 0; k < KK; k++) q[k] = Qt[k][row];

    float y[32];
#pragma unroll
    for (int j = 0; j < 32; j++) y[j] = 0.f;

    {
        const float4* H4 = (const float4*)Reg;
#pragma unroll
        for (int k = 0; k < KK; k++) {
            float qk = q[k];
#pragma unroll
            for (int jj = 0; jj < 8; jj++) {
                float4 h = H4[k * 16 + half * 8 + jj];
                y[jj * 4 + 0] += qk * h.x;
                y[jj * 4 + 1] += qk * h.y;
                y[jj * 4 + 2] += qk * h.z;
                y[jj * 4 + 3] += qk * h.w;
            }
        }
    }
    __syncthreads();

    for (int st = 0; st < CH; st += 32) {
        for (int i = tid; i < 2048; i += 256) {
            int s = i >> 6, k = i & 63;
            int grow = (base + st + s) * NQ;
            Reg[i]        = g_QKV[grow + 128 + k];
            Reg[2048 + i] = g_QKV[grow + 64 + k] * decay[c * CH + st + s];
        }
        __syncthreads();
        if (row >= st) {
            int sm = row - st + 1;
            if (sm > 32) sm = 32;
            const float4* V4 = (const float4*)Reg;
            const float4* F4 = (const float4*)(Reg + 2048);
            for (int s = 0; s < sm; s++) {
                float sc = 0.f;
#pragma unroll
                for (int kk = 0; kk < 16; kk++) {
                    float4 v = V4[s * 16 + kk];
                    sc += q[kk * 4 + 0] * v.x + q[kk * 4 + 1] * v.y
                        + q[kk * 4 + 2] * v.z + q[kk * 4 + 3] * v.w;
                }
#pragma unroll
                for (int jj = 0; jj < 8; jj++) {
                    float4 f = F4[s * 16 + half * 8 + jj];
                    y[jj * 4 + 0] += sc * f.x;
                    y[jj * 4 + 1] += sc * f.y;
                    y[jj * 4 + 2] += sc * f.z;
                    y[jj * 4 + 3] += sc * f.w;
                }
            }
        }
        __syncthreads();
    }

    // epilogue: split to bf16 hi/lo, 8-byte packed stores
    int ybase = (base + row) * KK + half * 32;
#pragma unroll
    for (int jj = 0; jj < 8; jj++) {
        __nv_bfloat16 hp[4], lp[4];
#pragma unroll
        for (int e = 0; e < 4; e++) {
            float f = y[jj * 4 + e];
            hp[e] = __float2bfloat16_rn(f);
            lp[e] = __float2bfloat16_rn(f - __bfloat162float(hp[e]));
        }
        *(uint2*)&g_Yhi[ybase + jj * 4] = *(uint2*)hp;
        *(uint2*)&g_Ylo[ybase + jj * 4] = *(uint2*)lp;
    }
}

// ---------------------------------------------------------------------------
// Kernel D: out = Y @ W_o + b_o  on tensor cores (3-term split, K packed=192)
// Block tile 128x64, 8 warps, 6 k-iters of 32. Register-prefetch pattern.
// ---------------------------------------------------------------------------
__global__ __launch_bounds__(256) void out_mma(const float* __restrict__ b_o,
                                               float* __restrict__ out)
{
    __shared__ __nv_bfloat16 As[128][APITCH];
    __shared__ __nv_bfloat16 Bs[32][BPITCH];
    int r0 = blockIdx.x * 128;
    int n0 = blockIdx.y * 64;
    int tid = threadIdx.x;
    int lane = tid & 31, w = tid >> 5;
    int wm = (w & 3) * 32, wn = (w >> 2) * 32;

    float acc[2][4][4];
#pragma unroll
    for (int mt = 0; mt < 2; mt++)
#pragma unroll
        for (int nt = 0; nt < 4; nt++)
#pragma unroll
            for (int r = 0; r < 4; r++) acc[mt][nt][r] = 0.f;

    int ar = tid >> 2, ac = (tid & 3) * 8;
    int br = tid >> 3, bc = (tid & 7) * 8;

    float4 a0v, a1v, bv;
    {   // prefetch iter 0: phase 0 (Yhi, Wohi), kk = 0
        a0v = *(const float4*)&g_Yhi[(r0 + ar) * KK + ac];
        a1v = *(const float4*)&g_Yhi[(r0 + ar + 64) * KK + ac];
        bv  = *(const float4*)&g_Wohi[br * DD + n0 + bc];
    }

    for (int it = 0; it < 6; it++) {
        *(float4*)&As[ar][ac]      = a0v;
        *(float4*)&As[ar + 64][ac] = a1v;
        *(float4*)&Bs[br][bc]      = bv;
        __syncthreads();

        if (it + 1 < 6) {
            int nit = it + 1;
            int phase = nit >> 1;
            int kk = (nit & 1) * 32;
            const __nv_bfloat16* Asrc = (phase == 1) ? g_Ylo : g_Yhi;
            const __nv_bfloat16* Bsrc = (phase == 2) ? g_Wolo : g_Wohi;
            a0v = *(const float4*)&Asrc[(r0 + ar) * KK + kk + ac];
            a1v = *(const float4*)&Asrc[(r0 + ar + 64) * KK + kk + ac];
            bv  = *(const float4*)&Bsrc[(kk + br) * DD + n0 + bc];
        }

#pragma unroll
        for (int ks = 0; ks < 2; ks++) {
            int k = ks * 16;
            uint32_t a[2][4];
#pragma unroll
            for (int mt = 0; mt < 2; mt++) {
                uint32_t ad = smaddr(&As[wm + mt * 16 + (lane & 15)][k + ((lane >> 4) << 3)]);
                ldsm_x4(a[mt][0], a[mt][1], a[mt][2], a[mt][3], ad);
            }
            uint32_t b[2][4];
#pragma unroll
            for (int nb = 0; nb < 2; nb++) {
                uint32_t bd = smaddr(&Bs[k + (lane & 15)][wn + nb * 16 + ((lane >> 4) << 3)]);
                ldsm_x4_t(b[nb][0], b[nb][1], b[nb][2], b[nb][3], bd);
            }
#pragma unroll
            for (int mt = 0; mt < 2; mt++)
#pragma unroll
                for (int nt = 0; nt < 4; nt++) {
                    int nb = nt >> 1, pr = nt & 1;
                    mma_bf16(acc[mt][nt], a[mt], b[nb][pr * 2], b[nb][pr * 2 + 1]);
                }
        }
        __syncthreads();
    }

    int gr = lane >> 2, tc = (lane & 3) * 2;
#pragma unroll
    for (int mt = 0; mt < 2; mt++)
#pragma unroll
        for (int nt = 0; nt < 4; nt++) {
            int row = r0 + wm + mt * 16 + gr;
            int col = n0 + wn + nt * 8 + tc;
            float bb0 = b_o[col], bb1 = b_o[col + 1];
            out[row * DD + col]           = acc[mt][nt][0] + bb0;
            out[row * DD + col + 1]       = acc[mt][nt][1] + bb1;
            out[(row + 8) * DD + col]     = acc[mt][nt][2] + bb0;
            out[(row + 8) * DD + col + 1] = acc[mt][nt][3] + bb1;
        }
}

// ---------------------------------------------------------------------------
extern "C" void kernel_launch(void* const* d_in, const int* in_sizes, int n_in,
                              void* d_out, int out_size)
{
    const float* x      = (const float*)d_in[0];
    const float* W_pre  = (const float*)d_in[1];
    const float* b_pre  = (const float*)d_in[2];
    const float* Q_filt = (const float*)d_in[3];
    const float* K_filt = (const float*)d_in[4];
    const float* W_v    = (const float*)d_in[5];
    const float* b_v    = (const float*)d_in[6];
    const float* W_o    = (const float*)d_in[7];
    const float* b_o    = (const float*)d_in[8];
    const float* decay  = (const float*)d_in[9];
    float* out = (float*)d_out;

    split_x<<<(RR * DD / 4) / 256, 256>>>(x);
    wfilt_partial<<<dim3(16, 8), 256>>>(W_pre, Q_filt, K_filt);
    wqkv_finalize<<<(DD * NQ + 255) / 256, 256>>>(W_v);
    bias_kernel<<<192, 256>>>(b_pre, Q_filt, K_filt, b_v);
    wo_split<<<(KK * DD / 4) / 256, 256>>>(W_o);
    qkv_mma<<<dim3(64, 3), 256>>>();
    chunk_sum<<<64, 256>>>(decay);
    chunk_prefix<<<64, 256>>>();
    attn_kernel<<<64, 256>>>(decay);
    out_mma<<<dim3(64, 16), 256>>>(b_o, out);
}

// round 10
// speedup vs baseline: 1.5392x; 1.0715x over previous
#include <cuda_runtime.h>
#include <cuda_bf16.h>
#include <cstdint>

// Problem constants
#define BB 4
#define TT 2048
#define DD 1024
#define KK 64
#define RR (BB*TT)        // 8192 rows
#define NQ 192            // Q|K|V packed cols
#define CH 128            // chunk length
#define NC (TT/CH)        // 16 chunks per batch

// Scratch (device globals — no allocation allowed)
__device__ float g_Wpart[8 * DD * 128];          // split-K partials for W_pre@[Qf|Kf]
__device__ float g_bqkv[NQ];
__device__ float g_QKV[RR * NQ];                 // [row, 192]
__device__ float g_S[BB * NC * KK * KK];         // per-chunk state sums
__device__ float g_H[BB * NC * KK * KK];         // exclusive prefix states
// bf16 split operands
__device__ __nv_bfloat16 g_xhi[RR * DD];
__device__ __nv_bfloat16 g_xlo[RR * DD];
__device__ __nv_bfloat16 g_Whi[DD * NQ];
__device__ __nv_bfloat16 g_Wlo[DD * NQ];
__device__ __nv_bfloat16 g_Yhi[RR * KK];
__device__ __nv_bfloat16 g_Ylo[RR * KK];
__device__ __nv_bfloat16 g_Wohi[KK * DD];
__device__ __nv_bfloat16 g_Wolo[KK * DD];

// ---------------------------------------------------------------------------
// helpers
// ---------------------------------------------------------------------------
__device__ __forceinline__ uint32_t smaddr(const void* p) {
    return (uint32_t)__cvta_generic_to_shared(p);
}
__device__ __forceinline__ void ldsm_x4(uint32_t& r0, uint32_t& r1,
                                        uint32_t& r2, uint32_t& r3, uint32_t a) {
    asm volatile("ldmatrix.sync.aligned.m8n8.x4.shared.b16 {%0,%1,%2,%3}, [%4];"
                 : "=r"(r0), "=r"(r1), "=r"(r2), "=r"(r3) : "r"(a));
}
__device__ __forceinline__ void ldsm_x4_t(uint32_t& r0, uint32_t& r1,
                                          uint32_t& r2, uint32_t& r3, uint32_t a) {
    asm volatile("ldmatrix.sync.aligned.m8n8.x4.trans.shared.b16 {%0,%1,%2,%3}, [%4];"
                 : "=r"(r0), "=r"(r1), "=r"(r2), "=r"(r3) : "r"(a));
}
__device__ __forceinline__ void mma_bf16(float* c, const uint32_t* a,
                                         uint32_t b0, uint32_t b1) {
    asm volatile(
        "mma.sync.aligned.m16n8k16.row.col.f32.bf16.bf16.f32 "
        "{%0,%1,%2,%3}, {%4,%5,%6,%7}, {%8,%9}, {%0,%1,%2,%3};"
        : "+f"(c[0]), "+f"(c[1]), "+f"(c[2]), "+f"(c[3])
        : "r"(a[0]), "r"(a[1]), "r"(a[2]), "r"(a[3]), "r"(b0), "r"(b1));
}

// ---------------------------------------------------------------------------
// Fused preprocessing kernel: all consumers of raw inputs, run concurrently.
//   blocks [0,128)        : wfilt_partial  (16 d-tiles x 8 splits)
//   blocks [128,320)      : bias columns   (192)
//   blocks [320,384)      : wo_split       (64)
//   blocks [384,8576)     : split_x        (8192)
// ---------------------------------------------------------------------------
#define NB_WF   128
#define NB_BIAS 192
#define NB_WO   64
#define NB_SX   8192
__global__ __launch_bounds__(256) void prep_fused(
    const float* __restrict__ x,
    const float* __restrict__ W_pre,
    const float* __restrict__ b_pre,
    const float* __restrict__ Q_filt,
    const float* __restrict__ K_filt,
    const float* __restrict__ b_v,
    const float* __restrict__ W_o)
{
    __shared__ float sbuf[64 * 33 + 32 * 128];   // 24.8 KB, role-dependent
    int bid = blockIdx.x;
    int tid = threadIdx.x;

    if (bid < NB_WF) {
        // ---------------- wfilt_partial ----------------
        float (*Wp)[33]  = (float(*)[33])sbuf;
        float (*Fs)[128] = (float(*)[128])(sbuf + 64 * 33);
        int d0 = (bid & 15) * 64;
        int split = bid >> 4;
        int ty = tid >> 4, tx = tid & 15;
        float acc[4][8];
#pragma unroll
        for (int i = 0; i < 4; i++)
#pragma unroll
            for (int j = 0; j < 8; j++) acc[i][j] = 0.f;

        int t0 = split * 256;
        for (int kt = t0; kt < t0 + 256; kt += 32) {
            for (int i = tid; i < 64 * 32; i += 256) {
                int r = i >> 5, c = i & 31;
                Wp[r][c] = W_pre[(d0 + r) * TT + kt + c];
            }
            for (int i = tid; i < 32 * 128; i += 256) {
                int r = i >> 7, c = i & 127;
                Fs[r][c] = (c < 64) ? Q_filt[(kt + r) * KK + c]
                                    : K_filt[(kt + r) * KK + (c - 64)];
            }
            __syncthreads();
#pragma unroll
            for (int kk = 0; kk < 32; kk++) {
                float a[4];
#pragma unroll
                for (int i = 0; i < 4; i++) a[i] = Wp[ty * 4 + i][kk];
                const float4* F4 = (const float4*)&Fs[kk][0];
                float4 b0 = F4[tx * 2 + 0];
                float4 b1 = F4[tx * 2 + 1];
                float bb[8] = {b0.x, b0.y, b0.z, b0.w, b1.x, b1.y, b1.z, b1.w};
#pragma unroll
                for (int i = 0; i < 4; i++)
#pragma unroll
                    for (int j = 0; j < 8; j++) acc[i][j] += a[i] * bb[j];
            }
            __syncthreads();
        }
#pragma unroll
        for (int i = 0; i < 4; i++)
#pragma unroll
            for (int j = 0; j < 8; j++)
                g_Wpart[(split * DD + d0 + ty * 4 + i) * 128 + tx * 8 + j] = acc[i][j];
    } else if (bid < NB_WF + NB_BIAS) {
        // ---------------- bias columns ----------------
        int j = bid - NB_WF;            // 0..191
        if (j >= 128) {
            if (tid == 0) g_bqkv[j] = b_v[j - 128];
            return;
        }
        const float* F = (j < 64) ? Q_filt : K_filt;
        int col = j & 63;
        float s = 0.f;
        for (int t = tid; t < TT; t += 256)
            s += b_pre[t] * F[t * KK + col];
#pragma unroll
        for (int o = 16; o > 0; o >>= 1)
            s += __shfl_xor_sync(0xffffffff, s, o);
        float* red = sbuf;
        if ((tid & 31) == 0) red[tid >> 5] = s;
        __syncthreads();
        if (tid == 0) {
            float tot = 0.f;
#pragma unroll
            for (int w = 0; w < 8; w++) tot += red[w];
            g_bqkv[j] = tot;
        }
    } else if (bid < NB_WF + NB_BIAS + NB_WO) {
        // ---------------- wo_split ----------------
        int i = (bid - NB_WF - NB_BIAS) * 256 + tid;
        float4 v = ((const float4*)W_o)[i];
        __nv_bfloat16 h[4], l[4];
        float f[4] = {v.x, v.y, v.z, v.w};
#pragma unroll
        for (int j = 0; j < 4; j++) {
            h[j] = __float2bfloat16_rn(f[j]);
            l[j] = __float2bfloat16_rn(f[j] - __bfloat162float(h[j]));
        }
        *(uint2*)&g_Wohi[i * 4] = *(uint2*)h;
        *(uint2*)&g_Wolo[i * 4] = *(uint2*)l;
    } else {
        // ---------------- split_x ----------------
        int i = (bid - NB_WF - NB_BIAS - NB_WO) * 256 + tid;
        float4 v = ((const float4*)x)[i];
        __nv_bfloat16 h[4], l[4];
        float f[4] = {v.x, v.y, v.z, v.w};
#pragma unroll
        for (int j = 0; j < 4; j++) {
            h[j] = __float2bfloat16_rn(f[j]);
            l[j] = __float2bfloat16_rn(f[j] - __bfloat162float(h[j]));
        }
        *(uint2*)&g_xhi[i * 4] = *(uint2*)h;
        *(uint2*)&g_xlo[i * 4] = *(uint2*)l;
    }
}

// ---------------------------------------------------------------------------
// Kernel A2: reduce split-K partials + W_v, write bf16 hi/lo directly
// ---------------------------------------------------------------------------
__global__ void wqkv_finalize(const float* __restrict__ W_v)
{
    int idx = blockIdx.x * blockDim.x + threadIdx.x;
    if (idx >= DD * NQ) return;
    int d = idx / NQ, j = idx % NQ;
    float s;
    if (j < 128) {
        s = 0.f;
#pragma unroll
        for (int p = 0; p < 8; p++) s += g_Wpart[(p * DD + d) * 128 + j];
    } else {
        s = W_v[d * KK + (j - 128)];
    }
    __nv_bfloat16 h = __float2bfloat16_rn(s);
    g_Whi[idx] = h;
    g_Wlo[idx] = __float2bfloat16_rn(s - __bfloat162float(h));
}

// ---------------------------------------------------------------------------
// Kernel B: QKV GEMM on tensor cores, bf16 split (3 phases packed as K=3072)
// Double-buffered smem, one __syncthreads per k-iter, 2 blocks/SM co-resident.
// Block tile 128x64, 8 warps (4m x 2n), warp tile 32x32, k-step 32.
// ---------------------------------------------------------------------------
#define APITCH 40
#define BPITCH 72
__global__ __launch_bounds__(256, 2) void qkv_mma()
{
    __shared__ __nv_bfloat16 As[2][128][APITCH];
    __shared__ __nv_bfloat16 Bs[2][32][BPITCH];
    int r0 = blockIdx.x * 128;
    int n0 = blockIdx.y * 64;
    int tid = threadIdx.x;
    int lane = tid & 31, w = tid >> 5;
    int wm = (w & 3) * 32, wn = (w >> 2) * 32;

    float acc[2][4][4];
#pragma unroll
    for (int mt = 0; mt < 2; mt++)
#pragma unroll
        for (int nt = 0; nt < 4; nt++)
#pragma unroll
            for (int r = 0; r < 4; r++) acc[mt][nt][r] = 0.f;

    int ar = tid >> 2, ac = (tid & 3) * 8;      // A: rows ar, ar+64 ; 8 bf16 each
    int br = tid >> 3, bc = (tid & 7) * 8;      // B: one 8-bf16 vector

    float4 a0v, a1v, bv;
    // iter 0 -> regs -> smem buf 0
    a0v = *(const float4*)&g_xhi[(r0 + ar) * DD + ac];
    a1v = *(const float4*)&g_xhi[(r0 + ar + 64) * DD + ac];
    bv  = *(const float4*)&g_Whi[br * NQ + n0 + bc];
    *(float4*)&As[0][ar][ac]      = a0v;
    *(float4*)&As[0][ar + 64][ac] = a1v;
    *(float4*)&Bs[0][br][bc]      = bv;
    __syncthreads();

    for (int it = 0; it < 96; it++) {
        int buf = it & 1;
        bool more = (it + 1 < 96);
        if (more) {
            int kt = (it + 1) * 32;
            int phase = kt >> 10;
            int kk = kt & 1023;
            const __nv_bfloat16* Asrc = (phase == 1) ? g_xlo : g_xhi;
            const __nv_bfloat16* Bsrc = (phase == 2) ? g_Wlo : g_Whi;
            a0v = *(const float4*)&Asrc[(r0 + ar) * DD + kk + ac];
            a1v = *(const float4*)&Asrc[(r0 + ar + 64) * DD + kk + ac];
            bv  = *(const float4*)&Bsrc[(kk + br) * NQ + n0 + bc];
        }

#pragma unroll
        for (int ks = 0; ks < 2; ks++) {
            int k = ks * 16;
            uint32_t a[2][4];
#pragma unroll
            for (int mt = 0; mt < 2; mt++) {
                uint32_t ad = smaddr(&As[buf][wm + mt * 16 + (lane & 15)][k + ((lane >> 4) << 3)]);
                ldsm_x4(a[mt][0], a[mt][1], a[mt][2], a[mt][3], ad);
            }
            uint32_t b[2][4];
#pragma unroll
            for (int nb = 0; nb < 2; nb++) {
                uint32_t bd = smaddr(&Bs[buf][k + (lane & 15)][wn + nb * 16 + ((lane >> 4) << 3)]);
                ldsm_x4_t(b[nb][0], b[nb][1], b[nb][2], b[nb][3], bd);
            }
#pragma unroll
            for (int mt = 0; mt < 2; mt++)
#pragma unroll
                for (int nt = 0; nt < 4; nt++) {
                    int nb = nt >> 1, pr = nt & 1;
                    mma_bf16(acc[mt][nt], a[mt], b[nb][pr * 2], b[nb][pr * 2 + 1]);
                }
        }

        if (more) {
            *(float4*)&As[buf ^ 1][ar][ac]      = a0v;
            *(float4*)&As[buf ^ 1][ar + 64][ac] = a1v;
            *(float4*)&Bs[buf ^ 1][br][bc]      = bv;
            __syncthreads();
        }
    }

    // epilogue: add bias, write fp32 QKV
    int gr = lane >> 2, tc = (lane & 3) * 2;
#pragma unroll
    for (int mt = 0; mt < 2; mt++)
#pragma unroll
        for (int nt = 0; nt < 4; nt++) {
            int row = r0 + wm + mt * 16 + gr;
            int col = n0 + wn + nt * 8 + tc;
            float bb0 = g_bqkv[col], bb1 = g_bqkv[col + 1];
            g_QKV[row * NQ + col]           = acc[mt][nt][0] + bb0;
            g_QKV[row * NQ + col + 1]       = acc[mt][nt][1] + bb1;
            g_QKV[(row + 8) * NQ + col]     = acc[mt][nt][2] + bb0;
            g_QKV[(row + 8) * NQ + col + 1] = acc[mt][nt][3] + bb1;
        }
}

// ---------------------------------------------------------------------------
// Kernel C1: per-chunk state sums  S_c[p,n] = sum_s decay_s * V[s,p]*Kf[s,n]
// ---------------------------------------------------------------------------
__global__ __launch_bounds__(256) void chunk_sum(const float* __restrict__ decay)
{
    __shared__ float Vs[64][65];
    __shared__ float Ks[64][65];
    int b = blockIdx.x >> 4, c = blockIdx.x & 15;
    int base = b * TT + c * CH;
    int tid = threadIdx.x;
    int ty = tid >> 4, tx = tid & 15;
    float acc[4][4];
#pragma unroll
    for (int i = 0; i < 4; i++)
#pragma unroll
        for (int j = 0; j < 4; j++) acc[i][j] = 0.f;

    for (int st = 0; st < CH; st += 64) {
        for (int i = tid; i < 64 * 64; i += 256) {
            int r = i >> 6, k = i & 63;
            int row = base + st + r;
            float d = decay[c * CH + st + r];
            Vs[r][k] = g_QKV[row * NQ + 128 + k];
            Ks[r][k] = g_QKV[row * NQ + 64 + k] * d;
        }
        __syncthreads();
#pragma unroll 8
        for (int s = 0; s < 64; s++) {
            float a[4], bb[4];
#pragma unroll
            for (int i = 0; i < 4; i++) a[i] = Vs[s][ty * 4 + i];
#pragma unroll
            for (int j = 0; j < 4; j++) bb[j] = Ks[s][tx * 4 + j];
#pragma unroll
            for (int i = 0; i < 4; i++)
#pragma unroll
                for (int j = 0; j < 4; j++) acc[i][j] += a[i] * bb[j];
        }
        __syncthreads();
    }
    int sb = (b * NC + c) * KK * KK;
#pragma unroll
    for (int i = 0; i < 4; i++)
#pragma unroll
        for (int j = 0; j < 4; j++)
            g_S[sb + (ty * 4 + i) * KK + tx * 4 + j] = acc[i][j];
}

// ---------------------------------------------------------------------------
// Kernel C2: exclusive prefix over chunks — 64 blocks for SM coverage
// ---------------------------------------------------------------------------
__global__ __launch_bounds__(256) void chunk_prefix()
{
    int b = blockIdx.x >> 4;
    int e = (blockIdx.x & 15) * 256 + threadIdx.x;   // 0..4095
    float acc = 0.f;
    for (int c = 0; c < NC; c++) {
        int idx = (b * NC + c) * KK * KK + e;
        g_H[idx] = acc;
        acc += g_S[idx];
    }
}

// ---------------------------------------------------------------------------
// Kernel C3: Y_chunk = Q @ H_prev + causal intra-chunk; emits Y as bf16 hi/lo
// ---------------------------------------------------------------------------
__global__ __launch_bounds__(256) void attn_kernel(const float* __restrict__ decay)
{
    __shared__ float Qt[KK][CH];
    __shared__ float Reg[4096];
    int b = blockIdx.x >> 4, c = blockIdx.x & 15;
    int base = b * TT + c * CH;
    int tid = threadIdx.x;
    int row = tid >> 1;
    int half = tid & 1;

    for (int i = tid; i < KK * CH; i += 256) {
        int r = i & (CH - 1), k = i >> 7;
        Qt[k][r] = g_QKV[(base + r) * NQ + k];
    }
    int hb = (b * NC + c) * KK * KK;
    for (int i = tid; i < KK * KK; i += 256) Reg[i] = g_H[hb + i];
    __syncthreads();

    float q[KK];
#pragma unroll
    for (int k = 0; k < KK; k++) q[k] = Qt[k][row];

    float y[32];
#pragma unroll
    for (int j = 0; j < 32; j++) y[j] = 0.f;

    {
        const float4* H4 = (const float4*)Reg;
#pragma unroll
        for (int k = 0; k < KK; k++) {
            float qk = q[k];
#pragma unroll
            for (int jj = 0; jj < 8; jj++) {
                float4 h = H4[k * 16 + half * 8 + jj];
                y[jj * 4 + 0] += qk * h.x;
                y[jj * 4 + 1] += qk * h.y;
                y[jj * 4 + 2] += qk * h.z;
                y[jj * 4 + 3] += qk * h.w;
            }
        }
    }
    __syncthreads();

    for (int st = 0; st < CH; st += 32) {
        for (int i = tid; i < 2048; i += 256) {
            int s = i >> 6, k = i & 63;
            int grow = (base + st + s) * NQ;
            Reg[i]        = g_QKV[grow + 128 + k];
            Reg[2048 + i] = g_QKV[grow + 64 + k] * decay[c * CH + st + s];
        }
        __syncthreads();
        if (row >= st) {
            int sm = row - st + 1;
            if (sm > 32) sm = 32;
            const float4* V4 = (const float4*)Reg;
            const float4* F4 = (const float4*)(Reg + 2048);
            for (int s = 0; s < sm; s++) {
                float sc = 0.f;
#pragma unroll
                for (int kk = 0; kk < 16; kk++) {
                    float4 v = V4[s * 16 + kk];
                    sc += q[kk * 4 + 0] * v.x + q[kk * 4 + 1] * v.y
                        + q[kk * 4 + 2] * v.z + q[kk * 4 + 3] * v.w;
                }
#pragma unroll
                for (int jj = 0; jj < 8; jj++) {
                    float4 f = F4[s * 16 + half * 8 + jj];
                    y[jj * 4 + 0] += sc * f.x;
                    y[jj * 4 + 1] += sc * f.y;
                    y[jj * 4 + 2] += sc * f.z;
                    y[jj * 4 + 3] += sc * f.w;
                }
            }
        }
        __syncthreads();
    }

    // epilogue: split to bf16 hi/lo, 8-byte packed stores
    int ybase = (base + row) * KK + half * 32;
#pragma unroll
    for (int jj = 0; jj < 8; jj++) {
        __nv_bfloat16 hp[4], lp[4];
#pragma unroll
        for (int e = 0; e < 4; e++) {
            float f = y[jj * 4 + e];
            hp[e] = __float2bfloat16_rn(f);
            lp[e] = __float2bfloat16_rn(f - __bfloat162float(hp[e]));
        }
        *(uint2*)&g_Yhi[ybase + jj * 4] = *(uint2*)hp;
        *(uint2*)&g_Ylo[ybase + jj * 4] = *(uint2*)lp;
    }
}

// ---------------------------------------------------------------------------
// Kernel D: out = Y @ W_o + b_o  on tensor cores (3-term split, K packed=192)
// Block tile 128x64, 8 warps, 6 k-iters of 32. Register-prefetch pattern.
// ---------------------------------------------------------------------------
__global__ __launch_bounds__(256, 2) void out_mma(const float* __restrict__ b_o,
                                                  float* __restrict__ out)
{
    __shared__ __nv_bfloat16 As[128][APITCH];
    __shared__ __nv_bfloat16 Bs[32][BPITCH];
    int r0 = blockIdx.x * 128;
    int n0 = blockIdx.y * 64;
    int tid = threadIdx.x;
    int lane = tid & 31, w = tid >> 5;
    int wm = (w & 3) * 32, wn = (w >> 2) * 32;

    float acc[2][4][4];
#pragma unroll
    for (int mt = 0; mt < 2; mt++)
#pragma unroll
        for (int nt = 0; nt < 4; nt++)
#pragma unroll
            for (int r = 0; r < 4; r++) acc[mt][nt][r] = 0.f;

    int ar = tid >> 2, ac = (tid & 3) * 8;
    int br = tid >> 3, bc = (tid & 7) * 8;

    float4 a0v, a1v, bv;
    {   // prefetch iter 0: phase 0 (Yhi, Wohi), kk = 0
        a0v = *(const float4*)&g_Yhi[(r0 + ar) * KK + ac];
        a1v = *(const float4*)&g_Yhi[(r0 + ar + 64) * KK + ac];
        bv  = *(const float4*)&g_Wohi[br * DD + n0 + bc];
    }

    for (int it = 0; it < 6; it++) {
        *(float4*)&As[ar][ac]      = a0v;
        *(float4*)&As[ar + 64][ac] = a1v;
        *(float4*)&Bs[br][bc]      = bv;
        __syncthreads();

        if (it + 1 < 6) {
            int nit = it + 1;
            int phase = nit >> 1;
            int kk = (nit & 1) * 32;
            const __nv_bfloat16* Asrc = (phase == 1) ? g_Ylo : g_Yhi;
            const __nv_bfloat16* Bsrc = (phase == 2) ? g_Wolo : g_Wohi;
            a0v = *(const float4*)&Asrc[(r0 + ar) * KK + kk + ac];
            a1v = *(const float4*)&Asrc[(r0 + ar + 64) * KK + kk + ac];
            bv  = *(const float4*)&Bsrc[(kk + br) * DD + n0 + bc];
        }

#pragma unroll
        for (int ks = 0; ks < 2; ks++) {
            int k = ks * 16;
            uint32_t a[2][4];
#pragma unroll
            for (int mt = 0; mt < 2; mt++) {
                uint32_t ad = smaddr(&As[wm + mt * 16 + (lane & 15)][k + ((lane >> 4) << 3)]);
                ldsm_x4(a[mt][0], a[mt][1], a[mt][2], a[mt][3], ad);
            }
            uint32_t b[2][4];
#pragma unroll
            for (int nb = 0; nb < 2; nb++) {
                uint32_t bd = smaddr(&Bs[k + (lane & 15)][wn + nb * 16 + ((lane >> 4) << 3)]);
                ldsm_x4_t(b[nb][0], b[nb][1], b[nb][2], b[nb][3], bd);
            }
#pragma unroll
            for (int mt = 0; mt < 2; mt++)
#pragma unroll
                for (int nt = 0; nt < 4; nt++) {
                    int nb = nt >> 1, pr = nt & 1;
                    mma_bf16(acc[mt][nt], a[mt], b[nb][pr * 2], b[nb][pr * 2 + 1]);
                }
        }
        __syncthreads();
    }

    int gr = lane >> 2, tc = (lane & 3) * 2;
#pragma unroll
    for (int mt = 0; mt < 2; mt++)
#pragma unroll
        for (int nt = 0; nt < 4; nt++) {
            int row = r0 + wm + mt * 16 + gr;
            int col = n0 + wn + nt * 8 + tc;
            float bb0 = b_o[col], bb1 = b_o[col + 1];
            out[row * DD + col]           = acc[mt][nt][0] + bb0;
            out[row * DD + col + 1]       = acc[mt][nt][1] + bb1;
            out[(row + 8) * DD + col]     = acc[mt][nt][2] + bb0;
            out[(row + 8) * DD + col + 1] = acc[mt][nt][3] + bb1;
        }
}

// ---------------------------------------------------------------------------
extern "C" void kernel_launch(void* const* d_in, const int* in_sizes, int n_in,
                              void* d_out, int out_size)
{
    const float* x      = (const float*)d_in[0];
    const float* W_pre  = (const float*)d_in[1];
    const float* b_pre  = (const float*)d_in[2];
    const float* Q_filt = (const float*)d_in[3];
    const float* K_filt = (const float*)d_in[4];
    const float* W_v    = (const float*)d_in[5];
    const float* b_v    = (const float*)d_in[6];
    const float* W_o    = (const float*)d_in[7];
    const float* b_o    = (const float*)d_in[8];
    const float* decay  = (const float*)d_in[9];
    float* out = (float*)d_out;

    prep_fused<<<NB_WF + NB_BIAS + NB_WO + NB_SX, 256>>>(
        x, W_pre, b_pre, Q_filt, K_filt, b_v, W_o);
    wqkv_finalize<<<(DD * NQ + 255) / 256, 256>>>(W_v);
    qkv_mma<<<dim3(64, 3), 256>>>();
    chunk_sum<<<64, 256>>>(decay);
    chunk_prefix<<<64, 256>>>();
    attn_kernel<<<64, 256>>>(decay);
    out_mma<<<dim3(64, 16), 256>>>(b_o, out);
}

// round 11
// speedup vs baseline: 1.6169x; 1.0505x over previous
#include <cuda_runtime.h>
#include <cuda_bf16.h>
#include <cstdint>

// Problem constants
#define BB 4
#define TT 2048
#define DD 1024
#define KK 64
#define RR (BB*TT)        // 8192 rows
#define NQ 192            // Q|K|V packed cols
#define CH 128            // chunk length
#define NC (TT/CH)        // 16 chunks per batch
#define NSC 32            // sub-chunks per batch (64 steps each)

// Scratch (device globals — no allocation allowed)
__device__ float g_Wpart[8 * DD * 128];          // split-K partials for W_pre@[Qf|Kf]
__device__ float g_bqkv[NQ];
__device__ float g_QKV[RR * NQ];                 // [row, 192]
__device__ float g_S[BB * NSC * KK * KK];        // per-SUB-chunk state sums
__device__ float g_H[BB * NC * KK * KK];         // exclusive prefix states (per chunk)
// bf16 split operands
__device__ __nv_bfloat16 g_xhi[RR * DD];
__device__ __nv_bfloat16 g_xlo[RR * DD];
__device__ __nv_bfloat16 g_Whi[DD * NQ];
__device__ __nv_bfloat16 g_Wlo[DD * NQ];
__device__ __nv_bfloat16 g_Yhi[RR * KK];
__device__ __nv_bfloat16 g_Ylo[RR * KK];
__device__ __nv_bfloat16 g_Wohi[KK * DD];
__device__ __nv_bfloat16 g_Wolo[KK * DD];

// ---------------------------------------------------------------------------
// helpers
// ---------------------------------------------------------------------------
__device__ __forceinline__ uint32_t smaddr(const void* p) {
    return (uint32_t)__cvta_generic_to_shared(p);
}
__device__ __forceinline__ void ldsm_x4(uint32_t& r0, uint32_t& r1,
                                        uint32_t& r2, uint32_t& r3, uint32_t a) {
    asm volatile("ldmatrix.sync.aligned.m8n8.x4.shared.b16 {%0,%1,%2,%3}, [%4];"
                 : "=r"(r0), "=r"(r1), "=r"(r2), "=r"(r3) : "r"(a));
}
__device__ __forceinline__ void ldsm_x4_t(uint32_t& r0, uint32_t& r1,
                                          uint32_t& r2, uint32_t& r3, uint32_t a) {
    asm volatile("ldmatrix.sync.aligned.m8n8.x4.trans.shared.b16 {%0,%1,%2,%3}, [%4];"
                 : "=r"(r0), "=r"(r1), "=r"(r2), "=r"(r3) : "r"(a));
}
__device__ __forceinline__ void mma_bf16(float* c, const uint32_t* a,
                                         uint32_t b0, uint32_t b1) {
    asm volatile(
        "mma.sync.aligned.m16n8k16.row.col.f32.bf16.bf16.f32 "
        "{%0,%1,%2,%3}, {%4,%5,%6,%7}, {%8,%9}, {%0,%1,%2,%3};"
        : "+f"(c[0]), "+f"(c[1]), "+f"(c[2]), "+f"(c[3])
        : "r"(a[0]), "r"(a[1]), "r"(a[2]), "r"(a[3]), "r"(b0), "r"(b1));
}

// ---------------------------------------------------------------------------
// Fused preprocessing kernel: all consumers of raw inputs, run concurrently.
// ---------------------------------------------------------------------------
#define NB_WF   128
#define NB_BIAS 192
#define NB_WO   64
#define NB_SX   8192
__global__ __launch_bounds__(256) void prep_fused(
    const float* __restrict__ x,
    const float* __restrict__ W_pre,
    const float* __restrict__ b_pre,
    const float* __restrict__ Q_filt,
    const float* __restrict__ K_filt,
    const float* __restrict__ b_v,
    const float* __restrict__ W_o)
{
    __shared__ float sbuf[64 * 33 + 32 * 128];   // 24.8 KB, role-dependent
    int bid = blockIdx.x;
    int tid = threadIdx.x;

    if (bid < NB_WF) {
        // ---------------- wfilt_partial ----------------
        float (*Wp)[33]  = (float(*)[33])sbuf;
        float (*Fs)[128] = (float(*)[128])(sbuf + 64 * 33);
        int d0 = (bid & 15) * 64;
        int split = bid >> 4;
        int ty = tid >> 4, tx = tid & 15;
        float acc[4][8];
#pragma unroll
        for (int i = 0; i < 4; i++)
#pragma unroll
            for (int j = 0; j < 8; j++) acc[i][j] = 0.f;

        int t0 = split * 256;
        for (int kt = t0; kt < t0 + 256; kt += 32) {
            for (int i = tid; i < 64 * 32; i += 256) {
                int r = i >> 5, c = i & 31;
                Wp[r][c] = W_pre[(d0 + r) * TT + kt + c];
            }
            for (int i = tid; i < 32 * 128; i += 256) {
                int r = i >> 7, c = i & 127;
                Fs[r][c] = (c < 64) ? Q_filt[(kt + r) * KK + c]
                                    : K_filt[(kt + r) * KK + (c - 64)];
            }
            __syncthreads();
#pragma unroll
            for (int kk = 0; kk < 32; kk++) {
                float a[4];
#pragma unroll
                for (int i = 0; i < 4; i++) a[i] = Wp[ty * 4 + i][kk];
                const float4* F4 = (const float4*)&Fs[kk][0];
                float4 b0 = F4[tx * 2 + 0];
                float4 b1 = F4[tx * 2 + 1];
                float bb[8] = {b0.x, b0.y, b0.z, b0.w, b1.x, b1.y, b1.z, b1.w};
#pragma unroll
                for (int i = 0; i < 4; i++)
#pragma unroll
                    for (int j = 0; j < 8; j++) acc[i][j] += a[i] * bb[j];
            }
            __syncthreads();
        }
#pragma unroll
        for (int i = 0; i < 4; i++)
#pragma unroll
            for (int j = 0; j < 8; j++)
                g_Wpart[(split * DD + d0 + ty * 4 + i) * 128 + tx * 8 + j] = acc[i][j];
    } else if (bid < NB_WF + NB_BIAS) {
        // ---------------- bias columns ----------------
        int j = bid - NB_WF;            // 0..191
        if (j >= 128) {
            if (tid == 0) g_bqkv[j] = b_v[j - 128];
            return;
        }
        const float* F = (j < 64) ? Q_filt : K_filt;
        int col = j & 63;
        float s = 0.f;
        for (int t = tid; t < TT; t += 256)
            s += b_pre[t] * F[t * KK + col];
#pragma unroll
        for (int o = 16; o > 0; o >>= 1)
            s += __shfl_xor_sync(0xffffffff, s, o);
        float* red = sbuf;
        if ((tid & 31) == 0) red[tid >> 5] = s;
        __syncthreads();
        if (tid == 0) {
            float tot = 0.f;
#pragma unroll
            for (int w = 0; w < 8; w++) tot += red[w];
            g_bqkv[j] = tot;
        }
    } else if (bid < NB_WF + NB_BIAS + NB_WO) {
        // ---------------- wo_split ----------------
        int i = (bid - NB_WF - NB_BIAS) * 256 + tid;
        float4 v = ((const float4*)W_o)[i];
        __nv_bfloat16 h[4], l[4];
        float f[4] = {v.x, v.y, v.z, v.w};
#pragma unroll
        for (int j = 0; j < 4; j++) {
            h[j] = __float2bfloat16_rn(f[j]);
            l[j] = __float2bfloat16_rn(f[j] - __bfloat162float(h[j]));
        }
        *(uint2*)&g_Wohi[i * 4] = *(uint2*)h;
        *(uint2*)&g_Wolo[i * 4] = *(uint2*)l;
    } else {
        // ---------------- split_x ----------------
        int i = (bid - NB_WF - NB_BIAS - NB_WO) * 256 + tid;
        float4 v = ((const float4*)x)[i];
        __nv_bfloat16 h[4], l[4];
        float f[4] = {v.x, v.y, v.z, v.w};
#pragma unroll
        for (int j = 0; j < 4; j++) {
            h[j] = __float2bfloat16_rn(f[j]);
            l[j] = __float2bfloat16_rn(f[j] - __bfloat162float(h[j]));
        }
        *(uint2*)&g_xhi[i * 4] = *(uint2*)h;
        *(uint2*)&g_xlo[i * 4] = *(uint2*)l;
    }
}

// ---------------------------------------------------------------------------
// Kernel A2: reduce split-K partials + W_v, write bf16 hi/lo directly
// ---------------------------------------------------------------------------
__global__ void wqkv_finalize(const float* __restrict__ W_v)
{
    int idx = blockIdx.x * blockDim.x + threadIdx.x;
    if (idx >= DD * NQ) return;
    int d = idx / NQ, j = idx % NQ;
    float s;
    if (j < 128) {
        s = 0.f;
#pragma unroll
        for (int p = 0; p < 8; p++) s += g_Wpart[(p * DD + d) * 128 + j];
    } else {
        s = W_v[d * KK + (j - 128)];
    }
    __nv_bfloat16 h = __float2bfloat16_rn(s);
    g_Whi[idx] = h;
    g_Wlo[idx] = __float2bfloat16_rn(s - __bfloat162float(h));
}

// ---------------------------------------------------------------------------
// Kernel B: QKV GEMM on tensor cores, bf16 split (3 phases packed as K=3072)
// k-step 64, double-buffered smem, one sync per iter, 48 iters.
// Grid 192 linearized bid = row*3 + n (co-resident blocks share A rows).
// Block tile 128x64, 8 warps (4m x 2n), warp tile 32x32.
// ---------------------------------------------------------------------------
#define QAP 72
__global__ __launch_bounds__(256, 2) void qkv_mma()
{
    __shared__ __nv_bfloat16 As[2][128][QAP];   // 36.9 KB
    __shared__ __nv_bfloat16 Bs[2][64][QAP];    // 18.4 KB
    int bid = blockIdx.x;
    int r0 = (bid / 3) * 128;
    int n0 = (bid % 3) * 64;
    int tid = threadIdx.x;
    int lane = tid & 31, w = tid >> 5;
    int wm = (w & 3) * 32, wn = (w >> 2) * 32;

    float acc[2][4][4];
#pragma unroll
    for (int mt = 0; mt < 2; mt++)
#pragma unroll
        for (int nt = 0; nt < 4; nt++)
#pragma unroll
            for (int r = 0; r < 4; r++) acc[mt][nt][r] = 0.f;

    int ar = tid >> 3, ac = (tid & 7) * 8;   // A rows ar+{0,32,64,96}, 8 bf16 each
    int br = tid >> 3, bc = (tid & 7) * 8;   // B rows br, br+32

    float4 av[4], bv[2];
    // iter 0 (phase 0: xhi, Whi, kk=0) -> regs -> smem buf 0
#pragma unroll
    for (int r = 0; r < 4; r++)
        av[r] = *(const float4*)&g_xhi[(r0 + ar + r * 32) * DD + ac];
    bv[0] = *(const float4*)&g_Whi[br * NQ + n0 + bc];
    bv[1] = *(const float4*)&g_Whi[(br + 32) * NQ + n0 + bc];
#pragma unroll
    for (int r = 0; r < 4; r++)
        *(float4*)&As[0][ar + r * 32][ac] = av[r];
    *(float4*)&Bs[0][br][bc]      = bv[0];
    *(float4*)&Bs[0][br + 32][bc] = bv[1];
    __syncthreads();

    for (int it = 0; it < 48; it++) {
        int buf = it & 1;
        bool more = (it + 1 < 48);
        if (more) {
            int kt = (it + 1) * 64;
            int phase = kt >> 10;
            int kk = kt & 1023;
            const __nv_bfloat16* Asrc = (phase == 1) ? g_xlo : g_xhi;
            const __nv_bfloat16* Bsrc = (phase == 2) ? g_Wlo : g_Whi;
#pragma unroll
            for (int r = 0; r < 4; r++)
                av[r] = *(const float4*)&Asrc[(r0 + ar + r * 32) * DD + kk + ac];
            bv[0] = *(const float4*)&Bsrc[(kk + br) * NQ + n0 + bc];
            bv[1] = *(const float4*)&Bsrc[(kk + br + 32) * NQ + n0 + bc];
        }

#pragma unroll
        for (int ks = 0; ks < 4; ks++) {
            int k = ks * 16;
            uint32_t a[2][4];
#pragma unroll
            for (int mt = 0; mt < 2; mt++) {
                uint32_t ad = smaddr(&As[buf][wm + mt * 16 + (lane & 15)][k + ((lane >> 4) << 3)]);
                ldsm_x4(a[mt][0], a[mt][1], a[mt][2], a[mt][3], ad);
            }
            uint32_t b[2][4];
#pragma unroll
            for (int nb = 0; nb < 2; nb++) {
                uint32_t bd = smaddr(&Bs[buf][k + (lane & 15)][wn + nb * 16 + ((lane >> 4) << 3)]);
                ldsm_x4_t(b[nb][0], b[nb][1], b[nb][2], b[nb][3], bd);
            }
#pragma unroll
            for (int mt = 0; mt < 2; mt++)
#pragma unroll
                for (int nt = 0; nt < 4; nt++) {
                    int nb = nt >> 1, pr = nt & 1;
                    mma_bf16(acc[mt][nt], a[mt], b[nb][pr * 2], b[nb][pr * 2 + 1]);
                }
        }

        if (more) {
#pragma unroll
            for (int r = 0; r < 4; r++)
                *(float4*)&As[buf ^ 1][ar + r * 32][ac] = av[r];
            *(float4*)&Bs[buf ^ 1][br][bc]      = bv[0];
            *(float4*)&Bs[buf ^ 1][br + 32][bc] = bv[1];
            __syncthreads();
        }
    }

    // epilogue: add bias, write fp32 QKV
    int gr = lane >> 2, tc = (lane & 3) * 2;
#pragma unroll
    for (int mt = 0; mt < 2; mt++)
#pragma unroll
        for (int nt = 0; nt < 4; nt++) {
            int row = r0 + wm + mt * 16 + gr;
            int col = n0 + wn + nt * 8 + tc;
            float bb0 = g_bqkv[col], bb1 = g_bqkv[col + 1];
            g_QKV[row * NQ + col]           = acc[mt][nt][0] + bb0;
            g_QKV[row * NQ + col + 1]       = acc[mt][nt][1] + bb1;
            g_QKV[(row + 8) * NQ + col]     = acc[mt][nt][2] + bb0;
            g_QKV[(row + 8) * NQ + col + 1] = acc[mt][nt][3] + bb1;
        }
}

// ---------------------------------------------------------------------------
// Kernel C1: per-SUB-chunk state sums (64 steps each), grid 128
// ---------------------------------------------------------------------------
__global__ __launch_bounds__(256) void chunk_sum(const float* __restrict__ decay)
{
    __shared__ float Vs[64][65];
    __shared__ float Ks[64][65];
    int b = blockIdx.x >> 5, sc = blockIdx.x & 31;
    int base = b * TT + sc * 64;
    int tid = threadIdx.x;
    int ty = tid >> 4, tx = tid & 15;
    float acc[4][4];
#pragma unroll
    for (int i = 0; i < 4; i++)
#pragma unroll
        for (int j = 0; j < 4; j++) acc[i][j] = 0.f;

    for (int i = tid; i < 64 * 64; i += 256) {
        int r = i >> 6, k = i & 63;
        int row = base + r;
        float d = decay[sc * 64 + r];
        Vs[r][k] = g_QKV[row * NQ + 128 + k];
        Ks[r][k] = g_QKV[row * NQ + 64 + k] * d;
    }
    __syncthreads();
#pragma unroll 8
    for (int s = 0; s < 64; s++) {
        float a[4], bb[4];
#pragma unroll
        for (int i = 0; i < 4; i++) a[i] = Vs[s][ty * 4 + i];
#pragma unroll
        for (int j = 0; j < 4; j++) bb[j] = Ks[s][tx * 4 + j];
#pragma unroll
        for (int i = 0; i < 4; i++)
#pragma unroll
            for (int j = 0; j < 4; j++) acc[i][j] += a[i] * bb[j];
    }
    int sb = (b * NSC + sc) * KK * KK;
#pragma unroll
    for (int i = 0; i < 4; i++)
#pragma unroll
        for (int j = 0; j < 4; j++)
            g_S[sb + (ty * 4 + i) * KK + tx * 4 + j] = acc[i][j];
}

// ---------------------------------------------------------------------------
// Kernel C2: exclusive prefix over chunks (sums sub-chunk pairs), 64 blocks
// ---------------------------------------------------------------------------
__global__ __launch_bounds__(256) void chunk_prefix()
{
    int b = blockIdx.x >> 4;
    int e = (blockIdx.x & 15) * 256 + threadIdx.x;   // 0..4095
    float acc = 0.f;
    int sbase = b * NSC * KK * KK;
    int hbase = b * NC * KK * KK;
    for (int c = 0; c < NC; c++) {
        g_H[hbase + c * KK * KK + e] = acc;
        acc += g_S[sbase + (2 * c) * KK * KK + e]
             + g_S[sbase + (2 * c + 1) * KK * KK + e];
    }
}

// ---------------------------------------------------------------------------
// Kernel C3: Y_chunk = Q @ H_prev + causal intra-chunk; emits Y as bf16 hi/lo
// ---------------------------------------------------------------------------
__global__ __launch_bounds__(256) void attn_kernel(const float* __restrict__ decay)
{
    __shared__ float Qt[KK][CH];
    __shared__ float Reg[4096];
    int b = blockIdx.x >> 4, c = blockIdx.x & 15;
    int base = b * TT + c * CH;
    int tid = threadIdx.x;
    int row = tid >> 1;
    int half = tid & 1;

    for (int i = tid; i < KK * CH; i += 256) {
        int r = i & (CH - 1), k = i >> 7;
        Qt[k][r] = g_QKV[(base + r) * NQ + k];
    }
    int hb = (b * NC + c) * KK * KK;
    for (int i = tid; i < KK * KK; i += 256) Reg[i] = g_H[hb + i];
    __syncthreads();

    float q[KK];
#pragma unroll
    for (int k = 0; k < KK; k++) q[k] = Qt[k][row];

    float y[32];
#pragma unroll
    for (int j = 0; j < 32; j++) y[j] = 0.f;

    {
        const float4* H4 = (const float4*)Reg;
#pragma unroll
        for (int k = 0; k < KK; k++) {
            float qk = q[k];
#pragma unroll
            for (int jj = 0; jj < 8; jj++) {
                float4 h = H4[k * 16 + half * 8 + jj];
                y[jj * 4 + 0] += qk * h.x;
                y[jj * 4 + 1] += qk * h.y;
                y[jj * 4 + 2] += qk * h.z;
                y[jj * 4 + 3] += qk * h.w;
            }
        }
    }
    __syncthreads();

    for (int st = 0; st < CH; st += 32) {
        for (int i = tid; i < 2048; i += 256) {
            int s = i >> 6, k = i & 63;
            int grow = (base + st + s) * NQ;
            Reg[i]        = g_QKV[grow + 128 + k];
            Reg[2048 + i] = g_QKV[grow + 64 + k] * decay[c * CH + st + s];
        }
        __syncthreads();
        if (row >= st) {
            int sm = row - st + 1;
            if (sm > 32) sm = 32;
            const float4* V4 = (const float4*)Reg;
            const float4* F4 = (const float4*)(Reg + 2048);
            for (int s = 0; s < sm; s++) {
                float sc = 0.f;
#pragma unroll
                for (int kk = 0; kk < 16; kk++) {
                    float4 v = V4[s * 16 + kk];
                    sc += q[kk * 4 + 0] * v.x + q[kk * 4 + 1] * v.y
                        + q[kk * 4 + 2] * v.z + q[kk * 4 + 3] * v.w;
                }
#pragma unroll
                for (int jj = 0; jj < 8; jj++) {
                    float4 f = F4[s * 16 + half * 8 + jj];
                    y[jj * 4 + 0] += sc * f.x;
                    y[jj * 4 + 1] += sc * f.y;
                    y[jj * 4 + 2] += sc * f.z;
                    y[jj * 4 + 3] += sc * f.w;
                }
            }
        }
        __syncthreads();
    }

    // epilogue: split to bf16 hi/lo, 8-byte packed stores
    int ybase = (base + row) * KK + half * 32;
#pragma unroll
    for (int jj = 0; jj < 8; jj++) {
        __nv_bfloat16 hp[4], lp[4];
#pragma unroll
        for (int e = 0; e < 4; e++) {
            float f = y[jj * 4 + e];
            hp[e] = __float2bfloat16_rn(f);
            lp[e] = __float2bfloat16_rn(f - __bfloat162float(hp[e]));
        }
        *(uint2*)&g_Yhi[ybase + jj * 4] = *(uint2*)hp;
        *(uint2*)&g_Ylo[ybase + jj * 4] = *(uint2*)lp;
    }
}

// ---------------------------------------------------------------------------
// Kernel D: out = Y @ W_o + b_o  on tensor cores (3-term split, K packed=192)
// ---------------------------------------------------------------------------
#define APITCH 40
#define BPITCH 72
__global__ __launch_bounds__(256, 2) void out_mma(const float* __restrict__ b_o,
                                                  float* __restrict__ out)
{
    __shared__ __nv_bfloat16 As[128][APITCH];
    __shared__ __nv_bfloat16 Bs[32][BPITCH];
    int r0 = blockIdx.x * 128;
    int n0 = blockIdx.y * 64;
    int tid = threadIdx.x;
    int lane = tid & 31, w = tid >> 5;
    int wm = (w & 3) * 32, wn = (w >> 2) * 32;

    float acc[2][4][4];
#pragma unroll
    for (int mt = 0; mt < 2; mt++)
#pragma unroll
        for (int nt = 0; nt < 4; nt++)
#pragma unroll
            for (int r = 0; r < 4; r++) acc[mt][nt][r] = 0.f;

    int ar = tid >> 2, ac = (tid & 3) * 8;
    int br = tid >> 3, bc = (tid & 7) * 8;

    float4 a0v, a1v, bv;
    {   // prefetch iter 0: phase 0 (Yhi, Wohi), kk = 0
        a0v = *(const float4*)&g_Yhi[(r0 + ar) * KK + ac];
        a1v = *(const float4*)&g_Yhi[(r0 + ar + 64) * KK + ac];
        bv  = *(const float4*)&g_Wohi[br * DD + n0 + bc];
    }

    for (int it = 0; it < 6; it++) {
        *(float4*)&As[ar][ac]      = a0v;
        *(float4*)&As[ar + 64][ac] = a1v;
        *(float4*)&Bs[br][bc]      = bv;
        __syncthreads();

        if (it + 1 < 6) {
            int nit = it + 1;
            int phase = nit >> 1;
            int kk = (nit & 1) * 32;
            const __nv_bfloat16* Asrc = (phase == 1) ? g_Ylo : g_Yhi;
            const __nv_bfloat16* Bsrc = (phase == 2) ? g_Wolo : g_Wohi;
            a0v = *(const float4*)&Asrc[(r0 + ar) * KK + kk + ac];
            a1v = *(const float4*)&Asrc[(r0 + ar + 64) * KK + kk + ac];
            bv  = *(const float4*)&Bsrc[(kk + br) * DD + n0 + bc];
        }

#pragma unroll
        for (int ks = 0; ks < 2; ks++) {
            int k = ks * 16;
            uint32_t a[2][4];
#pragma unroll
            for (int mt = 0; mt < 2; mt++) {
                uint32_t ad = smaddr(&As[wm + mt * 16 + (lane & 15)][k + ((lane >> 4) << 3)]);
                ldsm_x4(a[mt][0], a[mt][1], a[mt][2], a[mt][3], ad);
            }
            uint32_t b[2][4];
#pragma unroll
            for (int nb = 0; nb < 2; nb++) {
                uint32_t bd = smaddr(&Bs[k + (lane & 15)][wn + nb * 16 + ((lane >> 4) << 3)]);
                ldsm_x4_t(b[nb][0], b[nb][1], b[nb][2], b[nb][3], bd);
            }
#pragma unroll
            for (int mt = 0; mt < 2; mt++)
#pragma unroll
                for (int nt = 0; nt < 4; nt++) {
                    int nb = nt >> 1, pr = nt & 1;
                    mma_bf16(acc[mt][nt], a[mt], b[nb][pr * 2], b[nb][pr * 2 + 1]);
                }
        }
        __syncthreads();
    }

    int gr = lane >> 2, tc = (lane & 3) * 2;
#pragma unroll
    for (int mt = 0; mt < 2; mt++)
#pragma unroll
        for (int nt = 0; nt < 4; nt++) {
            int row = r0 + wm + mt * 16 + gr;
            int col = n0 + wn + nt * 8 + tc;
            float bb0 = b_o[col], bb1 = b_o[col + 1];
            out[row * DD + col]           = acc[mt][nt][0] + bb0;
            out[row * DD + col + 1]       = acc[mt][nt][1] + bb1;
            out[(row + 8) * DD + col]     = acc[mt][nt][2] + bb0;
            out[(row + 8) * DD + col + 1] = acc[mt][nt][3] + bb1;
        }
}

// ---------------------------------------------------------------------------
extern "C" void kernel_launch(void* const* d_in, const int* in_sizes, int n_in,
                              void* d_out, int out_size)
{
    const float* x      = (const float*)d_in[0];
    const float* W_pre  = (const float*)d_in[1];
    const float* b_pre  = (const float*)d_in[2];
    const float* Q_filt = (const float*)d_in[3];
    const float* K_filt = (const float*)d_in[4];
    const float* W_v    = (const float*)d_in[5];
    const float* b_v    = (const float*)d_in[6];
    const float* W_o    = (const float*)d_in[7];
    const float* b_o    = (const float*)d_in[8];
    const float* decay  = (const float*)d_in[9];
    float* out = (float*)d_out;

    prep_fused<<<NB_WF + NB_BIAS + NB_WO + NB_SX, 256>>>(
        x, W_pre, b_pre, Q_filt, K_filt, b_v, W_o);
    wqkv_finalize<<<(DD * NQ + 255) / 256, 256>>>(W_v);
    qkv_mma<<<192, 256>>>();
    chunk_sum<<<128, 256>>>(decay);
    chunk_prefix<<<64, 256>>>();
    attn_kernel<<<64, 256>>>(decay);
    out_mma<<<dim3(64, 16), 256>>>(b_o, out);
}

// round 12
// speedup vs baseline: 1.7149x; 1.0606x over previous
#include <cuda_runtime.h>
#include <cuda_bf16.h>
#include <cstdint>

// Problem constants
#define BB 4
#define TT 2048
#define DD 1024
#define KK 64
#define RR (BB*TT)        // 8192 rows
#define NQ 192            // Q|K|V packed cols
#define NSC 64            // sub-chunks per batch for S (32 steps each)
#define NH 32             // H states per batch (64-row half-chunks)

// Scratch (device globals — no allocation allowed)
__device__ float g_Wpart[8 * DD * 128];          // split-K partials for W_pre@[Qf|Kf]
__device__ float g_bqkv[NQ];
__device__ float g_QKV[RR * NQ];                 // [row, 192]
__device__ float g_S[BB * NSC * KK * KK];        // per-32-step-sub-chunk sums (4MB)
__device__ float g_H[BB * NH * KK * KK];         // exclusive prefix states (2MB)
// bf16 split operands
__device__ __nv_bfloat16 g_xhi[RR * DD];
__device__ __nv_bfloat16 g_xlo[RR * DD];
__device__ __nv_bfloat16 g_Whi[DD * NQ];
__device__ __nv_bfloat16 g_Wlo[DD * NQ];
__device__ __nv_bfloat16 g_Yhi[RR * KK];
__device__ __nv_bfloat16 g_Ylo[RR * KK];
__device__ __nv_bfloat16 g_Wohi[KK * DD];
__device__ __nv_bfloat16 g_Wolo[KK * DD];

// ---------------------------------------------------------------------------
// helpers
// ---------------------------------------------------------------------------
__device__ __forceinline__ uint32_t smaddr(const void* p) {
    return (uint32_t)__cvta_generic_to_shared(p);
}
__device__ __forceinline__ void ldsm_x4(uint32_t& r0, uint32_t& r1,
                                        uint32_t& r2, uint32_t& r3, uint32_t a) {
    asm volatile("ldmatrix.sync.aligned.m8n8.x4.shared.b16 {%0,%1,%2,%3}, [%4];"
                 : "=r"(r0), "=r"(r1), "=r"(r2), "=r"(r3) : "r"(a));
}
__device__ __forceinline__ void ldsm_x4_t(uint32_t& r0, uint32_t& r1,
                                          uint32_t& r2, uint32_t& r3, uint32_t a) {
    asm volatile("ldmatrix.sync.aligned.m8n8.x4.trans.shared.b16 {%0,%1,%2,%3}, [%4];"
                 : "=r"(r0), "=r"(r1), "=r"(r2), "=r"(r3) : "r"(a));
}
__device__ __forceinline__ void mma_bf16(float* c, const uint32_t* a,
                                         uint32_t b0, uint32_t b1) {
    asm volatile(
        "mma.sync.aligned.m16n8k16.row.col.f32.bf16.bf16.f32 "
        "{%0,%1,%2,%3}, {%4,%5,%6,%7}, {%8,%9}, {%0,%1,%2,%3};"
        : "+f"(c[0]), "+f"(c[1]), "+f"(c[2]), "+f"(c[3])
        : "r"(a[0]), "r"(a[1]), "r"(a[2]), "r"(a[3]), "r"(b0), "r"(b1));
}

// ---------------------------------------------------------------------------
// Fused preprocessing kernel: all consumers of raw inputs, run concurrently.
// ---------------------------------------------------------------------------
#define NB_WF   128
#define NB_BIAS 192
#define NB_WO   64
#define NB_SX   8192
__global__ __launch_bounds__(256) void prep_fused(
    const float* __restrict__ x,
    const float* __restrict__ W_pre,
    const float* __restrict__ b_pre,
    const float* __restrict__ Q_filt,
    const float* __restrict__ K_filt,
    const float* __restrict__ b_v,
    const float* __restrict__ W_o)
{
    __shared__ float sbuf[64 * 33 + 32 * 128];   // 24.8 KB, role-dependent
    int bid = blockIdx.x;
    int tid = threadIdx.x;

    if (bid < NB_WF) {
        // ---------------- wfilt_partial ----------------
        float (*Wp)[33]  = (float(*)[33])sbuf;
        float (*Fs)[128] = (float(*)[128])(sbuf + 64 * 33);
        int d0 = (bid & 15) * 64;
        int split = bid >> 4;
        int ty = tid >> 4, tx = tid & 15;
        float acc[4][8];
#pragma unroll
        for (int i = 0; i < 4; i++)
#pragma unroll
            for (int j = 0; j < 8; j++) acc[i][j] = 0.f;

        int t0 = split * 256;
        for (int kt = t0; kt < t0 + 256; kt += 32) {
            for (int i = tid; i < 64 * 32; i += 256) {
                int r = i >> 5, c = i & 31;
                Wp[r][c] = W_pre[(d0 + r) * TT + kt + c];
            }
            for (int i = tid; i < 32 * 128; i += 256) {
                int r = i >> 7, c = i & 127;
                Fs[r][c] = (c < 64) ? Q_filt[(kt + r) * KK + c]
                                    : K_filt[(kt + r) * KK + (c - 64)];
            }
            __syncthreads();
#pragma unroll
            for (int kk = 0; kk < 32; kk++) {
                float a[4];
#pragma unroll
                for (int i = 0; i < 4; i++) a[i] = Wp[ty * 4 + i][kk];
                const float4* F4 = (const float4*)&Fs[kk][0];
                float4 b0 = F4[tx * 2 + 0];
                float4 b1 = F4[tx * 2 + 1];
                float bb[8] = {b0.x, b0.y, b0.z, b0.w, b1.x, b1.y, b1.z, b1.w};
#pragma unroll
                for (int i = 0; i < 4; i++)
#pragma unroll
                    for (int j = 0; j < 8; j++) acc[i][j] += a[i] * bb[j];
            }
            __syncthreads();
        }
#pragma unroll
        for (int i = 0; i < 4; i++)
#pragma unroll
            for (int j = 0; j < 8; j++)
                g_Wpart[(split * DD + d0 + ty * 4 + i) * 128 + tx * 8 + j] = acc[i][j];
    } else if (bid < NB_WF + NB_BIAS) {
        // ---------------- bias columns ----------------
        int j = bid - NB_WF;            // 0..191
        if (j >= 128) {
            if (tid == 0) g_bqkv[j] = b_v[j - 128];
            return;
        }
        const float* F = (j < 64) ? Q_filt : K_filt;
        int col = j & 63;
        float s = 0.f;
        for (int t = tid; t < TT; t += 256)
            s += b_pre[t] * F[t * KK + col];
#pragma unroll
        for (int o = 16; o > 0; o >>= 1)
            s += __shfl_xor_sync(0xffffffff, s, o);
        float* red = sbuf;
        if ((tid & 31) == 0) red[tid >> 5] = s;
        __syncthreads();
        if (tid == 0) {
            float tot = 0.f;
#pragma unroll
            for (int w = 0; w < 8; w++) tot += red[w];
            g_bqkv[j] = tot;
        }
    } else if (bid < NB_WF + NB_BIAS + NB_WO) {
        // ---------------- wo_split ----------------
        int i = (bid - NB_WF - NB_BIAS) * 256 + tid;
        float4 v = ((const float4*)W_o)[i];
        __nv_bfloat16 h[4], l[4];
        float f[4] = {v.x, v.y, v.z, v.w};
#pragma unroll
        for (int j = 0; j < 4; j++) {
            h[j] = __float2bfloat16_rn(f[j]);
            l[j] = __float2bfloat16_rn(f[j] - __bfloat162float(h[j]));
        }
        *(uint2*)&g_Wohi[i * 4] = *(uint2*)h;
        *(uint2*)&g_Wolo[i * 4] = *(uint2*)l;
    } else {
        // ---------------- split_x ----------------
        int i = (bid - NB_WF - NB_BIAS - NB_WO) * 256 + tid;
        float4 v = ((const float4*)x)[i];
        __nv_bfloat16 h[4], l[4];
        float f[4] = {v.x, v.y, v.z, v.w};
#pragma unroll
        for (int j = 0; j < 4; j++) {
            h[j] = __float2bfloat16_rn(f[j]);
            l[j] = __float2bfloat16_rn(f[j] - __bfloat162float(h[j]));
        }
        *(uint2*)&g_xhi[i * 4] = *(uint2*)h;
        *(uint2*)&g_xlo[i * 4] = *(uint2*)l;
    }
}

// ---------------------------------------------------------------------------
// Kernel A2: reduce split-K partials + W_v, write bf16 hi/lo directly
// ---------------------------------------------------------------------------
__global__ void wqkv_finalize(const float* __restrict__ W_v)
{
    int idx = blockIdx.x * blockDim.x + threadIdx.x;
    if (idx >= DD * NQ) return;
    int d = idx / NQ, j = idx % NQ;
    float s;
    if (j < 128) {
        s = 0.f;
#pragma unroll
        for (int p = 0; p < 8; p++) s += g_Wpart[(p * DD + d) * 128 + j];
    } else {
        s = W_v[d * KK + (j - 128)];
    }
    __nv_bfloat16 h = __float2bfloat16_rn(s);
    g_Whi[idx] = h;
    g_Wlo[idx] = __float2bfloat16_rn(s - __bfloat162float(h));
}

// ---------------------------------------------------------------------------
// Kernel B: QKV GEMM on tensor cores, bf16 split (3 phases packed as K=3072)
// k-step 64, double-buffered smem, one sync per iter, 48 iters.
// ---------------------------------------------------------------------------
#define QAP 72
__global__ __launch_bounds__(256, 2) void qkv_mma()
{
    __shared__ __nv_bfloat16 As[2][128][QAP];   // 36.9 KB
    __shared__ __nv_bfloat16 Bs[2][64][QAP];    // 18.4 KB
    int bid = blockIdx.x;
    int r0 = (bid / 3) * 128;
    int n0 = (bid % 3) * 64;
    int tid = threadIdx.x;
    int lane = tid & 31, w = tid >> 5;
    int wm = (w & 3) * 32, wn = (w >> 2) * 32;

    float acc[2][4][4];
#pragma unroll
    for (int mt = 0; mt < 2; mt++)
#pragma unroll
        for (int nt = 0; nt < 4; nt++)
#pragma unroll
            for (int r = 0; r < 4; r++) acc[mt][nt][r] = 0.f;

    int ar = tid >> 3, ac = (tid & 7) * 8;   // A rows ar+{0,32,64,96}, 8 bf16 each
    int br = tid >> 3, bc = (tid & 7) * 8;   // B rows br, br+32

    float4 av[4], bv[2];
#pragma unroll
    for (int r = 0; r < 4; r++)
        av[r] = *(const float4*)&g_xhi[(r0 + ar + r * 32) * DD + ac];
    bv[0] = *(const float4*)&g_Whi[br * NQ + n0 + bc];
    bv[1] = *(const float4*)&g_Whi[(br + 32) * NQ + n0 + bc];
#pragma unroll
    for (int r = 0; r < 4; r++)
        *(float4*)&As[0][ar + r * 32][ac] = av[r];
    *(float4*)&Bs[0][br][bc]      = bv[0];
    *(float4*)&Bs[0][br + 32][bc] = bv[1];
    __syncthreads();

    for (int it = 0; it < 48; it++) {
        int buf = it & 1;
        bool more = (it + 1 < 48);
        if (more) {
            int kt = (it + 1) * 64;
            int phase = kt >> 10;
            int kk = kt & 1023;
            const __nv_bfloat16* Asrc = (phase == 1) ? g_xlo : g_xhi;
            const __nv_bfloat16* Bsrc = (phase == 2) ? g_Wlo : g_Whi;
#pragma unroll
            for (int r = 0; r < 4; r++)
                av[r] = *(const float4*)&Asrc[(r0 + ar + r * 32) * DD + kk + ac];
            bv[0] = *(const float4*)&Bsrc[(kk + br) * NQ + n0 + bc];
            bv[1] = *(const float4*)&Bsrc[(kk + br + 32) * NQ + n0 + bc];
        }

#pragma unroll
        for (int ks = 0; ks < 4; ks++) {
            int k = ks * 16;
            uint32_t a[2][4];
#pragma unroll
            for (int mt = 0; mt < 2; mt++) {
                uint32_t ad = smaddr(&As[buf][wm + mt * 16 + (lane & 15)][k + ((lane >> 4) << 3)]);
                ldsm_x4(a[mt][0], a[mt][1], a[mt][2], a[mt][3], ad);
            }
            uint32_t b[2][4];
#pragma unroll
            for (int nb = 0; nb < 2; nb++) {
                uint32_t bd = smaddr(&Bs[buf][k + (lane & 15)][wn + nb * 16 + ((lane >> 4) << 3)]);
                ldsm_x4_t(b[nb][0], b[nb][1], b[nb][2], b[nb][3], bd);
            }
#pragma unroll
            for (int mt = 0; mt < 2; mt++)
#pragma unroll
                for (int nt = 0; nt < 4; nt++) {
                    int nb = nt >> 1, pr = nt & 1;
                    mma_bf16(acc[mt][nt], a[mt], b[nb][pr * 2], b[nb][pr * 2 + 1]);
                }
        }

        if (more) {
#pragma unroll
            for (int r = 0; r < 4; r++)
                *(float4*)&As[buf ^ 1][ar + r * 32][ac] = av[r];
            *(float4*)&Bs[buf ^ 1][br][bc]      = bv[0];
            *(float4*)&Bs[buf ^ 1][br + 32][bc] = bv[1];
            __syncthreads();
        }
    }

    // epilogue: add bias, write fp32 QKV
    int gr = lane >> 2, tc = (lane & 3) * 2;
#pragma unroll
    for (int mt = 0; mt < 2; mt++)
#pragma unroll
        for (int nt = 0; nt < 4; nt++) {
            int row = r0 + wm + mt * 16 + gr;
            int col = n0 + wn + nt * 8 + tc;
            float bb0 = g_bqkv[col], bb1 = g_bqkv[col + 1];
            g_QKV[row * NQ + col]           = acc[mt][nt][0] + bb0;
            g_QKV[row * NQ + col + 1]       = acc[mt][nt][1] + bb1;
            g_QKV[(row + 8) * NQ + col]     = acc[mt][nt][2] + bb0;
            g_QKV[(row + 8) * NQ + col + 1] = acc[mt][nt][3] + bb1;
        }
}

// ---------------------------------------------------------------------------
// Kernel C1: per-sub-chunk state sums (32 steps each), grid 256
// ---------------------------------------------------------------------------
__global__ __launch_bounds__(256) void chunk_sum(const float* __restrict__ decay)
{
    __shared__ float Vs[32][65];
    __shared__ float Ks[32][65];
    int b = blockIdx.x >> 6, sc = blockIdx.x & 63;
    int base = b * TT + sc * 32;
    int tid = threadIdx.x;
    int ty = tid >> 4, tx = tid & 15;
    float acc[4][4];
#pragma unroll
    for (int i = 0; i < 4; i++)
#pragma unroll
        for (int j = 0; j < 4; j++) acc[i][j] = 0.f;

    for (int i = tid; i < 32 * 64; i += 256) {
        int r = i >> 6, k = i & 63;
        int row = base + r;
        float d = decay[sc * 32 + r];
        Vs[r][k] = g_QKV[row * NQ + 128 + k];
        Ks[r][k] = g_QKV[row * NQ + 64 + k] * d;
    }
    __syncthreads();
#pragma unroll 8
    for (int s = 0; s < 32; s++) {
        float a[4], bb[4];
#pragma unroll
        for (int i = 0; i < 4; i++) a[i] = Vs[s][ty * 4 + i];
#pragma unroll
        for (int j = 0; j < 4; j++) bb[j] = Ks[s][tx * 4 + j];
#pragma unroll
        for (int i = 0; i < 4; i++)
#pragma unroll
            for (int j = 0; j < 4; j++) acc[i][j] += a[i] * bb[j];
    }
    int sb = (b * NSC + sc) * KK * KK;
#pragma unroll
    for (int i = 0; i < 4; i++)
#pragma unroll
        for (int j = 0; j < 4; j++)
            g_S[sb + (ty * 4 + i) * KK + tx * 4 + j] = acc[i][j];
}

// ---------------------------------------------------------------------------
// Kernel C2: exclusive prefix over 64-row half-chunks (sums S pairs), 64 blocks
// ---------------------------------------------------------------------------
__global__ __launch_bounds__(256) void chunk_prefix()
{
    int b = blockIdx.x >> 4;
    int e = (blockIdx.x & 15) * 256 + threadIdx.x;   // 0..4095
    float acc = 0.f;
    int sbase = b * NSC * KK * KK;
    int hbase = b * NH * KK * KK;
    for (int c = 0; c < NH; c++) {
        g_H[hbase + c * KK * KK + e] = acc;
        acc += g_S[sbase + (2 * c) * KK * KK + e]
             + g_S[sbase + (2 * c + 1) * KK * KK + e];
    }
}

// ---------------------------------------------------------------------------
// Kernel C3: half-chunk attention (64 rows). grid = BB*NH = 128 blocks.
// threads: row (0..63) x quarter (16 n-cols). Y emitted as bf16 hi/lo.
// ---------------------------------------------------------------------------
__global__ __launch_bounds__(256) void attn_kernel(const float* __restrict__ decay)
{
    __shared__ float Qt[KK][64];       // transposed Q [k][r], 16KB
    __shared__ float Reg[4096];        // union: H[64][64] | V[32][64]+Kd[32][64]
    int b = blockIdx.x >> 5, hc = blockIdx.x & 31;
    int base = b * TT + hc * 64;
    int tid = threadIdx.x;
    int row = tid >> 2;                // 0..63
    int qd = tid & 3;                  // n-quarter: cols qd*16 .. qd*16+15

    for (int i = tid; i < KK * 64; i += 256) {
        int r = i & 63, k = i >> 6;
        Qt[k][r] = g_QKV[(base + r) * NQ + k];
    }
    int hb = (b * NH + hc) * KK * KK;
    for (int i = tid; i < KK * KK; i += 256) Reg[i] = g_H[hb + i];
    __syncthreads();

    float q[KK];
#pragma unroll
    for (int k = 0; k < KK; k++) q[k] = Qt[k][row];

    float y[16];
#pragma unroll
    for (int j = 0; j < 16; j++) y[j] = 0.f;

    // inter: y += q . H[:, quarter]
    {
        const float4* H4 = (const float4*)Reg;
#pragma unroll
        for (int k = 0; k < KK; k++) {
            float qk = q[k];
#pragma unroll
            for (int jj = 0; jj < 4; jj++) {
                float4 h = H4[k * 16 + qd * 4 + jj];
                y[jj * 4 + 0] += qk * h.x;
                y[jj * 4 + 1] += qk * h.y;
                y[jj * 4 + 2] += qk * h.z;
                y[jj * 4 + 3] += qk * h.w;
            }
        }
    }
    __syncthreads();

    // intra-half-chunk causal, 2 s-tiles of 32
    for (int st = 0; st < 64; st += 32) {
        for (int i = tid; i < 2048; i += 256) {
            int s = i >> 6, k = i & 63;
            int grow = (base + st + s) * NQ;
            Reg[i]        = g_QKV[grow + 128 + k];
            Reg[2048 + i] = g_QKV[grow + 64 + k] * decay[hc * 64 + st + s];
        }
        __syncthreads();
        if (row >= st) {
            int sm = row - st + 1;
            if (sm > 32) sm = 32;
            const float4* V4 = (const float4*)Reg;
            const float4* F4 = (const float4*)(Reg + 2048);
            for (int s = 0; s < sm; s++) {
                float sc = 0.f;
#pragma unroll
                for (int kk = 0; kk < 16; kk++) {
                    float4 v = V4[s * 16 + kk];
                    sc += q[kk * 4 + 0] * v.x + q[kk * 4 + 1] * v.y
                        + q[kk * 4 + 2] * v.z + q[kk * 4 + 3] * v.w;
                }
#pragma unroll
                for (int jj = 0; jj < 4; jj++) {
                    float4 f = F4[s * 16 + qd * 4 + jj];
                    y[jj * 4 + 0] += sc * f.x;
                    y[jj * 4 + 1] += sc * f.y;
                    y[jj * 4 + 2] += sc * f.z;
                    y[jj * 4 + 3] += sc * f.w;
                }
            }
        }
        __syncthreads();
    }

    // epilogue: split to bf16 hi/lo, 8-byte packed stores
    int ybase = (base + row) * KK + qd * 16;
#pragma unroll
    for (int jj = 0; jj < 4; jj++) {
        __nv_bfloat16 hp[4], lp[4];
#pragma unroll
        for (int e = 0; e < 4; e++) {
            float f = y[jj * 4 + e];
            hp[e] = __float2bfloat16_rn(f);
            lp[e] = __float2bfloat16_rn(f - __bfloat162float(hp[e]));
        }
        *(uint2*)&g_Yhi[ybase + jj * 4] = *(uint2*)hp;
        *(uint2*)&g_Ylo[ybase + jj * 4] = *(uint2*)lp;
    }
}

// ---------------------------------------------------------------------------
// Kernel D: out = Y @ W_o + b_o  on tensor cores (3-term split, K packed=192)
// ---------------------------------------------------------------------------
#define APITCH 40
#define BPITCH 72
__global__ __launch_bounds__(256, 2) void out_mma(const float* __restrict__ b_o,
                                                  float* __restrict__ out)
{
    __shared__ __nv_bfloat16 As[128][APITCH];
    __shared__ __nv_bfloat16 Bs[32][BPITCH];
    int r0 = blockIdx.x * 128;
    int n0 = blockIdx.y * 64;
    int tid = threadIdx.x;
    int lane = tid & 31, w = tid >> 5;
    int wm = (w & 3) * 32, wn = (w >> 2) * 32;

    float acc[2][4][4];
#pragma unroll
    for (int mt = 0; mt < 2; mt++)
#pragma unroll
        for (int nt = 0; nt < 4; nt++)
#pragma unroll
            for (int r = 0; r < 4; r++) acc[mt][nt][r] = 0.f;

    int ar = tid >> 2, ac = (tid & 3) * 8;
    int br = tid >> 3, bc = (tid & 7) * 8;

    float4 a0v, a1v, bv;
    {   // prefetch iter 0: phase 0 (Yhi, Wohi), kk = 0
        a0v = *(const float4*)&g_Yhi[(r0 + ar) * KK + ac];
        a1v = *(const float4*)&g_Yhi[(r0 + ar + 64) * KK + ac];
        bv  = *(const float4*)&g_Wohi[br * DD + n0 + bc];
    }

    for (int it = 0; it < 6; it++) {
        *(float4*)&As[ar][ac]      = a0v;
        *(float4*)&As[ar + 64][ac] = a1v;
        *(float4*)&Bs[br][bc]      = bv;
        __syncthreads();

        if (it + 1 < 6) {
            int nit = it + 1;
            int phase = nit >> 1;
            int kk = (nit & 1) * 32;
            const __nv_bfloat16* Asrc = (phase == 1) ? g_Ylo : g_Yhi;
            const __nv_bfloat16* Bsrc = (phase == 2) ? g_Wolo : g_Wohi;
            a0v = *(const float4*)&Asrc[(r0 + ar) * KK + kk + ac];
            a1v = *(const float4*)&Asrc[(r0 + ar + 64) * KK + kk + ac];
            bv  = *(const float4*)&Bsrc[(kk + br) * DD + n0 + bc];
        }

#pragma unroll
        for (int ks = 0; ks < 2; ks++) {
            int k = ks * 16;
            uint32_t a[2][4];
#pragma unroll
            for (int mt = 0; mt < 2; mt++) {
                uint32_t ad = smaddr(&As[wm + mt * 16 + (lane & 15)][k + ((lane >> 4) << 3)]);
                ldsm_x4(a[mt][0], a[mt][1], a[mt][2], a[mt][3], ad);
            }
            uint32_t b[2][4];
#pragma unroll
            for (int nb = 0; nb < 2; nb++) {
                uint32_t bd = smaddr(&Bs[k + (lane & 15)][wn + nb * 16 + ((lane >> 4) << 3)]);
                ldsm_x4_t(b[nb][0], b[nb][1], b[nb][2], b[nb][3], bd);
            }
#pragma unroll
            for (int mt = 0; mt < 2; mt++)
#pragma unroll
                for (int nt = 0; nt < 4; nt++) {
                    int nb = nt >> 1, pr = nt & 1;
                    mma_bf16(acc[mt][nt], a[mt], b[nb][pr * 2], b[nb][pr * 2 + 1]);
                }
        }
        __syncthreads();
    }

    int gr = lane >> 2, tc = (lane & 3) * 2;
#pragma unroll
    for (int mt = 0; mt < 2; mt++)
#pragma unroll
        for (int nt = 0; nt < 4; nt++) {
            int row = r0 + wm + mt * 16 + gr;
            int col = n0 + wn + nt * 8 + tc;
            float bb0 = b_o[col], bb1 = b_o[col + 1];
            out[row * DD + col]           = acc[mt][nt][0] + bb0;
            out[row * DD + col + 1]       = acc[mt][nt][1] + bb1;
            out[(row + 8) * DD + col]     = acc[mt][nt][2] + bb0;
            out[(row + 8) * DD + col + 1] = acc[mt][nt][3] + bb1;
        }
}

// ---------------------------------------------------------------------------
extern "C" void kernel_launch(void* const* d_in, const int* in_sizes, int n_in,
                              void* d_out, int out_size)
{
    const float* x      = (const float*)d_in[0];
    const float* W_pre  = (const float*)d_in[1];
    const float* b_pre  = (const float*)d_in[2];
    const float* Q_filt = (const float*)d_in[3];
    const float* K_filt = (const float*)d_in[4];
    const float* W_v    = (const float*)d_in[5];
    const float* b_v    = (const float*)d_in[6];
    const float* W_o    = (const float*)d_in[7];
    const float* b_o    = (const float*)d_in[8];
    const float* decay  = (const float*)d_in[9];
    float* out = (float*)d_out;

    prep_fused<<<NB_WF + NB_BIAS + NB_WO + NB_SX, 256>>>(
        x, W_pre, b_pre, Q_filt, K_filt, b_v, W_o);
    wqkv_finalize<<<(DD * NQ + 255) / 256, 256>>>(W_v);
    qkv_mma<<<192, 256>>>();
    chunk_sum<<<256, 256>>>(decay);
    chunk_prefix<<<64, 256>>>();
    attn_kernel<<<BB * NH, 256>>>(decay);
    out_mma<<<dim3(64, 16), 256>>>(b_o, out);
}

// round 13
// speedup vs baseline: 1.8153x; 1.0585x over previous
#include <cuda_runtime.h>
#include <cuda_bf16.h>
#include <cstdint>

// Problem constants
#define BB 4
#define TT 2048
#define DD 1024
#define KK 64
#define RR (BB*TT)        // 8192 rows
#define NQ 192            // Q|K|V packed cols
#define NSC 64            // sub-chunks per batch for S (32 steps each)
#define NH 32             // H states per batch (64-row half-chunks)

// Scratch (device globals — no allocation allowed)
__device__ float g_Wpart[8 * DD * 128];          // split-K partials for W_pre@[Qf|Kf]
__device__ float g_bqkv[NQ];
__device__ float g_Qp[3][RR * NQ];               // per-phase QKV partials (19MB)
__device__ float g_QKV[RR * NQ];                 // [row, 192]
__device__ float g_S[BB * NSC * KK * KK];        // per-32-step-sub-chunk sums (4MB)
__device__ float g_H[BB * NH * KK * KK];         // exclusive prefix states (2MB)
// bf16 split operands
__device__ __nv_bfloat16 g_xhi[RR * DD];
__device__ __nv_bfloat16 g_xlo[RR * DD];
__device__ __nv_bfloat16 g_Whi[DD * NQ];
__device__ __nv_bfloat16 g_Wlo[DD * NQ];
__device__ __nv_bfloat16 g_Yhi[RR * KK];
__device__ __nv_bfloat16 g_Ylo[RR * KK];
__device__ __nv_bfloat16 g_Wohi[KK * DD];
__device__ __nv_bfloat16 g_Wolo[KK * DD];

// ---------------------------------------------------------------------------
// helpers
// ---------------------------------------------------------------------------
__device__ __forceinline__ uint32_t smaddr(const void* p) {
    return (uint32_t)__cvta_generic_to_shared(p);
}
__device__ __forceinline__ void ldsm_x4(uint32_t& r0, uint32_t& r1,
                                        uint32_t& r2, uint32_t& r3, uint32_t a) {
    asm volatile("ldmatrix.sync.aligned.m8n8.x4.shared.b16 {%0,%1,%2,%3}, [%4];"
                 : "=r"(r0), "=r"(r1), "=r"(r2), "=r"(r3) : "r"(a));
}
__device__ __forceinline__ void ldsm_x4_t(uint32_t& r0, uint32_t& r1,
                                          uint32_t& r2, uint32_t& r3, uint32_t a) {
    asm volatile("ldmatrix.sync.aligned.m8n8.x4.trans.shared.b16 {%0,%1,%2,%3}, [%4];"
                 : "=r"(r0), "=r"(r1), "=r"(r2), "=r"(r3) : "r"(a));
}
__device__ __forceinline__ void mma_bf16(float* c, const uint32_t* a,
                                         uint32_t b0, uint32_t b1) {
    asm volatile(
        "mma.sync.aligned.m16n8k16.row.col.f32.bf16.bf16.f32 "
        "{%0,%1,%2,%3}, {%4,%5,%6,%7}, {%8,%9}, {%0,%1,%2,%3};"
        : "+f"(c[0]), "+f"(c[1]), "+f"(c[2]), "+f"(c[3])
        : "r"(a[0]), "r"(a[1]), "r"(a[2]), "r"(a[3]), "r"(b0), "r"(b1));
}

// ---------------------------------------------------------------------------
// Fused preprocessing kernel: all consumers of raw inputs, run concurrently.
// ---------------------------------------------------------------------------
#define NB_WF   128
#define NB_BIAS 192
#define NB_WO   64
#define NB_SX   8192
__global__ __launch_bounds__(256) void prep_fused(
    const float* __restrict__ x,
    const float* __restrict__ W_pre,
    const float* __restrict__ b_pre,
    const float* __restrict__ Q_filt,
    const float* __restrict__ K_filt,
    const float* __restrict__ b_v,
    const float* __restrict__ W_o)
{
    __shared__ float sbuf[64 * 33 + 32 * 128];   // 24.8 KB, role-dependent
    int bid = blockIdx.x;
    int tid = threadIdx.x;

    if (bid < NB_WF) {
        // ---------------- wfilt_partial ----------------
        float (*Wp)[33]  = (float(*)[33])sbuf;
        float (*Fs)[128] = (float(*)[128])(sbuf + 64 * 33);
        int d0 = (bid & 15) * 64;
        int split = bid >> 4;
        int ty = tid >> 4, tx = tid & 15;
        float acc[4][8];
#pragma unroll
        for (int i = 0; i < 4; i++)
#pragma unroll
            for (int j = 0; j < 8; j++) acc[i][j] = 0.f;

        int t0 = split * 256;
        for (int kt = t0; kt < t0 + 256; kt += 32) {
            for (int i = tid; i < 64 * 32; i += 256) {
                int r = i >> 5, c = i & 31;
                Wp[r][c] = W_pre[(d0 + r) * TT + kt + c];
            }
            for (int i = tid; i < 32 * 128; i += 256) {
                int r = i >> 7, c = i & 127;
                Fs[r][c] = (c < 64) ? Q_filt[(kt + r) * KK + c]
                                    : K_filt[(kt + r) * KK + (c - 64)];
            }
            __syncthreads();
#pragma unroll
            for (int kk = 0; kk < 32; kk++) {
                float a[4];
#pragma unroll
                for (int i = 0; i < 4; i++) a[i] = Wp[ty * 4 + i][kk];
                const float4* F4 = (const float4*)&Fs[kk][0];
                float4 b0 = F4[tx * 2 + 0];
                float4 b1 = F4[tx * 2 + 1];
                float bb[8] = {b0.x, b0.y, b0.z, b0.w, b1.x, b1.y, b1.z, b1.w};
#pragma unroll
                for (int i = 0; i < 4; i++)
#pragma unroll
                    for (int j = 0; j < 8; j++) acc[i][j] += a[i] * bb[j];
            }
            __syncthreads();
        }
#pragma unroll
        for (int i = 0; i < 4; i++)
#pragma unroll
            for (int j = 0; j < 8; j++)
                g_Wpart[(split * DD + d0 + ty * 4 + i) * 128 + tx * 8 + j] = acc[i][j];
    } else if (bid < NB_WF + NB_BIAS) {
        // ---------------- bias columns ----------------
        int j = bid - NB_WF;            // 0..191
        if (j >= 128) {
            if (tid == 0) g_bqkv[j] = b_v[j - 128];
            return;
        }
        const float* F = (j < 64) ? Q_filt : K_filt;
        int col = j & 63;
        float s = 0.f;
        for (int t = tid; t < TT; t += 256)
            s += b_pre[t] * F[t * KK + col];
#pragma unroll
        for (int o = 16; o > 0; o >>= 1)
            s += __shfl_xor_sync(0xffffffff, s, o);
        float* red = sbuf;
        if ((tid & 31) == 0) red[tid >> 5] = s;
        __syncthreads();
        if (tid == 0) {
            float tot = 0.f;
#pragma unroll
            for (int w = 0; w < 8; w++) tot += red[w];
            g_bqkv[j] = tot;
        }
    } else if (bid < NB_WF + NB_BIAS + NB_WO) {
        // ---------------- wo_split ----------------
        int i = (bid - NB_WF - NB_BIAS) * 256 + tid;
        float4 v = ((const float4*)W_o)[i];
        __nv_bfloat16 h[4], l[4];
        float f[4] = {v.x, v.y, v.z, v.w};
#pragma unroll
        for (int j = 0; j < 4; j++) {
            h[j] = __float2bfloat16_rn(f[j]);
            l[j] = __float2bfloat16_rn(f[j] - __bfloat162float(h[j]));
        }
        *(uint2*)&g_Wohi[i * 4] = *(uint2*)h;
        *(uint2*)&g_Wolo[i * 4] = *(uint2*)l;
    } else {
        // ---------------- split_x ----------------
        int i = (bid - NB_WF - NB_BIAS - NB_WO) * 256 + tid;
        float4 v = ((const float4*)x)[i];
        __nv_bfloat16 h[4], l[4];
        float f[4] = {v.x, v.y, v.z, v.w};
#pragma unroll
        for (int j = 0; j < 4; j++) {
            h[j] = __float2bfloat16_rn(f[j]);
            l[j] = __float2bfloat16_rn(f[j] - __bfloat162float(h[j]));
        }
        *(uint2*)&g_xhi[i * 4] = *(uint2*)h;
        *(uint2*)&g_xlo[i * 4] = *(uint2*)l;
    }
}

// ---------------------------------------------------------------------------
// Kernel A2: reduce split-K partials + W_v, write bf16 hi/lo directly
// ---------------------------------------------------------------------------
__global__ void wqkv_finalize(const float* __restrict__ W_v)
{
    int idx = blockIdx.x * blockDim.x + threadIdx.x;
    if (idx >= DD * NQ) return;
    int d = idx / NQ, j = idx % NQ;
    float s;
    if (j < 128) {
        s = 0.f;
#pragma unroll
        for (int p = 0; p < 8; p++) s += g_Wpart[(p * DD + d) * 128 + j];
    } else {
        s = W_v[d * KK + (j - 128)];
    }
    __nv_bfloat16 h = __float2bfloat16_rn(s);
    g_Whi[idx] = h;
    g_Wlo[idx] = __float2bfloat16_rn(s - __bfloat162float(h));
}

// ---------------------------------------------------------------------------
// Kernel B: QKV GEMM, K-split by phase. grid 576 = 64 rows x 3 n x 3 phase.
// Each block: K=1024 over its phase's (A,B) pair, writes fp32 partial.
// k-step 64, double-buffered smem, one sync per iter, 16 iters.
// ---------------------------------------------------------------------------
#define QAP 72
__global__ __launch_bounds__(256, 2) void qkv_mma()
{
    __shared__ __nv_bfloat16 As[2][128][QAP];   // 36.9 KB
    __shared__ __nv_bfloat16 Bs[2][64][QAP];    // 18.4 KB
    int bid = blockIdx.x;
    int phase = bid % 3;
    int n0 = ((bid / 3) % 3) * 64;
    int r0 = (bid / 9) * 128;
    const __nv_bfloat16* __restrict__ Asrc = (phase == 1) ? g_xlo : g_xhi;
    const __nv_bfloat16* __restrict__ Bsrc = (phase == 2) ? g_Wlo : g_Whi;

    int tid = threadIdx.x;
    int lane = tid & 31, w = tid >> 5;
    int wm = (w & 3) * 32, wn = (w >> 2) * 32;

    float acc[2][4][4];
#pragma unroll
    for (int mt = 0; mt < 2; mt++)
#pragma unroll
        for (int nt = 0; nt < 4; nt++)
#pragma unroll
            for (int r = 0; r < 4; r++) acc[mt][nt][r] = 0.f;

    int ar = tid >> 3, ac = (tid & 7) * 8;   // A rows ar+{0,32,64,96}, 8 bf16 each
    int br = tid >> 3, bc = (tid & 7) * 8;   // B rows br, br+32

    float4 av[4], bv[2];
#pragma unroll
    for (int r = 0; r < 4; r++)
        av[r] = *(const float4*)&Asrc[(r0 + ar + r * 32) * DD + ac];
    bv[0] = *(const float4*)&Bsrc[br * NQ + n0 + bc];
    bv[1] = *(const float4*)&Bsrc[(br + 32) * NQ + n0 + bc];
#pragma unroll
    for (int r = 0; r < 4; r++)
        *(float4*)&As[0][ar + r * 32][ac] = av[r];
    *(float4*)&Bs[0][br][bc]      = bv[0];
    *(float4*)&Bs[0][br + 32][bc] = bv[1];
    __syncthreads();

    for (int it = 0; it < 16; it++) {
        int buf = it & 1;
        bool more = (it + 1 < 16);
        if (more) {
            int kk = (it + 1) * 64;
#pragma unroll
            for (int r = 0; r < 4; r++)
                av[r] = *(const float4*)&Asrc[(r0 + ar + r * 32) * DD + kk + ac];
            bv[0] = *(const float4*)&Bsrc[(kk + br) * NQ + n0 + bc];
            bv[1] = *(const float4*)&Bsrc[(kk + br + 32) * NQ + n0 + bc];
        }

#pragma unroll
        for (int ks = 0; ks < 4; ks++) {
            int k = ks * 16;
            uint32_t a[2][4];
#pragma unroll
            for (int mt = 0; mt < 2; mt++) {
                uint32_t ad = smaddr(&As[buf][wm + mt * 16 + (lane & 15)][k + ((lane >> 4) << 3)]);
                ldsm_x4(a[mt][0], a[mt][1], a[mt][2], a[mt][3], ad);
            }
            uint32_t b[2][4];
#pragma unroll
            for (int nb = 0; nb < 2; nb++) {
                uint32_t bd = smaddr(&Bs[buf][k + (lane & 15)][wn + nb * 16 + ((lane >> 4) << 3)]);
                ldsm_x4_t(b[nb][0], b[nb][1], b[nb][2], b[nb][3], bd);
            }
#pragma unroll
            for (int mt = 0; mt < 2; mt++)
#pragma unroll
                for (int nt = 0; nt < 4; nt++) {
                    int nb = nt >> 1, pr = nt & 1;
                    mma_bf16(acc[mt][nt], a[mt], b[nb][pr * 2], b[nb][pr * 2 + 1]);
                }
        }

        if (more) {
#pragma unroll
            for (int r = 0; r < 4; r++)
                *(float4*)&As[buf ^ 1][ar + r * 32][ac] = av[r];
            *(float4*)&Bs[buf ^ 1][br][bc]      = bv[0];
            *(float4*)&Bs[buf ^ 1][br + 32][bc] = bv[1];
            __syncthreads();
        }
    }

    // epilogue: write fp32 partial (no bias here)
    float* Qp = g_Qp[phase];
    int gr = lane >> 2, tc = (lane & 3) * 2;
#pragma unroll
    for (int mt = 0; mt < 2; mt++)
#pragma unroll
        for (int nt = 0; nt < 4; nt++) {
            int row = r0 + wm + mt * 16 + gr;
            int col = n0 + wn + nt * 8 + tc;
            Qp[row * NQ + col]           = acc[mt][nt][0];
            Qp[row * NQ + col + 1]       = acc[mt][nt][1];
            Qp[(row + 8) * NQ + col]     = acc[mt][nt][2];
            Qp[(row + 8) * NQ + col + 1] = acc[mt][nt][3];
        }
}

// ---------------------------------------------------------------------------
// Kernel B2: QKV = p0 + p1 + p2 + bias
// ---------------------------------------------------------------------------
__global__ __launch_bounds__(256) void qkv_reduce()
{
    int i = blockIdx.x * blockDim.x + threadIdx.x;   // one float4
    float4 p0 = ((const float4*)g_Qp[0])[i];
    float4 p1 = ((const float4*)g_Qp[1])[i];
    float4 p2 = ((const float4*)g_Qp[2])[i];
    int col = (i * 4) % NQ;
    float4 bb = *(const float4*)&g_bqkv[col];
    float4 o;
    o.x = p0.x + p1.x + p2.x + bb.x;
    o.y = p0.y + p1.y + p2.y + bb.y;
    o.z = p0.z + p1.z + p2.z + bb.z;
    o.w = p0.w + p1.w + p2.w + bb.w;
    ((float4*)g_QKV)[i] = o;
}

// ---------------------------------------------------------------------------
// Kernel C1: per-sub-chunk state sums (32 steps each), grid 256, float4 LDS
// ---------------------------------------------------------------------------
__global__ __launch_bounds__(256) void chunk_sum(const float* __restrict__ decay)
{
    __shared__ float Vs[32][68];       // pitch 68: rows 16B-aligned
    __shared__ float Ks[32][68];
    int b = blockIdx.x >> 6, sc = blockIdx.x & 63;
    int base = b * TT + sc * 32;
    int tid = threadIdx.x;
    int ty = tid >> 4, tx = tid & 15;
    float acc[4][4];
#pragma unroll
    for (int i = 0; i < 4; i++)
#pragma unroll
        for (int j = 0; j < 4; j++) acc[i][j] = 0.f;

    for (int i = tid; i < 32 * 64; i += 256) {
        int r = i >> 6, k = i & 63;
        int row = base + r;
        float d = decay[sc * 32 + r];
        Vs[r][k] = g_QKV[row * NQ + 128 + k];
        Ks[r][k] = g_QKV[row * NQ + 64 + k] * d;
    }
    __syncthreads();
#pragma unroll 8
    for (int s = 0; s < 32; s++) {
        float4 a4 = *(const float4*)&Vs[s][ty * 4];
        float4 b4 = *(const float4*)&Ks[s][tx * 4];
        float a[4] = {a4.x, a4.y, a4.z, a4.w};
        float bb[4] = {b4.x, b4.y, b4.z, b4.w};
#pragma unroll
        for (int i = 0; i < 4; i++)
#pragma unroll
            for (int j = 0; j < 4; j++) acc[i][j] += a[i] * bb[j];
    }
    int sb = (b * NSC + sc) * KK * KK;
#pragma unroll
    for (int i = 0; i < 4; i++)
#pragma unroll
        for (int j = 0; j < 4; j++)
            g_S[sb + (ty * 4 + i) * KK + tx * 4 + j] = acc[i][j];
}

// ---------------------------------------------------------------------------
// Kernel C2: exclusive prefix over 64-row half-chunks (sums S pairs), 64 blocks
// ---------------------------------------------------------------------------
__global__ __launch_bounds__(256) void chunk_prefix()
{
    int b = blockIdx.x >> 4;
    int e = (blockIdx.x & 15) * 256 + threadIdx.x;   // 0..4095
    float acc = 0.f;
    int sbase = b * NSC * KK * KK;
    int hbase = b * NH * KK * KK;
    for (int c = 0; c < NH; c++) {
        g_H[hbase + c * KK * KK + e] = acc;
        acc += g_S[sbase + (2 * c) * KK * KK + e]
             + g_S[sbase + (2 * c + 1) * KK * KK + e];
    }
}

// ---------------------------------------------------------------------------
// Kernel C3: half-chunk attention (64 rows). grid = BB*NH = 128 blocks.
// ---------------------------------------------------------------------------
__global__ __launch_bounds__(256) void attn_kernel(const float* __restrict__ decay)
{
    __shared__ float Qt[KK][64];       // transposed Q [k][r], 16KB
    __shared__ float Reg[4096];        // union: H[64][64] | V[32][64]+Kd[32][64]
    int b = blockIdx.x >> 5, hc = blockIdx.x & 31;
    int base = b * TT + hc * 64;
    int tid = threadIdx.x;
    int row = tid >> 2;                // 0..63
    int qd = tid & 3;                  // n-quarter: cols qd*16 .. qd*16+15

    for (int i = tid; i < KK * 64; i += 256) {
        int r = i & 63, k = i >> 6;
        Qt[k][r] = g_QKV[(base + r) * NQ + k];
    }
    int hb = (b * NH + hc) * KK * KK;
    for (int i = tid; i < KK * KK; i += 256) Reg[i] = g_H[hb + i];
    __syncthreads();

    float q[KK];
#pragma unroll
    for (int k = 0; k < KK; k++) q[k] = Qt[k][row];

    float y[16];
#pragma unroll
    for (int j = 0; j < 16; j++) y[j] = 0.f;

    // inter: y += q . H[:, quarter]
    {
        const float4* H4 = (const float4*)Reg;
#pragma unroll
        for (int k = 0; k < KK; k++) {
            float qk = q[k];
#pragma unroll
            for (int jj = 0; jj < 4; jj++) {
                float4 h = H4[k * 16 + qd * 4 + jj];
                y[jj * 4 + 0] += qk * h.x;
                y[jj * 4 + 1] += qk * h.y;
                y[jj * 4 + 2] += qk * h.z;
                y[jj * 4 + 3] += qk * h.w;
            }
        }
    }
    __syncthreads();

    // intra-half-chunk causal, 2 s-tiles of 32
    for (int st = 0; st < 64; st += 32) {
        for (int i = tid; i < 2048; i += 256) {
            int s = i >> 6, k = i & 63;
            int grow = (base + st + s) * NQ;
            Reg[i]        = g_QKV[grow + 128 + k];
            Reg[2048 + i] = g_QKV[grow + 64 + k] * decay[hc * 64 + st + s];
        }
        __syncthreads();
        if (row >= st) {
            int sm = row - st + 1;
            if (sm > 32) sm = 32;
            const float4* V4 = (const float4*)Reg;
            const float4* F4 = (const float4*)(Reg + 2048);
            for (int s = 0; s < sm; s++) {
                float sc = 0.f;
#pragma unroll
                for (int kk = 0; kk < 16; kk++) {
                    float4 v = V4[s * 16 + kk];
                    sc += q[kk * 4 + 0] * v.x + q[kk * 4 + 1] * v.y
                        + q[kk * 4 + 2] * v.z + q[kk * 4 + 3] * v.w;
                }
#pragma unroll
                for (int jj = 0; jj < 4; jj++) {
                    float4 f = F4[s * 16 + qd * 4 + jj];
                    y[jj * 4 + 0] += sc * f.x;
                    y[jj * 4 + 1] += sc * f.y;
                    y[jj * 4 + 2] += sc * f.z;
                    y[jj * 4 + 3] += sc * f.w;
                }
            }
        }
        __syncthreads();
    }

    // epilogue: split to bf16 hi/lo, 8-byte packed stores
    int ybase = (base + row) * KK + qd * 16;
#pragma unroll
    for (int jj = 0; jj < 4; jj++) {
        __nv_bfloat16 hp[4], lp[4];
#pragma unroll
        for (int e = 0; e < 4; e++) {
            float f = y[jj * 4 + e];
            hp[e] = __float2bfloat16_rn(f);
            lp[e] = __float2bfloat16_rn(f - __bfloat162float(hp[e]));
        }
        *(uint2*)&g_Yhi[ybase + jj * 4] = *(uint2*)hp;
        *(uint2*)&g_Ylo[ybase + jj * 4] = *(uint2*)lp;
    }
}

// ---------------------------------------------------------------------------
// Kernel D: out = Y @ W_o + b_o  on tensor cores (3-term split, K packed=192)
// ---------------------------------------------------------------------------
#define APITCH 40
#define BPITCH 72
__global__ __launch_bounds__(256, 2) void out_mma(const float* __restrict__ b_o,
                                                  float* __restrict__ out)
{
    __shared__ __nv_bfloat16 As[128][APITCH];
    __shared__ __nv_bfloat16 Bs[32][BPITCH];
    int r0 = blockIdx.x * 128;
    int n0 = blockIdx.y * 64;
    int tid = threadIdx.x;
    int lane = tid & 31, w = tid >> 5;
    int wm = (w & 3) * 32, wn = (w >> 2) * 32;

    float acc[2][4][4];
#pragma unroll
    for (int mt = 0; mt < 2; mt++)
#pragma unroll
        for (int nt = 0; nt < 4; nt++)
#pragma unroll
            for (int r = 0; r < 4; r++) acc[mt][nt][r] = 0.f;

    int ar = tid >> 2, ac = (tid & 3) * 8;
    int br = tid >> 3, bc = (tid & 7) * 8;

    float4 a0v, a1v, bv;
    {   // prefetch iter 0: phase 0 (Yhi, Wohi), kk = 0
        a0v = *(const float4*)&g_Yhi[(r0 + ar) * KK + ac];
        a1v = *(const float4*)&g_Yhi[(r0 + ar + 64) * KK + ac];
        bv  = *(const float4*)&g_Wohi[br * DD + n0 + bc];
    }

    for (int it = 0; it < 6; it++) {
        *(float4*)&As[ar][ac]      = a0v;
        *(float4*)&As[ar + 64][ac] = a1v;
        *(float4*)&Bs[br][bc]      = bv;
        __syncthreads();

        if (it + 1 < 6) {
            int nit = it + 1;
            int phase = nit >> 1;
            int kk = (nit & 1) * 32;
            const __nv_bfloat16* Asrc = (phase == 1) ? g_Ylo : g_Yhi;
            const __nv_bfloat16* Bsrc = (phase == 2) ? g_Wolo : g_Wohi;
            a0v = *(const float4*)&Asrc[(r0 + ar) * KK + kk + ac];
            a1v = *(const float4*)&Asrc[(r0 + ar + 64) * KK + kk + ac];
            bv  = *(const float4*)&Bsrc[(kk + br) * DD + n0 + bc];
        }

#pragma unroll
        for (int ks = 0; ks < 2; ks++) {
            int k = ks * 16;
            uint32_t a[2][4];
#pragma unroll
            for (int mt = 0; mt < 2; mt++) {
                uint32_t ad = smaddr(&As[wm + mt * 16 + (lane & 15)][k + ((lane >> 4) << 3)]);
                ldsm_x4(a[mt][0], a[mt][1], a[mt][2], a[mt][3], ad);
            }
            uint32_t b[2][4];
#pragma unroll
            for (int nb = 0; nb < 2; nb++) {
                uint32_t bd = smaddr(&Bs[k + (lane & 15)][wn + nb * 16 + ((lane >> 4) << 3)]);
                ldsm_x4_t(b[nb][0], b[nb][1], b[nb][2], b[nb][3], bd);
            }
#pragma unroll
            for (int mt = 0; mt < 2; mt++)
#pragma unroll
                for (int nt = 0; nt < 4; nt++) {
                    int nb = nt >> 1, pr = nt & 1;
                    mma_bf16(acc[mt][nt], a[mt], b[nb][pr * 2], b[nb][pr * 2 + 1]);
                }
        }
        __syncthreads();
    }

    int gr = lane >> 2, tc = (lane & 3) * 2;
#pragma unroll
    for (int mt = 0; mt < 2; mt++)
#pragma unroll
        for (int nt = 0; nt < 4; nt++) {
            int row = r0 + wm + mt * 16 + gr;
            int col = n0 + wn + nt * 8 + tc;
            float bb0 = b_o[col], bb1 = b_o[col + 1];
            out[row * DD + col]           = acc[mt][nt][0] + bb0;
            out[row * DD + col + 1]       = acc[mt][nt][1] + bb1;
            out[(row + 8) * DD + col]     = acc[mt][nt][2] + bb0;
            out[(row + 8) * DD + col + 1] = acc[mt][nt][3] + bb1;
        }
}

// ---------------------------------------------------------------------------
extern "C" void kernel_launch(void* const* d_in, const int* in_sizes, int n_in,
                              void* d_out, int out_size)
{
    const float* x      = (const float*)d_in[0];
    const float* W_pre  = (const float*)d_in[1];
    const float* b_pre  = (const float*)d_in[2];
    const float* Q_filt = (const float*)d_in[3];
    const float* K_filt = (const float*)d_in[4];
    const float* W_v    = (const float*)d_in[5];
    const float* b_v    = (const float*)d_in[6];
    const float* W_o    = (const float*)d_in[7];
    const float* b_o    = (const float*)d_in[8];
    const float* decay  = (const float*)d_in[9];
    float* out = (float*)d_out;

    prep_fused<<<NB_WF + NB_BIAS + NB_WO + NB_SX, 256>>>(
        x, W_pre, b_pre, Q_filt, K_filt, b_v, W_o);
    wqkv_finalize<<<(DD * NQ + 255) / 256, 256>>>(W_v);
    qkv_mma<<<576, 256>>>();
    qkv_reduce<<<(RR * NQ / 4) / 256, 256>>>();
    chunk_sum<<<256, 256>>>(decay);
    chunk_prefix<<<64, 256>>>();
    attn_kernel<<<BB * NH, 256>>>(decay);
    out_mma<<<dim3(64, 16), 256>>>(b_o, out);
}

// round 15
// speedup vs baseline: 1.8310x; 1.0087x over previous
#include <cuda_runtime.h>
#include <cuda_bf16.h>
#include <cstdint>

// Problem constants
#define BB 4
#define TT 2048
#define DD 1024
#define KK 64
#define RR (BB*TT)        // 8192 rows
#define NQ 192            // Q|K|V packed cols
#define NSC 64            // sub-chunks per batch for S (32 steps each)
#define NH 32             // H states per batch (64-row half-chunks)

// Scratch (device globals — no allocation allowed)
__device__ float g_Wpart[8 * DD * 128];          // split-K partials for W_pre@[Qf|Kf]
__device__ float g_bqkv[NQ];
__device__ float g_Qp[3][RR * NQ];               // per-phase QKV partials (19MB)
__device__ float g_QKV[RR * NQ];                 // [row, 192]
__device__ float g_S[BB * NSC * KK * KK];        // per-32-step-sub-chunk sums (4MB)
__device__ float g_H[BB * NH * KK * KK];         // exclusive prefix states (2MB)
// bf16 split operands
__device__ __nv_bfloat16 g_xhi[RR * DD];
__device__ __nv_bfloat16 g_xlo[RR * DD];
__device__ __nv_bfloat16 g_Whi[DD * NQ];
__device__ __nv_bfloat16 g_Wlo[DD * NQ];
__device__ __nv_bfloat16 g_Yhi[RR * KK];
__device__ __nv_bfloat16 g_Ylo[RR * KK];
__device__ __nv_bfloat16 g_Wohi[KK * DD];
__device__ __nv_bfloat16 g_Wolo[KK * DD];

// ---------------------------------------------------------------------------
// helpers
// ---------------------------------------------------------------------------
__device__ __forceinline__ uint32_t smaddr(const void* p) {
    return (uint32_t)__cvta_generic_to_shared(p);
}
__device__ __forceinline__ void ldsm_x4(uint32_t& r0, uint32_t& r1,
                                        uint32_t& r2, uint32_t& r3, uint32_t a) {
    asm volatile("ldmatrix.sync.aligned.m8n8.x4.shared.b16 {%0,%1,%2,%3}, [%4];"
                 : "=r"(r0), "=r"(r1), "=r"(r2), "=r"(r3) : "r"(a));
}
__device__ __forceinline__ void ldsm_x4_t(uint32_t& r0, uint32_t& r1,
                                          uint32_t& r2, uint32_t& r3, uint32_t a) {
    asm volatile("ldmatrix.sync.aligned.m8n8.x4.trans.shared.b16 {%0,%1,%2,%3}, [%4];"
                 : "=r"(r0), "=r"(r1), "=r"(r2), "=r"(r3) : "r"(a));
}
__device__ __forceinline__ void mma_bf16(float* c, const uint32_t* a,
                                         uint32_t b0, uint32_t b1) {
    asm volatile(
        "mma.sync.aligned.m16n8k16.row.col.f32.bf16.bf16.f32 "
        "{%0,%1,%2,%3}, {%4,%5,%6,%7}, {%8,%9}, {%0,%1,%2,%3};"
        : "+f"(c[0]), "+f"(c[1]), "+f"(c[2]), "+f"(c[3])
        : "r"(a[0]), "r"(a[1]), "r"(a[2]), "r"(a[3]), "r"(b0), "r"(b1));
}

// ---------------------------------------------------------------------------
// Fused preprocessing kernel: all consumers of raw inputs, run concurrently.
// ---------------------------------------------------------------------------
#define NB_WF   128
#define NB_BIAS 192
#define NB_WO   64
#define NB_SX   8192
__global__ __launch_bounds__(256) void prep_fused(
    const float* __restrict__ x,
    const float* __restrict__ W_pre,
    const float* __restrict__ b_pre,
    const float* __restrict__ Q_filt,
    const float* __restrict__ K_filt,
    const float* __restrict__ b_v,
    const float* __restrict__ W_o)
{
    __shared__ float sbuf[64 * 33 + 32 * 128];   // 24.8 KB, role-dependent
    int bid = blockIdx.x;
    int tid = threadIdx.x;

    if (bid < NB_WF) {
        // ---------------- wfilt_partial ----------------
        float (*Wp)[33]  = (float(*)[33])sbuf;
        float (*Fs)[128] = (float(*)[128])(sbuf + 64 * 33);
        int d0 = (bid & 15) * 64;
        int split = bid >> 4;
        int ty = tid >> 4, tx = tid & 15;
        float acc[4][8];
#pragma unroll
        for (int i = 0; i < 4; i++)
#pragma unroll
            for (int j = 0; j < 8; j++) acc[i][j] = 0.f;

        int t0 = split * 256;
        for (int kt = t0; kt < t0 + 256; kt += 32) {
            for (int i = tid; i < 64 * 32; i += 256) {
                int r = i >> 5, c = i & 31;
                Wp[r][c] = W_pre[(d0 + r) * TT + kt + c];
            }
            for (int i = tid; i < 32 * 128; i += 256) {
                int r = i >> 7, c = i & 127;
                Fs[r][c] = (c < 64) ? Q_filt[(kt + r) * KK + c]
                                    : K_filt[(kt + r) * KK + (c - 64)];
            }
            __syncthreads();
#pragma unroll
            for (int kk = 0; kk < 32; kk++) {
                float a[4];
#pragma unroll
                for (int i = 0; i < 4; i++) a[i] = Wp[ty * 4 + i][kk];
                const float4* F4 = (const float4*)&Fs[kk][0];
                float4 b0 = F4[tx * 2 + 0];
                float4 b1 = F4[tx * 2 + 1];
                float bb[8] = {b0.x, b0.y, b0.z, b0.w, b1.x, b1.y, b1.z, b1.w};
#pragma unroll
                for (int i = 0; i < 4; i++)
#pragma unroll
                    for (int j = 0; j < 8; j++) acc[i][j] += a[i] * bb[j];
            }
            __syncthreads();
        }
#pragma unroll
        for (int i = 0; i < 4; i++)
#pragma unroll
            for (int j = 0; j < 8; j++)
                g_Wpart[(split * DD + d0 + ty * 4 + i) * 128 + tx * 8 + j] = acc[i][j];
    } else if (bid < NB_WF + NB_BIAS) {
        // ---------------- bias columns ----------------
        int j = bid - NB_WF;            // 0..191
        if (j >= 128) {
            if (tid == 0) g_bqkv[j] = b_v[j - 128];
            return;
        }
        const float* F = (j < 64) ? Q_filt : K_filt;
        int col = j & 63;
        float s = 0.f;
        for (int t = tid; t < TT; t += 256)
            s += b_pre[t] * F[t * KK + col];
#pragma unroll
        for (int o = 16; o > 0; o >>= 1)
            s += __shfl_xor_sync(0xffffffff, s, o);
        float* red = sbuf;
        if ((tid & 31) == 0) red[tid >> 5] = s;
        __syncthreads();
        if (tid == 0) {
            float tot = 0.f;
#pragma unroll
            for (int w = 0; w < 8; w++) tot += red[w];
            g_bqkv[j] = tot;
        }
    } else if (bid < NB_WF + NB_BIAS + NB_WO) {
        // ---------------- wo_split ----------------
        int i = (bid - NB_WF - NB_BIAS) * 256 + tid;
        float4 v = ((const float4*)W_o)[i];
        __nv_bfloat16 h[4], l[4];
        float f[4] = {v.x, v.y, v.z, v.w};
#pragma unroll
        for (int j = 0; j < 4; j++) {
            h[j] = __float2bfloat16_rn(f[j]);
            l[j] = __float2bfloat16_rn(f[j] - __bfloat162float(h[j]));
        }
        *(uint2*)&g_Wohi[i * 4] = *(uint2*)h;
        *(uint2*)&g_Wolo[i * 4] = *(uint2*)l;
    } else {
        // ---------------- split_x ----------------
        int i = (bid - NB_WF - NB_BIAS - NB_WO) * 256 + tid;
        float4 v = ((const float4*)x)[i];
        __nv_bfloat16 h[4], l[4];
        float f[4] = {v.x, v.y, v.z, v.w};
#pragma unroll
        for (int j = 0; j < 4; j++) {
            h[j] = __float2bfloat16_rn(f[j]);
            l[j] = __float2bfloat16_rn(f[j] - __bfloat162float(h[j]));
        }
        *(uint2*)&g_xhi[i * 4] = *(uint2*)h;
        *(uint2*)&g_xlo[i * 4] = *(uint2*)l;
    }
}

// ---------------------------------------------------------------------------
// Kernel A2: reduce split-K partials + W_v, write bf16 hi/lo directly
// ---------------------------------------------------------------------------
__global__ void wqkv_finalize(const float* __restrict__ W_v)
{
    int idx = blockIdx.x * blockDim.x + threadIdx.x;
    if (idx >= DD * NQ) return;
    int d = idx / NQ, j = idx % NQ;
    float s;
    if (j < 128) {
        s = 0.f;
#pragma unroll
        for (int p = 0; p < 8; p++) s += g_Wpart[(p * DD + d) * 128 + j];
    } else {
        s = W_v[d * KK + (j - 128)];
    }
    __nv_bfloat16 h = __float2bfloat16_rn(s);
    g_Whi[idx] = h;
    g_Wlo[idx] = __float2bfloat16_rn(s - __bfloat162float(h));
}

// ---------------------------------------------------------------------------
// Kernel B: QKV GEMM, K-split by phase. grid 576 = 64 rows x 3 n x 3 phase.
// ---------------------------------------------------------------------------
#define QAP 72
__global__ __launch_bounds__(256, 2) void qkv_mma()
{
    __shared__ __nv_bfloat16 As[2][128][QAP];   // 36.9 KB
    __shared__ __nv_bfloat16 Bs[2][64][QAP];    // 18.4 KB
    int bid = blockIdx.x;
    int phase = bid % 3;
    int n0 = ((bid / 3) % 3) * 64;
    int r0 = (bid / 9) * 128;
    const __nv_bfloat16* __restrict__ Asrc = (phase == 1) ? g_xlo : g_xhi;
    const __nv_bfloat16* __restrict__ Bsrc = (phase == 2) ? g_Wlo : g_Whi;

    int tid = threadIdx.x;
    int lane = tid & 31, w = tid >> 5;
    int wm = (w & 3) * 32, wn = (w >> 2) * 32;

    float acc[2][4][4];
#pragma unroll
    for (int mt = 0; mt < 2; mt++)
#pragma unroll
        for (int nt = 0; nt < 4; nt++)
#pragma unroll
            for (int r = 0; r < 4; r++) acc[mt][nt][r] = 0.f;

    int ar = tid >> 3, ac = (tid & 7) * 8;   // A rows ar+{0,32,64,96}, 8 bf16 each
    int br = tid >> 3, bc = (tid & 7) * 8;   // B rows br, br+32

    float4 av[4], bv[2];
#pragma unroll
    for (int r = 0; r < 4; r++)
        av[r] = *(const float4*)&Asrc[(r0 + ar + r * 32) * DD + ac];
    bv[0] = *(const float4*)&Bsrc[br * NQ + n0 + bc];
    bv[1] = *(const float4*)&Bsrc[(br + 32) * NQ + n0 + bc];
#pragma unroll
    for (int r = 0; r < 4; r++)
        *(float4*)&As[0][ar + r * 32][ac] = av[r];
    *(float4*)&Bs[0][br][bc]      = bv[0];
    *(float4*)&Bs[0][br + 32][bc] = bv[1];
    __syncthreads();

    for (int it = 0; it < 16; it++) {
        int buf = it & 1;
        bool more = (it + 1 < 16);
        if (more) {
            int kk = (it + 1) * 64;
#pragma unroll
            for (int r = 0; r < 4; r++)
                av[r] = *(const float4*)&Asrc[(r0 + ar + r * 32) * DD + kk + ac];
            bv[0] = *(const float4*)&Bsrc[(kk + br) * NQ + n0 + bc];
            bv[1] = *(const float4*)&Bsrc[(kk + br + 32) * NQ + n0 + bc];
        }

#pragma unroll
        for (int ks = 0; ks < 4; ks++) {
            int k = ks * 16;
            uint32_t a[2][4];
#pragma unroll
            for (int mt = 0; mt < 2; mt++) {
                uint32_t ad = smaddr(&As[buf][wm + mt * 16 + (lane & 15)][k + ((lane >> 4) << 3)]);
                ldsm_x4(a[mt][0], a[mt][1], a[mt][2], a[mt][3], ad);
            }
            uint32_t b[2][4];
#pragma unroll
            for (int nb = 0; nb < 2; nb++) {
                uint32_t bd = smaddr(&Bs[buf][k + (lane & 15)][wn + nb * 16 + ((lane >> 4) << 3)]);
                ldsm_x4_t(b[nb][0], b[nb][1], b[nb][2], b[nb][3], bd);
            }
#pragma unroll
            for (int mt = 0; mt < 2; mt++)
#pragma unroll
                for (int nt = 0; nt < 4; nt++) {
                    int nb = nt >> 1, pr = nt & 1;
                    mma_bf16(acc[mt][nt], a[mt], b[nb][pr * 2], b[nb][pr * 2 + 1]);
                }
        }

        if (more) {
#pragma unroll
            for (int r = 0; r < 4; r++)
                *(float4*)&As[buf ^ 1][ar + r * 32][ac] = av[r];
            *(float4*)&Bs[buf ^ 1][br][bc]      = bv[0];
            *(float4*)&Bs[buf ^ 1][br + 32][bc] = bv[1];
            __syncthreads();
        }
    }

    // epilogue: write fp32 partial (no bias here)
    float* Qp = g_Qp[phase];
    int gr = lane >> 2, tc = (lane & 3) * 2;
#pragma unroll
    for (int mt = 0; mt < 2; mt++)
#pragma unroll
        for (int nt = 0; nt < 4; nt++) {
            int row = r0 + wm + mt * 16 + gr;
            int col = n0 + wn + nt * 8 + tc;
            Qp[row * NQ + col]           = acc[mt][nt][0];
            Qp[row * NQ + col + 1]       = acc[mt][nt][1];
            Qp[(row + 8) * NQ + col]     = acc[mt][nt][2];
            Qp[(row + 8) * NQ + col + 1] = acc[mt][nt][3];
        }
}

// ---------------------------------------------------------------------------
// Kernel B2: QKV = p0 + p1 + p2 + bias
// ---------------------------------------------------------------------------
__global__ __launch_bounds__(256) void qkv_reduce()
{
    int i = blockIdx.x * blockDim.x + threadIdx.x;   // one float4
    float4 p0 = ((const float4*)g_Qp[0])[i];
    float4 p1 = ((const float4*)g_Qp[1])[i];
    float4 p2 = ((const float4*)g_Qp[2])[i];
    int col = (i * 4) % NQ;
    float4 bb = *(const float4*)&g_bqkv[col];
    float4 o;
    o.x = p0.x + p1.x + p2.x + bb.x;
    o.y = p0.y + p1.y + p2.y + bb.y;
    o.z = p0.z + p1.z + p2.z + bb.z;
    o.w = p0.w + p1.w + p2.w + bb.w;
    ((float4*)g_QKV)[i] = o;
}

// ---------------------------------------------------------------------------
// Kernel C1: per-sub-chunk state sums (32 steps each), grid 256, float4 LDS
// ---------------------------------------------------------------------------
__global__ __launch_bounds__(256) void chunk_sum(const float* __restrict__ decay)
{
    __shared__ float Vs[32][68];       // pitch 68: rows 16B-aligned
    __shared__ float Ks[32][68];
    int b = blockIdx.x >> 6, sc = blockIdx.x & 63;
    int base = b * TT + sc * 32;
    int tid = threadIdx.x;
    int ty = tid >> 4, tx = tid & 15;
    float acc[4][4];
#pragma unroll
    for (int i = 0; i < 4; i++)
#pragma unroll
        for (int j = 0; j < 4; j++) acc[i][j] = 0.f;

    for (int i = tid; i < 32 * 64; i += 256) {
        int r = i >> 6, k = i & 63;
        int row = base + r;
        float d = decay[sc * 32 + r];
        Vs[r][k] = g_QKV[row * NQ + 128 + k];
        Ks[r][k] = g_QKV[row * NQ + 64 + k] * d;
    }
    __syncthreads();
#pragma unroll 8
    for (int s = 0; s < 32; s++) {
        float4 a4 = *(const float4*)&Vs[s][ty * 4];
        float4 b4 = *(const float4*)&Ks[s][tx * 4];
        float a[4] = {a4.x, a4.y, a4.z, a4.w};
        float bb[4] = {b4.x, b4.y, b4.z, b4.w};
#pragma unroll
        for (int i = 0; i < 4; i++)
#pragma unroll
            for (int j = 0; j < 4; j++) acc[i][j] += a[i] * bb[j];
    }
    int sb = (b * NSC + sc) * KK * KK;
#pragma unroll
    for (int i = 0; i < 4; i++)
#pragma unroll
        for (int j = 0; j < 4; j++)
            g_S[sb + (ty * 4 + i) * KK + tx * 4 + j] = acc[i][j];
}

// ---------------------------------------------------------------------------
// Kernel C2: exclusive prefix over 64-row half-chunks. grid 128 x 128 threads
// ---------------------------------------------------------------------------
__global__ __launch_bounds__(128) void chunk_prefix()
{
    int b = blockIdx.x >> 5;
    int e = (blockIdx.x & 31) * 128 + threadIdx.x;   // 0..4095
    float acc = 0.f;
    int sbase = b * NSC * KK * KK;
    int hbase = b * NH * KK * KK;
    for (int c = 0; c < NH; c++) {
        g_H[hbase + c * KK * KK + e] = acc;
        acc += g_S[sbase + (2 * c) * KK * KK + e]
             + g_S[sbase + (2 * c + 1) * KK * KK + e];
    }
}

// ---------------------------------------------------------------------------
// Kernel C3: half-chunk attention split by n-half. grid = BB*NH*2 = 256.
// bid: b = bid>>6, hc = (bid>>1)&31, nh = bid&1 (cols nh*32..nh*32+31).
// threads: row (0..63) x quarter (8 cols within the half). y[8].
// ---------------------------------------------------------------------------
__global__ __launch_bounds__(256, 2) void attn_kernel(const float* __restrict__ decay)
{
    __shared__ float Qt[KK][64];       // transposed Q [k][r], 16KB
    __shared__ float Reg[3072];        // union: H[64][32] | V[32][64]+Kd[32][32]
    int b = blockIdx.x >> 6, hc = (blockIdx.x >> 1) & 31, nh = blockIdx.x & 1;
    int base = b * TT + hc * 64;
    int tid = threadIdx.x;
    int row = tid >> 2;                // 0..63
    int qd = tid & 3;                  // 8-col quarter within the 32-col half

    for (int i = tid; i < KK * 64; i += 256) {
        int r = i & 63, k = i >> 6;
        Qt[k][r] = g_QKV[(base + r) * NQ + k];
    }
    // H half: Reg[k*32 + j] = H[k][nh*32+j]
    int hb = (b * NH + hc) * KK * KK + nh * 32;
    for (int i = tid; i < KK * 32; i += 256) {
        int k = i >> 5, j = i & 31;
        Reg[i] = g_H[hb + k * KK + j];
    }
    __syncthreads();

    float q[KK];
#pragma unroll
    for (int k = 0; k < KK; k++) q[k] = Qt[k][row];

    float y[8];
#pragma unroll
    for (int j = 0; j < 8; j++) y[j] = 0.f;

    // inter: y += q . H[:, half cols]
    {
        const float4* H4 = (const float4*)Reg;
#pragma unroll
        for (int k = 0; k < KK; k++) {
            float qk = q[k];
#pragma unroll
            for (int jj = 0; jj < 2; jj++) {
                float4 h = H4[k * 8 + qd * 2 + jj];
                y[jj * 4 + 0] += qk * h.x;
                y[jj * 4 + 1] += qk * h.y;
                y[jj * 4 + 2] += qk * h.z;
                y[jj * 4 + 3] += qk * h.w;
            }
        }
    }
    __syncthreads();

    // intra-half-chunk causal, 2 s-tiles of 32
    for (int st = 0; st < 64; st += 32) {
        // V[32][64] at Reg[0..2048), Kf-half[32][32] at Reg[2048..3072)
        for (int i = tid; i < 2048; i += 256) {
            int s = i >> 6, k = i & 63;
            Reg[i] = g_QKV[(base + st + s) * NQ + 128 + k];
        }
        for (int i = tid; i < 1024; i += 256) {
            int s = i >> 5, j = i & 31;
            Reg[2048 + i] = g_QKV[(base + st + s) * NQ + 64 + nh * 32 + j]
                          * decay[hc * 64 + st + s];
        }
        __syncthreads();
        if (row >= st) {
            int sm = row - st + 1;
            if (sm > 32) sm = 32;
            const float4* V4 = (const float4*)Reg;
            const float4* F4 = (const float4*)(Reg + 2048);
            for (int s = 0; s < sm; s++) {
                float sc = 0.f;
#pragma unroll
                for (int kk = 0; kk < 16; kk++) {
                    float4 v = V4[s * 16 + kk];
                    sc += q[kk * 4 + 0] * v.x + q[kk * 4 + 1] * v.y
                        + q[kk * 4 + 2] * v.z + q[kk * 4 + 3] * v.w;
                }
#pragma unroll
                for (int jj = 0; jj < 2; jj++) {
                    float4 f = F4[s * 8 + qd * 2 + jj];
                    y[jj * 4 + 0] += sc * f.x;
                    y[jj * 4 + 1] += sc * f.y;
                    y[jj * 4 + 2] += sc * f.z;
                    y[jj * 4 + 3] += sc * f.w;
                }
            }
        }
        __syncthreads();
    }

    // epilogue: split to bf16 hi/lo, 8-byte packed stores
    int ybase = (base + row) * KK + nh * 32 + qd * 8;
#pragma unroll
    for (int jj = 0; jj < 2; jj++) {
        __nv_bfloat16 hp[4], lp[4];
#pragma unroll
        for (int e = 0; e < 4; e++) {
            float f = y[jj * 4 + e];
            hp[e] = __float2bfloat16_rn(f);
            lp[e] = __float2bfloat16_rn(f - __bfloat162float(hp[e]));
        }
        *(uint2*)&g_Yhi[ybase + jj * 4] = *(uint2*)hp;
        *(uint2*)&g_Ylo[ybase + jj * 4] = *(uint2*)lp;
    }
}

// ---------------------------------------------------------------------------
// Kernel D: out = Y @ W_o + b_o  on tensor cores (3-term split, K packed=192)
// Double-buffered smem, one sync per iter.
// ---------------------------------------------------------------------------
#define APITCH 40
#define BPITCH 72
__global__ __launch_bounds__(256, 2) void out_mma(const float* __restrict__ b_o,
                                                  float* __restrict__ out)
{
    __shared__ __nv_bfloat16 As[2][128][APITCH];
    __shared__ __nv_bfloat16 Bs[2][32][BPITCH];
    int r0 = blockIdx.x * 128;
    int n0 = blockIdx.y * 64;
    int tid = threadIdx.x;
    int lane = tid & 31, w = tid >> 5;
    int wm = (w & 3) * 32, wn = (w >> 2) * 32;

    float acc[2][4][4];
#pragma unroll
    for (int mt = 0; mt < 2; mt++)
#pragma unroll
        for (int nt = 0; nt < 4; nt++)
#pragma unroll
            for (int r = 0; r < 4; r++) acc[mt][nt][r] = 0.f;

    int ar = tid >> 2, ac = (tid & 3) * 8;
    int br = tid >> 3, bc = (tid & 7) * 8;

    float4 a0v, a1v, bv;
    // iter 0 (Yhi, Wohi, kk=0) -> buf 0
    a0v = *(const float4*)&g_Yhi[(r0 + ar) * KK + ac];
    a1v = *(const float4*)&g_Yhi[(r0 + ar + 64) * KK + ac];
    bv  = *(const float4*)&g_Wohi[br * DD + n0 + bc];
    *(float4*)&As[0][ar][ac]      = a0v;
    *(float4*)&As[0][ar + 64][ac] = a1v;
    *(float4*)&Bs[0][br][bc]      = bv;
    __syncthreads();

    for (int it = 0; it < 6; it++) {
        int buf = it & 1;
        bool more = (it + 1 < 6);
        if (more) {
            int nit = it + 1;
            int phase = nit >> 1;
            int kk = (nit & 1) * 32;
            const __nv_bfloat16* Asrc = (phase == 1) ? g_Ylo : g_Yhi;
            const __nv_bfloat16* Bsrc = (phase == 2) ? g_Wolo : g_Wohi;
            a0v = *(const float4*)&Asrc[(r0 + ar) * KK + kk + ac];
            a1v = *(const float4*)&Asrc[(r0 + ar + 64) * KK + kk + ac];
            bv  = *(const float4*)&Bsrc[(kk + br) * DD + n0 + bc];
        }

#pragma unroll
        for (int ks = 0; ks < 2; ks++) {
            int k = ks * 16;
            uint32_t a[2][4];
#pragma unroll
            for (int mt = 0; mt < 2; mt++) {
                uint32_t ad = smaddr(&As[buf][wm + mt * 16 + (lane & 15)][k + ((lane >> 4) << 3)]);
                ldsm_x4(a[mt][0], a[mt][1], a[mt][2], a[mt][3], ad);
            }
            uint32_t b[2][4];
#pragma unroll
            for (int nb = 0; nb < 2; nb++) {
                uint32_t bd = smaddr(&Bs[buf][k + (lane & 15)][wn + nb * 16 + ((lane >> 4) << 3)]);
                ldsm_x4_t(b[nb][0], b[nb][1], b[nb][2], b[nb][3], bd);
            }
#pragma unroll
            for (int mt = 0; mt < 2; mt++)
#pragma unroll
                for (int nt = 0; nt < 4; nt++) {
                    int nb = nt >> 1, pr = nt & 1;
                    mma_bf16(acc[mt][nt], a[mt], b[nb][pr * 2], b[nb][pr * 2 + 1]);
                }
        }

        if (more) {
            *(float4*)&As[buf ^ 1][ar][ac]      = a0v;
            *(float4*)&As[buf ^ 1][ar + 64][ac] = a1v;
            *(float4*)&Bs[buf ^ 1][br][bc]      = bv;
            __syncthreads();
        }
    }

    int gr = lane >> 2, tc = (lane & 3) * 2;
#pragma unroll
    for (int mt = 0; mt < 2; mt++)
#pragma unroll
        for (int nt = 0; nt < 4; nt++) {
            int row = r0 + wm + mt * 16 + gr;
            int col = n0 + wn + nt * 8 + tc;
            float bb0 = b_o[col], bb1 = b_o[col + 1];
            out[row * DD + col]           = acc[mt][nt][0] + bb0;
            out[row * DD + col + 1]       = acc[mt][nt][1] + bb1;
            out[(row + 8) * DD + col]     = acc[mt][nt][2] + bb0;
            out[(row + 8) * DD + col + 1] = acc[mt][nt][3] + bb1;
        }
}

// ---------------------------------------------------------------------------
extern "C" void kernel_launch(void* const* d_in, const int* in_sizes, int n_in,
                              void* d_out, int out_size)
{
    const float* x      = (const float*)d_in[0];
    const float* W_pre  = (const float*)d_in[1];
    const float* b_pre  = (const float*)d_in[2];
    const float* Q_filt = (const float*)d_in[3];
    const float* K_filt = (const float*)d_in[4];
    const float* W_v    = (const float*)d_in[5];
    const float* b_v    = (const float*)d_in[6];
    const float* W_o    = (const float*)d_in[7];
    const float* b_o    = (const float*)d_in[8];
    const float* decay  = (const float*)d_in[9];
    float* out = (float*)d_out;

    prep_fused<<<NB_WF + NB_BIAS + NB_WO + NB_SX, 256>>>(
        x, W_pre, b_pre, Q_filt, K_filt, b_v, W_o);
    wqkv_finalize<<<(DD * NQ + 255) / 256, 256>>>(W_v);
    qkv_mma<<<576, 256>>>();
    qkv_reduce<<<(RR * NQ / 4) / 256, 256>>>();
    chunk_sum<<<256, 256>>>(decay);
    chunk_prefix<<<128, 128>>>();
    attn_kernel<<<BB * NH * 2, 256>>>(decay);
    out_mma<<<dim3(64, 16), 256>>>(b_o, out);
}

// round 16
// speedup vs baseline: 2.2024x; 1.2028x over previous
#include <cuda_runtime.h>
#include <cuda_bf16.h>
#include <cstdint>

// Problem constants
#define BB 4
#define TT 2048
#define DD 1024
#define KK 64
#define RR (BB*TT)        // 8192 rows
#define NQ 192            // Q|K|V packed cols
#define NSC 64            // sub-chunks per batch for S (32 steps each)
#define NH 32             // H states per batch (64-row half-chunks)

// Scratch (device globals — no allocation allowed)
__device__ float g_Wpart[12 * DD * 128];         // 3 phases x 4 K-splits partials
__device__ float g_bqkv[NQ];
__device__ float g_Qp[3][RR * NQ];               // per-phase QKV partials (19MB)
__device__ float g_QKV[RR * NQ];                 // [row, 192]
__device__ float g_S[BB * NSC * KK * KK];        // per-32-step-sub-chunk sums (4MB)
__device__ float g_H[BB * NH * KK * KK];         // exclusive prefix states (2MB)
// bf16 split operands
__device__ __nv_bfloat16 g_xhi[RR * DD];
__device__ __nv_bfloat16 g_xlo[RR * DD];
__device__ __nv_bfloat16 g_Phi[DD * TT];         // W_pre hi/lo
__device__ __nv_bfloat16 g_Plo[DD * TT];
__device__ __nv_bfloat16 g_Fhi[TT * 128];        // packed [Qf|Kf] hi/lo
__device__ __nv_bfloat16 g_Flo[TT * 128];
__device__ __nv_bfloat16 g_Whi[DD * NQ];
__device__ __nv_bfloat16 g_Wlo[DD * NQ];
__device__ __nv_bfloat16 g_Yhi[RR * KK];
__device__ __nv_bfloat16 g_Ylo[RR * KK];
__device__ __nv_bfloat16 g_Wohi[KK * DD];
__device__ __nv_bfloat16 g_Wolo[KK * DD];

// ---------------------------------------------------------------------------
// helpers
// ---------------------------------------------------------------------------
__device__ __forceinline__ uint32_t smaddr(const void* p) {
    return (uint32_t)__cvta_generic_to_shared(p);
}
__device__ __forceinline__ void ldsm_x4(uint32_t& r0, uint32_t& r1,
                                        uint32_t& r2, uint32_t& r3, uint32_t a) {
    asm volatile("ldmatrix.sync.aligned.m8n8.x4.shared.b16 {%0,%1,%2,%3}, [%4];"
                 : "=r"(r0), "=r"(r1), "=r"(r2), "=r"(r3) : "r"(a));
}
__device__ __forceinline__ void ldsm_x4_t(uint32_t& r0, uint32_t& r1,
                                          uint32_t& r2, uint32_t& r3, uint32_t a) {
    asm volatile("ldmatrix.sync.aligned.m8n8.x4.trans.shared.b16 {%0,%1,%2,%3}, [%4];"
                 : "=r"(r0), "=r"(r1), "=r"(r2), "=r"(r3) : "r"(a));
}
__device__ __forceinline__ void mma_bf16(float* c, const uint32_t* a,
                                         uint32_t b0, uint32_t b1) {
    asm volatile(
        "mma.sync.aligned.m16n8k16.row.col.f32.bf16.bf16.f32 "
        "{%0,%1,%2,%3}, {%4,%5,%6,%7}, {%8,%9}, {%0,%1,%2,%3};"
        : "+f"(c[0]), "+f"(c[1]), "+f"(c[2]), "+f"(c[3])
        : "r"(a[0]), "r"(a[1]), "r"(a[2]), "r"(a[3]), "r"(b0), "r"(b1));
}
__device__ __forceinline__ void split4(float4 v, void* hi, void* lo) {
    __nv_bfloat16 h[4], l[4];
    float f[4] = {v.x, v.y, v.z, v.w};
#pragma unroll
    for (int j = 0; j < 4; j++) {
        h[j] = __float2bfloat16_rn(f[j]);
        l[j] = __float2bfloat16_rn(f[j] - __bfloat162float(h[j]));
    }
    *(uint2*)hi = *(uint2*)h;
    *(uint2*)lo = *(uint2*)l;
}

// ---------------------------------------------------------------------------
// Fused preprocessing kernel: pure streaming splits + bias reduction.
//   [0, 2048)      : W_pre -> Phi/Plo
//   [2048, 2304)   : packed [Qf|Kf] -> Fhi/Flo
//   [2304, 2496)   : bias columns (192)
//   [2496, 2560)   : W_o -> Wohi/Wolo (64)
//   [2560, 10752)  : x -> xhi/xlo (8192)
// ---------------------------------------------------------------------------
#define NB_WPS  2048
#define NB_FS   256
#define NB_BIAS 192
#define NB_WO   64
#define NB_SX   8192
__global__ __launch_bounds__(256) void prep_fused(
    const float* __restrict__ x,
    const float* __restrict__ W_pre,
    const float* __restrict__ b_pre,
    const float* __restrict__ Q_filt,
    const float* __restrict__ K_filt,
    const float* __restrict__ b_v,
    const float* __restrict__ W_o)
{
    int bid = blockIdx.x;
    int tid = threadIdx.x;

    if (bid < NB_WPS) {
        // ---------------- W_pre split ----------------
        int i = bid * 256 + tid;                    // float4 index
        float4 v = ((const float4*)W_pre)[i];
        split4(v, &g_Phi[i * 4], &g_Plo[i * 4]);
    } else if (bid < NB_WPS + NB_FS) {
        // ---------------- filter split (packed [Qf|Kf]) ----------------
        int gi = (bid - NB_WPS) * 256 + tid;        // float4 over TT*128
        int e = gi * 4;
        int t = e >> 7, j = e & 127;
        const float* src = (j < 64) ? &Q_filt[t * 64 + j]
                                    : &K_filt[t * 64 + (j - 64)];
        float4 v = *(const float4*)src;
        split4(v, &g_Fhi[e], &g_Flo[e]);
    } else if (bid < NB_WPS + NB_FS + NB_BIAS) {
        // ---------------- bias columns ----------------
        int j = bid - NB_WPS - NB_FS;               // 0..191
        if (j >= 128) {
            if (tid == 0) g_bqkv[j] = b_v[j - 128];
            return;
        }
        const float* F = (j < 64) ? Q_filt : K_filt;
        int col = j & 63;
        float s = 0.f;
        for (int t = tid; t < TT; t += 256)
            s += b_pre[t] * F[t * KK + col];
#pragma unroll
        for (int o = 16; o > 0; o >>= 1)
            s += __shfl_xor_sync(0xffffffff, s, o);
        __shared__ float red[8];
        if ((tid & 31) == 0) red[tid >> 5] = s;
        __syncthreads();
        if (tid == 0) {
            float tot = 0.f;
#pragma unroll
            for (int w = 0; w < 8; w++) tot += red[w];
            g_bqkv[j] = tot;
        }
    } else if (bid < NB_WPS + NB_FS + NB_BIAS + NB_WO) {
        // ---------------- wo_split ----------------
        int i = (bid - NB_WPS - NB_FS - NB_BIAS) * 256 + tid;
        float4 v = ((const float4*)W_o)[i];
        split4(v, &g_Wohi[i * 4], &g_Wolo[i * 4]);
    } else {
        // ---------------- split_x ----------------
        int i = (bid - NB_WPS - NB_FS - NB_BIAS - NB_WO) * 256 + tid;
        float4 v = ((const float4*)x)[i];
        split4(v, &g_xhi[i * 4], &g_xlo[i * 4]);
    }
}

// ---------------------------------------------------------------------------
// Kernel A1: wfilt GEMM on tensor cores: Wqkv[:,0:128] = W_pre @ [Qf|Kf]
// M=1024, N=128, K=2048. 3-term split x 4-way K-split -> 12 partial layers.
// grid 192 = 8 m-tiles x 2 n x 3 phase x 4 ksplit. k-step 64, 8 iters.
// ---------------------------------------------------------------------------
#define QAP 72
__global__ __launch_bounds__(256, 2) void wfilt_mma()
{
    __shared__ __nv_bfloat16 As[2][128][QAP];
    __shared__ __nv_bfloat16 Bs[2][64][QAP];
    int bid = blockIdx.x;
    int ks = bid & 3;
    int phase = (bid >> 2) % 3;
    int n0 = ((bid / 12) & 1) * 64;
    int r0 = (bid / 24) * 128;
    const __nv_bfloat16* __restrict__ Asrc = (phase == 1) ? g_Plo : g_Phi;
    const __nv_bfloat16* __restrict__ Bsrc = (phase == 2) ? g_Flo : g_Fhi;
    int k0 = ks * 512;

    int tid = threadIdx.x;
    int lane = tid & 31, w = tid >> 5;
    int wm = (w & 3) * 32, wn = (w >> 2) * 32;

    float acc[2][4][4];
#pragma unroll
    for (int mt = 0; mt < 2; mt++)
#pragma unroll
        for (int nt = 0; nt < 4; nt++)
#pragma unroll
            for (int r = 0; r < 4; r++) acc[mt][nt][r] = 0.f;

    int ar = tid >> 3, ac = (tid & 7) * 8;
    int br = tid >> 3, bc = (tid & 7) * 8;

    float4 av[4], bv[2];
#pragma unroll
    for (int r = 0; r < 4; r++)
        av[r] = *(const float4*)&Asrc[(r0 + ar + r * 32) * TT + k0 + ac];
    bv[0] = *(const float4*)&Bsrc[(k0 + br) * 128 + n0 + bc];
    bv[1] = *(const float4*)&Bsrc[(k0 + br + 32) * 128 + n0 + bc];
#pragma unroll
    for (int r = 0; r < 4; r++)
        *(float4*)&As[0][ar + r * 32][ac] = av[r];
    *(float4*)&Bs[0][br][bc]      = bv[0];
    *(float4*)&Bs[0][br + 32][bc] = bv[1];
    __syncthreads();

    for (int it = 0; it < 8; it++) {
        int buf = it & 1;
        bool more = (it + 1 < 8);
        if (more) {
            int kk = k0 + (it + 1) * 64;
#pragma unroll
            for (int r = 0; r < 4; r++)
                av[r] = *(const float4*)&Asrc[(r0 + ar + r * 32) * TT + kk + ac];
            bv[0] = *(const float4*)&Bsrc[(kk + br) * 128 + n0 + bc];
            bv[1] = *(const float4*)&Bsrc[(kk + br + 32) * 128 + n0 + bc];
        }

#pragma unroll
        for (int kq = 0; kq < 4; kq++) {
            int k = kq * 16;
            uint32_t a[2][4];
#pragma unroll
            for (int mt = 0; mt < 2; mt++) {
                uint32_t ad = smaddr(&As[buf][wm + mt * 16 + (lane & 15)][k + ((lane >> 4) << 3)]);
                ldsm_x4(a[mt][0], a[mt][1], a[mt][2], a[mt][3], ad);
            }
            uint32_t b[2][4];
#pragma unroll
            for (int nb = 0; nb < 2; nb++) {
                uint32_t bd = smaddr(&Bs[buf][k + (lane & 15)][wn + nb * 16 + ((lane >> 4) << 3)]);
                ldsm_x4_t(b[nb][0], b[nb][1], b[nb][2], b[nb][3], bd);
            }
#pragma unroll
            for (int mt = 0; mt < 2; mt++)
#pragma unroll
                for (int nt = 0; nt < 4; nt++) {
                    int nb = nt >> 1, pr = nt & 1;
                    mma_bf16(acc[mt][nt], a[mt], b[nb][pr * 2], b[nb][pr * 2 + 1]);
                }
        }

        if (more) {
#pragma unroll
            for (int r = 0; r < 4; r++)
                *(float4*)&As[buf ^ 1][ar + r * 32][ac] = av[r];
            *(float4*)&Bs[buf ^ 1][br][bc]      = bv[0];
            *(float4*)&Bs[buf ^ 1][br + 32][bc] = bv[1];
            __syncthreads();
        }
    }

    int layer = phase * 4 + ks;
    float* Wp = &g_Wpart[layer * DD * 128];
    int gr = lane >> 2, tc = (lane & 3) * 2;
#pragma unroll
    for (int mt = 0; mt < 2; mt++)
#pragma unroll
        for (int nt = 0; nt < 4; nt++) {
            int row = r0 + wm + mt * 16 + gr;
            int col = n0 + wn + nt * 8 + tc;
            Wp[row * 128 + col]           = acc[mt][nt][0];
            Wp[row * 128 + col + 1]       = acc[mt][nt][1];
            Wp[(row + 8) * 128 + col]     = acc[mt][nt][2];
            Wp[(row + 8) * 128 + col + 1] = acc[mt][nt][3];
        }
}

// ---------------------------------------------------------------------------
// Kernel A2: reduce 12 partial layers + W_v, write bf16 hi/lo directly
// ---------------------------------------------------------------------------
__global__ void wqkv_finalize(const float* __restrict__ W_v)
{
    int idx = blockIdx.x * blockDim.x + threadIdx.x;
    if (idx >= DD * NQ) return;
    int d = idx / NQ, j = idx % NQ;
    float s;
    if (j < 128) {
        s = 0.f;
#pragma unroll
        for (int p = 0; p < 12; p++) s += g_Wpart[(p * DD + d) * 128 + j];
    } else {
        s = W_v[d * KK + (j - 128)];
    }
    __nv_bfloat16 h = __float2bfloat16_rn(s);
    g_Whi[idx] = h;
    g_Wlo[idx] = __float2bfloat16_rn(s - __bfloat162float(h));
}

// ---------------------------------------------------------------------------
// Kernel B: QKV GEMM, K-split by phase. grid 576 = 64 rows x 3 n x 3 phase.
// ---------------------------------------------------------------------------
__global__ __launch_bounds__(256, 2) void qkv_mma()
{
    __shared__ __nv_bfloat16 As[2][128][QAP];   // 36.9 KB
    __shared__ __nv_bfloat16 Bs[2][64][QAP];    // 18.4 KB
    int bid = blockIdx.x;
    int phase = bid % 3;
    int n0 = ((bid / 3) % 3) * 64;
    int r0 = (bid / 9) * 128;
    const __nv_bfloat16* __restrict__ Asrc = (phase == 1) ? g_xlo : g_xhi;
    const __nv_bfloat16* __restrict__ Bsrc = (phase == 2) ? g_Wlo : g_Whi;

    int tid = threadIdx.x;
    int lane = tid & 31, w = tid >> 5;
    int wm = (w & 3) * 32, wn = (w >> 2) * 32;

    float acc[2][4][4];
#pragma unroll
    for (int mt = 0; mt < 2; mt++)
#pragma unroll
        for (int nt = 0; nt < 4; nt++)
#pragma unroll
            for (int r = 0; r < 4; r++) acc[mt][nt][r] = 0.f;

    int ar = tid >> 3, ac = (tid & 7) * 8;
    int br = tid >> 3, bc = (tid & 7) * 8;

    float4 av[4], bv[2];
#pragma unroll
    for (int r = 0; r < 4; r++)
        av[r] = *(const float4*)&Asrc[(r0 + ar + r * 32) * DD + ac];
    bv[0] = *(const float4*)&Bsrc[br * NQ + n0 + bc];
    bv[1] = *(const float4*)&Bsrc[(br + 32) * NQ + n0 + bc];
#pragma unroll
    for (int r = 0; r < 4; r++)
        *(float4*)&As[0][ar + r * 32][ac] = av[r];
    *(float4*)&Bs[0][br][bc]      = bv[0];
    *(float4*)&Bs[0][br + 32][bc] = bv[1];
    __syncthreads();

    for (int it = 0; it < 16; it++) {
        int buf = it & 1;
        bool more = (it + 1 < 16);
        if (more) {
            int kk = (it + 1) * 64;
#pragma unroll
            for (int r = 0; r < 4; r++)
                av[r] = *(const float4*)&Asrc[(r0 + ar + r * 32) * DD + kk + ac];
            bv[0] = *(const float4*)&Bsrc[(kk + br) * NQ + n0 + bc];
            bv[1] = *(const float4*)&Bsrc[(kk + br + 32) * NQ + n0 + bc];
        }

#pragma unroll
        for (int kq = 0; kq < 4; kq++) {
            int k = kq * 16;
            uint32_t a[2][4];
#pragma unroll
            for (int mt = 0; mt < 2; mt++) {
                uint32_t ad = smaddr(&As[buf][wm + mt * 16 + (lane & 15)][k + ((lane >> 4) << 3)]);
                ldsm_x4(a[mt][0], a[mt][1], a[mt][2], a[mt][3], ad);
            }
            uint32_t b[2][4];
#pragma unroll
            for (int nb = 0; nb < 2; nb++) {
                uint32_t bd = smaddr(&Bs[buf][k + (lane & 15)][wn + nb * 16 + ((lane >> 4) << 3)]);
                ldsm_x4_t(b[nb][0], b[nb][1], b[nb][2], b[nb][3], bd);
            }
#pragma unroll
            for (int mt = 0; mt < 2; mt++)
#pragma unroll
                for (int nt = 0; nt < 4; nt++) {
                    int nb = nt >> 1, pr = nt & 1;
                    mma_bf16(acc[mt][nt], a[mt], b[nb][pr * 2], b[nb][pr * 2 + 1]);
                }
        }

        if (more) {
#pragma unroll
            for (int r = 0; r < 4; r++)
                *(float4*)&As[buf ^ 1][ar + r * 32][ac] = av[r];
            *(float4*)&Bs[buf ^ 1][br][bc]      = bv[0];
            *(float4*)&Bs[buf ^ 1][br + 32][bc] = bv[1];
            __syncthreads();
        }
    }

    float* Qp = g_Qp[phase];
    int gr = lane >> 2, tc = (lane & 3) * 2;
#pragma unroll
    for (int mt = 0; mt < 2; mt++)
#pragma unroll
        for (int nt = 0; nt < 4; nt++) {
            int row = r0 + wm + mt * 16 + gr;
            int col = n0 + wn + nt * 8 + tc;
            Qp[row * NQ + col]           = acc[mt][nt][0];
            Qp[row * NQ + col + 1]       = acc[mt][nt][1];
            Qp[(row + 8) * NQ + col]     = acc[mt][nt][2];
            Qp[(row + 8) * NQ + col + 1] = acc[mt][nt][3];
        }
}

// ---------------------------------------------------------------------------
// Kernel B2: QKV = p0 + p1 + p2 + bias
// ---------------------------------------------------------------------------
__global__ __launch_bounds__(256) void qkv_reduce()
{
    int i = blockIdx.x * blockDim.x + threadIdx.x;   // one float4
    float4 p0 = ((const float4*)g_Qp[0])[i];
    float4 p1 = ((const float4*)g_Qp[1])[i];
    float4 p2 = ((const float4*)g_Qp[2])[i];
    int col = (i * 4) % NQ;
    float4 bb = *(const float4*)&g_bqkv[col];
    float4 o;
    o.x = p0.x + p1.x + p2.x + bb.x;
    o.y = p0.y + p1.y + p2.y + bb.y;
    o.z = p0.z + p1.z + p2.z + bb.z;
    o.w = p0.w + p1.w + p2.w + bb.w;
    ((float4*)g_QKV)[i] = o;
}

// ---------------------------------------------------------------------------
// Kernel C1: per-sub-chunk state sums (32 steps each), grid 256, float4 LDS
// ---------------------------------------------------------------------------
__global__ __launch_bounds__(256) void chunk_sum(const float* __restrict__ decay)
{
    __shared__ float Vs[32][68];
    __shared__ float Ks[32][68];
    int b = blockIdx.x >> 6, sc = blockIdx.x & 63;
    int base = b * TT + sc * 32;
    int tid = threadIdx.x;
    int ty = tid >> 4, tx = tid & 15;
    float acc[4][4];
#pragma unroll
    for (int i = 0; i < 4; i++)
#pragma unroll
        for (int j = 0; j < 4; j++) acc[i][j] = 0.f;

    for (int i = tid; i < 32 * 64; i += 256) {
        int r = i >> 6, k = i & 63;
        int row = base + r;
        float d = decay[sc * 32 + r];
        Vs[r][k] = g_QKV[row * NQ + 128 + k];
        Ks[r][k] = g_QKV[row * NQ + 64 + k] * d;
    }
    __syncthreads();
#pragma unroll 8
    for (int s = 0; s < 32; s++) {
        float4 a4 = *(const float4*)&Vs[s][ty * 4];
        float4 b4 = *(const float4*)&Ks[s][tx * 4];
        float a[4] = {a4.x, a4.y, a4.z, a4.w};
        float bb[4] = {b4.x, b4.y, b4.z, b4.w};
#pragma unroll
        for (int i = 0; i < 4; i++)
#pragma unroll
            for (int j = 0; j < 4; j++) acc[i][j] += a[i] * bb[j];
    }
    int sb = (b * NSC + sc) * KK * KK;
#pragma unroll
    for (int i = 0; i < 4; i++)
#pragma unroll
        for (int j = 0; j < 4; j++)
            g_S[sb + (ty * 4 + i) * KK + tx * 4 + j] = acc[i][j];
}

// ---------------------------------------------------------------------------
// Kernel C2: exclusive prefix over 64-row half-chunks. grid 128 x 128 threads
// ---------------------------------------------------------------------------
__global__ __launch_bounds__(128) void chunk_prefix()
{
    int b = blockIdx.x >> 5;
    int e = (blockIdx.x & 31) * 128 + threadIdx.x;   // 0..4095
    float acc = 0.f;
    int sbase = b * NSC * KK * KK;
    int hbase = b * NH * KK * KK;
    for (int c = 0; c < NH; c++) {
        g_H[hbase + c * KK * KK + e] = acc;
        acc += g_S[sbase + (2 * c) * KK * KK + e]
             + g_S[sbase + (2 * c + 1) * KK * KK + e];
    }
}

// ---------------------------------------------------------------------------
// Kernel C3: half-chunk attention split by n-half. grid = BB*NH*2 = 256.
// ---------------------------------------------------------------------------
__global__ __launch_bounds__(256, 2) void attn_kernel(const float* __restrict__ decay)
{
    __shared__ float Qt[KK][64];
    __shared__ float Reg[3072];
    int b = blockIdx.x >> 6, hc = (blockIdx.x >> 1) & 31, nh = blockIdx.x & 1;
    int base = b * TT + hc * 64;
    int tid = threadIdx.x;
    int row = tid >> 2;
    int qd = tid & 3;

    for (int i = tid; i < KK * 64; i += 256) {
        int r = i & 63, k = i >> 6;
        Qt[k][r] = g_QKV[(base + r) * NQ + k];
    }
    int hb = (b * NH + hc) * KK * KK + nh * 32;
    for (int i = tid; i < KK * 32; i += 256) {
        int k = i >> 5, j = i & 31;
        Reg[i] = g_H[hb + k * KK + j];
    }
    __syncthreads();

    float q[KK];
#pragma unroll
    for (int k = 0; k < KK; k++) q[k] = Qt[k][row];

    float y[8];
#pragma unroll
    for (int j = 0; j < 8; j++) y[j] = 0.f;

    {
        const float4* H4 = (const float4*)Reg;
#pragma unroll
        for (int k = 0; k < KK; k++) {
            float qk = q[k];
#pragma unroll
            for (int jj = 0; jj < 2; jj++) {
                float4 h = H4[k * 8 + qd * 2 + jj];
                y[jj * 4 + 0] += qk * h.x;
                y[jj * 4 + 1] += qk * h.y;
                y[jj * 4 + 2] += qk * h.z;
                y[jj * 4 + 3] += qk * h.w;
            }
        }
    }
    __syncthreads();

    for (int st = 0; st < 64; st += 32) {
        for (int i = tid; i < 2048; i += 256) {
            int s = i >> 6, k = i & 63;
            Reg[i] = g_QKV[(base + st + s) * NQ + 128 + k];
        }
        for (int i = tid; i < 1024; i += 256) {
            int s = i >> 5, j = i & 31;
            Reg[2048 + i] = g_QKV[(base + st + s) * NQ + 64 + nh * 32 + j]
                          * decay[hc * 64 + st + s];
        }
        __syncthreads();
        if (row >= st) {
            int sm = row - st + 1;
            if (sm > 32) sm = 32;
            const float4* V4 = (const float4*)Reg;
            const float4* F4 = (const float4*)(Reg + 2048);
            for (int s = 0; s < sm; s++) {
                float sc = 0.f;
#pragma unroll
                for (int kk = 0; kk < 16; kk++) {
                    float4 v = V4[s * 16 + kk];
                    sc += q[kk * 4 + 0] * v.x + q[kk * 4 + 1] * v.y
                        + q[kk * 4 + 2] * v.z + q[kk * 4 + 3] * v.w;
                }
#pragma unroll
                for (int jj = 0; jj < 2; jj++) {
                    float4 f = F4[s * 8 + qd * 2 + jj];
                    y[jj * 4 + 0] += sc * f.x;
                    y[jj * 4 + 1] += sc * f.y;
                    y[jj * 4 + 2] += sc * f.z;
                    y[jj * 4 + 3] += sc * f.w;
                }
            }
        }
        __syncthreads();
    }

    int ybase = (base + row) * KK + nh * 32 + qd * 8;
#pragma unroll
    for (int jj = 0; jj < 2; jj++) {
        __nv_bfloat16 hp[4], lp[4];
#pragma unroll
        for (int e = 0; e < 4; e++) {
            float f = y[jj * 4 + e];
            hp[e] = __float2bfloat16_rn(f);
            lp[e] = __float2bfloat16_rn(f - __bfloat162float(hp[e]));
        }
        *(uint2*)&g_Yhi[ybase + jj * 4] = *(uint2*)hp;
        *(uint2*)&g_Ylo[ybase + jj * 4] = *(uint2*)lp;
    }
}

// ---------------------------------------------------------------------------
// Kernel D: out = Y @ W_o + b_o  on tensor cores (3-term split, K packed=192)
// Double-buffered smem, one sync per iter.
// ---------------------------------------------------------------------------
#define APITCH 40
#define BPITCH 72
__global__ __launch_bounds__(256, 2) void out_mma(const float* __restrict__ b_o,
                                                  float* __restrict__ out)
{
    __shared__ __nv_bfloat16 As[2][128][APITCH];
    __shared__ __nv_bfloat16 Bs[2][32][BPITCH];
    int r0 = blockIdx.x * 128;
    int n0 = blockIdx.y * 64;
    int tid = threadIdx.x;
    int lane = tid & 31, w = tid >> 5;
    int wm = (w & 3) * 32, wn = (w >> 2) * 32;

    float acc[2][4][4];
#pragma unroll
    for (int mt = 0; mt < 2; mt++)
#pragma unroll
        for (int nt = 0; nt < 4; nt++)
#pragma unroll
            for (int r = 0; r < 4; r++) acc[mt][nt][r] = 0.f;

    int ar = tid >> 2, ac = (tid & 3) * 8;
    int br = tid >> 3, bc = (tid & 7) * 8;

    float4 a0v, a1v, bv;
    a0v = *(const float4*)&g_Yhi[(r0 + ar) * KK + ac];
    a1v = *(const float4*)&g_Yhi[(r0 + ar + 64) * KK + ac];
    bv  = *(const float4*)&g_Wohi[br * DD + n0 + bc];
    *(float4*)&As[0][ar][ac]      = a0v;
    *(float4*)&As[0][ar + 64][ac] = a1v;
    *(float4*)&Bs[0][br][bc]      = bv;
    __syncthreads();

    for (int it = 0; it < 6; it++) {
        int buf = it & 1;
        bool more = (it + 1 < 6);
        if (more) {
            int nit = it + 1;
            int phase = nit >> 1;
            int kk = (nit & 1) * 32;
            const __nv_bfloat16* Asrc = (phase == 1) ? g_Ylo : g_Yhi;
            const __nv_bfloat16* Bsrc = (phase == 2) ? g_Wolo : g_Wohi;
            a0v = *(const float4*)&Asrc[(r0 + ar) * KK + kk + ac];
            a1v = *(const float4*)&Asrc[(r0 + ar + 64) * KK + kk + ac];
            bv  = *(const float4*)&Bsrc[(kk + br) * DD + n0 + bc];
        }

#pragma unroll
        for (int kq = 0; kq < 2; kq++) {
            int k = kq * 16;
            uint32_t a[2][4];
#pragma unroll
            for (int mt = 0; mt < 2; mt++) {
                uint32_t ad = smaddr(&As[buf][wm + mt * 16 + (lane & 15)][k + ((lane >> 4) << 3)]);
                ldsm_x4(a[mt][0], a[mt][1], a[mt][2], a[mt][3], ad);
            }
            uint32_t b[2][4];
#pragma unroll
            for (int nb = 0; nb < 2; nb++) {
                uint32_t bd = smaddr(&Bs[buf][k + (lane & 15)][wn + nb * 16 + ((lane >> 4) << 3)]);
                ldsm_x4_t(b[nb][0], b[nb][1], b[nb][2], b[nb][3], bd);
            }
#pragma unroll
            for (int mt = 0; mt < 2; mt++)
#pragma unroll
                for (int nt = 0; nt < 4; nt++) {
                    int nb = nt >> 1, pr = nt & 1;
                    mma_bf16(acc[mt][nt], a[mt], b[nb][pr * 2], b[nb][pr * 2 + 1]);
                }
        }

        if (more) {
            *(float4*)&As[buf ^ 1][ar][ac]      = a0v;
            *(float4*)&As[buf ^ 1][ar + 64][ac] = a1v;
            *(float4*)&Bs[buf ^ 1][br][bc]      = bv;
            __syncthreads();
        }
    }

    int gr = lane >> 2, tc = (lane & 3) * 2;
#pragma unroll
    for (int mt = 0; mt < 2; mt++)
#pragma unroll
        for (int nt = 0; nt < 4; nt++) {
            int row = r0 + wm + mt * 16 + gr;
            int col = n0 + wn + nt * 8 + tc;
            float bb0 = b_o[col], bb1 = b_o[col + 1];
            out[row * DD + col]           = acc[mt][nt][0] + bb0;
            out[row * DD + col + 1]       = acc[mt][nt][1] + bb1;
            out[(row + 8) * DD + col]     = acc[mt][nt][2] + bb0;
            out[(row + 8) * DD + col + 1] = acc[mt][nt][3] + bb1;
        }
}

// ---------------------------------------------------------------------------
extern "C" void kernel_launch(void* const* d_in, const int* in_sizes, int n_in,
                              void* d_out, int out_size)
{
    const float* x      = (const float*)d_in[0];
    const float* W_pre  = (const float*)d_in[1];
    const float* b_pre  = (const float*)d_in[2];
    const float* Q_filt = (const float*)d_in[3];
    const float* K_filt = (const float*)d_in[4];
    const float* W_v    = (const float*)d_in[5];
    const float* b_v    = (const float*)d_in[6];
    const float* W_o    = (const float*)d_in[7];
    const float* b_o    = (const float*)d_in[8];
    const float* decay  = (const float*)d_in[9];
    float* out = (float*)d_out;

    prep_fused<<<NB_WPS + NB_FS + NB_BIAS + NB_WO + NB_SX, 256>>>(
        x, W_pre, b_pre, Q_filt, K_filt, b_v, W_o);
    wfilt_mma<<<192, 256>>>();
    wqkv_finalize<<<(DD * NQ + 255) / 256, 256>>>(W_v);
    qkv_mma<<<576, 256>>>();
    qkv_reduce<<<(RR * NQ / 4) / 256, 256>>>();
    chunk_sum<<<256, 256>>>(decay);
    chunk_prefix<<<128, 128>>>();
    attn_kernel<<<BB * NH * 2, 256>>>(decay);
    out_mma<<<dim3(64, 16), 256>>>(b_o, out);
}